// round 1
// baseline (speedup 1.0000x reference)
#include <cuda_runtime.h>
#include <cstdint>

// ---------------- problem constants ----------------
#define B_WIN  2048
#define NTOK   49
#define DIMF   256
#define HEADS  8
#define HD     32
#define MROWS  (B_WIN * NTOK)        // 100352
#define QKVCOL 768

// ---------------- scratch (static device globals; no allocation) ----------------
__device__ float g_qkv [MROWS * QKVCOL];    // 308 MB  [B*49, 768]
__device__ float g_attn[MROWS * DIMF];      // 103 MB  [B*49, 256]
__device__ float g_bias[HEADS * NTOK * NTOK];
__device__ float g_scale[HEADS];

// ---------------- helpers ----------------
__device__ __forceinline__ float warp_sum(float v) {
#pragma unroll
    for (int o = 16; o > 0; o >>= 1) v += __shfl_xor_sync(0xffffffffu, v, o);
    return v;
}
__device__ __forceinline__ float warp_max(float v) {
#pragma unroll
    for (int o = 16; o > 0; o >>= 1) v = fmaxf(v, __shfl_xor_sync(0xffffffffu, v, o));
    return v;
}

// =====================================================================
// Kernel 1: CPB-MLP bias table + logit scale  (tiny; one CTA)
//   bias[h][i][j] = 16*sigmoid( MLP(coords[rel_idx(i,j)])[h] )
//   scale[h]      = exp(clip(logit_scale[h], -100, ln(100)))
// =====================================================================
__device__ __forceinline__ float cpb_coord(int i) {
    float x = (float)(i - (NTOK / 7 * 0 + 6)) * (8.0f / 6.0f);   // (i-6)*8/6
    // sign(x) * log(|x|+1) / log(8)
    return copysignf(log1pf(fabsf(x)) * 0.4808983469629878f, x);
}

__global__ void cpb_kernel(const float* __restrict__ logit_scale,
                           const float* __restrict__ w1,   // [2,512]
                           const float* __restrict__ b1,   // [512]
                           const float* __restrict__ w2,   // [512,8]
                           float* __restrict__ bias_out,   // [8,49,49]
                           float* __restrict__ scale_out)  // [8]
{
    __shared__ float table[169][HEADS];
    const int tid = threadIdx.x;

    if (tid < HEADS) {
        float ls = logit_scale[tid];
        ls = fminf(ls, logf(100.0f));
        ls = fmaxf(ls, -100.0f);
        scale_out[tid] = expf(ls);
    }

    for (int e = tid; e < 169; e += blockDim.x) {
        const int i = e / 13, j = e % 13;
        const float c0 = cpb_coord(i);
        const float c1 = cpb_coord(j);
        float acc[HEADS];
#pragma unroll
        for (int hh = 0; hh < HEADS; hh++) acc[hh] = 0.0f;
        for (int kk = 0; kk < 512; kk++) {
            float hpre = c0 * w1[kk] + c1 * w1[512 + kk] + b1[kk];
            // exact GELU: 0.5*x*(1+erf(x/sqrt(2)))
            float g = 0.5f * hpre * (1.0f + erff(hpre * 0.7071067811865475f));
#pragma unroll
            for (int hh = 0; hh < HEADS; hh++) acc[hh] += g * w2[kk * 8 + hh];
        }
#pragma unroll
        for (int hh = 0; hh < HEADS; hh++) table[e][hh] = acc[hh];
    }
    __syncthreads();

    for (int idx = tid; idx < HEADS * NTOK * NTOK; idx += blockDim.x) {
        const int hh  = idx / (NTOK * NTOK);
        const int rem = idx % (NTOK * NTOK);
        const int r   = rem / NTOK;
        const int c   = rem % NTOK;
        const int dh  = (r / 7) - (c / 7) + 6;
        const int dw  = (r % 7) - (c % 7) + 6;
        const float v = table[dh * 13 + dw][hh];
        bias_out[idx] = 16.0f / (1.0f + __expf(-v));
    }
}

// =====================================================================
// Kernel 2/4: tiled fp32 GEMM  C[M,N] = A[M,K] @ W[K,N] + bias[N]
//   BM=128, BN=64, BK=16, 256 threads, 8x4 per-thread microtile,
//   accumulators packed as f32x2 pairs along M (fma.rn.f32x2 = full-rate
//   fma pipe on sm_103a, vs half-rate 3-reg FFMA).
//   Requires M%128==0, N%64==0, K%16==0 (true for all calls).
// =====================================================================
#define GBM 128
#define GBN 64
#define GBK 16

__global__ __launch_bounds__(256) void gemm_bias_kernel(
    const float* __restrict__ A, const float* __restrict__ W,
    const float* __restrict__ bias, float* __restrict__ C,
    int M, int N, int K)
{
    __shared__ float As[GBK][GBM + 4];   // transposed A tile (stride 132: 16B-aligned rows)
    __shared__ float Bs[GBK][GBN];

    const int tid = threadIdx.x;
    const int tx = tid & 15;             // 16 thread-cols
    const int ty = tid >> 4;             // 16 thread-rows
    const int rowBase = blockIdx.y * GBM;
    const int colBase = blockIdx.x * GBN;

    // A-load mapping: 512 float4 per tile, 2 per thread
    const int arow = tid >> 2;           // 0..63
    const int akc  = (tid & 3) * 4;      // 0,4,8,12
    // B-load mapping: 256 float4 per tile, 1 per thread
    const int bkr  = tid >> 4;           // 0..15
    const int bnc  = (tid & 15) * 4;     // 0..60

    unsigned long long acc2[4][4];
#pragma unroll
    for (int mp = 0; mp < 4; mp++)
#pragma unroll
        for (int n = 0; n < 4; n++) acc2[mp][n] = 0ull;

    const float* Abase = A + (size_t)rowBase * K;

    for (int k0 = 0; k0 < K; k0 += GBK) {
        float4 a0 = *(const float4*)(Abase + (size_t)arow        * K + k0 + akc);
        float4 a1 = *(const float4*)(Abase + (size_t)(arow + 64) * K + k0 + akc);
        float4 b0 = *(const float4*)(W + (size_t)(k0 + bkr) * N + colBase + bnc);

        As[akc + 0][arow] = a0.x;  As[akc + 1][arow] = a0.y;
        As[akc + 2][arow] = a0.z;  As[akc + 3][arow] = a0.w;
        As[akc + 0][arow + 64] = a1.x;  As[akc + 1][arow + 64] = a1.y;
        As[akc + 2][arow + 64] = a1.z;  As[akc + 3][arow + 64] = a1.w;
        *(float4*)&Bs[bkr][bnc] = b0;
        __syncthreads();

#pragma unroll
        for (int kk = 0; kk < GBK; kk++) {
            unsigned long long ap[4];
#pragma unroll
            for (int mp = 0; mp < 4; mp++)
                ap[mp] = *(const unsigned long long*)&As[kk][ty * 8 + 2 * mp];
            float4 bv = *(const float4*)&Bs[kk][tx * 4];
            unsigned long long bd[4];
            asm("mov.b64 %0, {%1, %1};" : "=l"(bd[0]) : "f"(bv.x));
            asm("mov.b64 %0, {%1, %1};" : "=l"(bd[1]) : "f"(bv.y));
            asm("mov.b64 %0, {%1, %1};" : "=l"(bd[2]) : "f"(bv.z));
            asm("mov.b64 %0, {%1, %1};" : "=l"(bd[3]) : "f"(bv.w));
#pragma unroll
            for (int mp = 0; mp < 4; mp++)
#pragma unroll
                for (int n = 0; n < 4; n++)
                    asm("fma.rn.f32x2 %0, %1, %2, %0;"
                        : "+l"(acc2[mp][n]) : "l"(ap[mp]), "l"(bd[n]));
        }
        __syncthreads();
    }

    // epilogue: unpack + bias + store
    float4 bb = *(const float4*)(bias + colBase + tx * 4);
    const float bcol[4] = {bb.x, bb.y, bb.z, bb.w};
#pragma unroll
    for (int mp = 0; mp < 4; mp++) {
        float lo[4], hi[4];
#pragma unroll
        for (int n = 0; n < 4; n++)
            asm("mov.b64 {%0, %1}, %2;" : "=f"(lo[n]), "=f"(hi[n]) : "l"(acc2[mp][n]));
        const int row0 = rowBase + ty * 8 + mp * 2;
        float4 o0 = make_float4(lo[0] + bcol[0], lo[1] + bcol[1], lo[2] + bcol[2], lo[3] + bcol[3]);
        float4 o1 = make_float4(hi[0] + bcol[0], hi[1] + bcol[1], hi[2] + bcol[2], hi[3] + bcol[3]);
        *(float4*)(C + (size_t)row0 * N + colBase + tx * 4)       = o0;
        *(float4*)(C + (size_t)(row0 + 1) * N + colBase + tx * 4) = o1;
    }
}

// =====================================================================
// Kernel 3: per-(window,head) cosine attention
//   grid (2048, 8), 128 threads (4 warps)
// =====================================================================
__global__ __launch_bounds__(128) void attn_kernel(
    const float* __restrict__ qkv,    // [B*49, 768]
    const float* __restrict__ bias,   // [8,49,49] (16*sigmoid applied)
    const float* __restrict__ scale,  // [8]
    float* __restrict__ attn_out)     // [B*49, 256]
{
    const int b = blockIdx.x;
    const int h = blockIdx.y;

    __shared__ float qs[NTOK][36];
    __shared__ float ks[64][36];      // rows 49..63 zeroed (no guards in dot)
    __shared__ float vs[NTOK][36];
    __shared__ float Pt[NTOK][52];    // transposed probs: Pt[j][i]; 52*4B=208B rows (16B-aligned)

    const int tid  = threadIdx.x;
    const int lane = tid & 31;
    const int w    = tid >> 5;

    const float* base = qkv + (size_t)b * NTOK * QKVCOL + h * HD;

    // load q,k,v head slices (float4 vectorized, coalesced)
    for (int idx = tid; idx < NTOK * 8; idx += 128) {
        const int t  = idx >> 3;
        const int d4 = (idx & 7) * 4;
        const float* row = base + (size_t)t * QKVCOL;
        *(float4*)&qs[t][d4] = *(const float4*)(row + 0   + d4);
        *(float4*)&ks[t][d4] = *(const float4*)(row + 256 + d4);
        *(float4*)&vs[t][d4] = *(const float4*)(row + 512 + d4);
    }
    // zero k padding rows
    for (int idx = tid; idx < (64 - NTOK) * 36; idx += 128)
        ks[NTOK + idx / 36][idx % 36] = 0.0f;
    __syncthreads();

    const float sc = scale[h];

    // L2-normalize rows; fold logit scale into q
    for (int r = w; r < NTOK; r += 4) {
        float qv = qs[r][lane];
        float kv = ks[r][lane];
        float qn = warp_sum(qv * qv);
        float kn = warp_sum(kv * kv);
        qs[r][lane] = qv * (rsqrtf(qn) * sc);
        ks[r][lane] = kv * rsqrtf(kn);
    }
    __syncthreads();

    // S = q@k^T, +bias, softmax -> Pt (transposed), one warp per row
    const float* brow = bias + (size_t)h * NTOK * NTOK;
    for (int r = w; r < NTOK; r += 4) {
        const int j  = lane;
        const int j2 = lane + 32;
        float s1 = 0.0f, s2 = 0.0f;
#pragma unroll
        for (int kk4 = 0; kk4 < HD; kk4 += 4) {
            float4 qv = *(const float4*)&qs[r][kk4];
            float4 k1 = *(const float4*)&ks[j][kk4];
            float4 k2 = *(const float4*)&ks[j2][kk4];   // zero rows beyond 48
            s1 += qv.x * k1.x + qv.y * k1.y + qv.z * k1.z + qv.w * k1.w;
            s2 += qv.x * k2.x + qv.y * k2.y + qv.z * k2.z + qv.w * k2.w;
        }
        s1 += brow[r * NTOK + j];
        s2 = (j2 < NTOK) ? (s2 + brow[r * NTOK + j2]) : -1e30f;

        float mx = warp_max(fmaxf(s1, s2));
        float p1 = __expf(s1 - mx);
        float p2 = (j2 < NTOK) ? __expf(s2 - mx) : 0.0f;
        float rs = 1.0f / warp_sum(p1 + p2);
        Pt[j][r] = p1 * rs;
        if (j2 < NTOK) Pt[j2][r] = p2 * rs;
    }
    __syncthreads();

    // O = P@V : 4-row groups per warp pass, Pt broadcast reads
    float* obase = attn_out + (size_t)b * NTOK * DIMF + h * HD;
    for (int g = w; g < 13; g += 4) {
        const int r0 = g * 4;
        float a0 = 0.f, a1 = 0.f, a2 = 0.f, a3 = 0.f;
#pragma unroll 7
        for (int j = 0; j < NTOK; j++) {
            const float vj = vs[j][lane];
            float4 p = *(const float4*)&Pt[j][r0];
            a0 += p.x * vj;  a1 += p.y * vj;
            a2 += p.z * vj;  a3 += p.w * vj;
        }
        const int rem = NTOK - r0;
        float* o = obase + (size_t)r0 * DIMF;
        o[lane] = a0;
        if (rem > 1) o[DIMF + lane]     = a1;
        if (rem > 2) o[2 * DIMF + lane] = a2;
        if (rem > 3) o[3 * DIMF + lane] = a3;
    }
}

// =====================================================================
// launch
// =====================================================================
extern "C" void kernel_launch(void* const* d_in, const int* in_sizes, int n_in,
                              void* d_out, int out_size)
{
    const float* x           = (const float*)d_in[0];
    const float* qkv_w       = (const float*)d_in[1];
    const float* qkv_b       = (const float*)d_in[2];
    const float* proj_w      = (const float*)d_in[3];
    const float* proj_b      = (const float*)d_in[4];
    const float* logit_scale = (const float*)d_in[5];
    const float* cpb_w1      = (const float*)d_in[6];
    const float* cpb_b1      = (const float*)d_in[7];
    const float* cpb_w2      = (const float*)d_in[8];
    float* out = (float*)d_out;

    float *qkvbuf, *attnbuf, *biasbuf, *scalebuf;
    cudaGetSymbolAddress((void**)&qkvbuf,  g_qkv);
    cudaGetSymbolAddress((void**)&attnbuf, g_attn);
    cudaGetSymbolAddress((void**)&biasbuf, g_bias);
    cudaGetSymbolAddress((void**)&scalebuf, g_scale);

    // 1) CPB bias + logit scale (tiny)
    cpb_kernel<<<1, 256>>>(logit_scale, cpb_w1, cpb_b1, cpb_w2, biasbuf, scalebuf);

    // 2) QKV GEMM: [100352,256]@[256,768]+b -> g_qkv
    gemm_bias_kernel<<<dim3(QKVCOL / GBN, MROWS / GBM), 256>>>(
        x, qkv_w, qkv_b, qkvbuf, MROWS, QKVCOL, DIMF);

    // 3) attention per (window, head)
    attn_kernel<<<dim3(B_WIN, HEADS), 128>>>(qkvbuf, biasbuf, scalebuf, attnbuf);

    // 4) proj GEMM: [100352,256]@[256,256]+b -> out
    gemm_bias_kernel<<<dim3(DIMF / GBN, MROWS / GBM), 256>>>(
        attnbuf, proj_w, proj_b, out, MROWS, DIMF, DIMF);
}

// round 3
// speedup vs baseline: 1.4937x; 1.4937x over previous
#include <cuda_runtime.h>
#include <cuda_bf16.h>
#include <cstdint>

// ---------------- problem constants ----------------
#define B_WIN  2048
#define NTOK   49
#define DIMF   256
#define HEADS  8
#define HD     32
#define MROWS  (B_WIN * NTOK)        // 100352
#define QKVCOL 768

// ---------------- scratch (static device globals; no allocation) ----------------
__device__ float g_qkv [MROWS * QKVCOL];    // 308 MB
__device__ float g_attn[MROWS * DIMF];      // 103 MB
__device__ float g_bias[HEADS * NTOK * NTOK];
__device__ float g_scale[HEADS];
// pre-split weights: per (N-tile, k-chunk): 16 KB chunk = [hi 8KB | lo 8KB],
// each = 32 k-rows x 256 bytes (128 bf16 cols), XOR-swizzled for ldmatrix.
__device__ unsigned char g_wq[48 * 16384];  // QKV: 6 N-tiles x 8 k-chunks
__device__ unsigned char g_wp[16 * 16384];  // proj: 2 N-tiles x 8 k-chunks

// ---------------- helpers ----------------
static __device__ __forceinline__ uint32_t s2u(const void* p) {
    uint32_t a;
    asm("{ .reg .u64 t; cvta.to.shared.u64 t, %1; cvt.u32.u64 %0, t; }" : "=r"(a) : "l"(p));
    return a;
}

// swizzle within a 128-byte segment: conflict-free ldmatrix for row strides
// that are multiples of 128B.
static __device__ __host__ __forceinline__ uint32_t swz(uint32_t byte_in_row, uint32_t row) {
    return (byte_in_row & ~0x7Fu) | ((byte_in_row & 0x7Fu) ^ ((row & 7u) << 4));
}

#define LDSM_X4(r, a)                                                        \
    asm volatile("ldmatrix.sync.aligned.m8n8.x4.shared.b16 {%0,%1,%2,%3}, [%4];" \
        : "=r"((r)[0]), "=r"((r)[1]), "=r"((r)[2]), "=r"((r)[3]) : "r"(a))

#define LDSM_X4T(r, a)                                                       \
    asm volatile("ldmatrix.sync.aligned.m8n8.x4.trans.shared.b16 {%0,%1,%2,%3}, [%4];" \
        : "=r"((r)[0]), "=r"((r)[1]), "=r"((r)[2]), "=r"((r)[3]) : "r"(a))

#define MMA16816(c, a, b)                                                    \
    asm volatile("mma.sync.aligned.m16n8k16.row.col.f32.bf16.bf16.f32 "      \
        "{%0,%1,%2,%3}, {%4,%5,%6,%7}, {%8,%9}, {%0,%1,%2,%3};"              \
        : "+f"((c)[0]), "+f"((c)[1]), "+f"((c)[2]), "+f"((c)[3])             \
        : "r"((a)[0]), "r"((a)[1]), "r"((a)[2]), "r"((a)[3]),                \
          "r"((b)[0]), "r"((b)[1]))

#define CP16(d, s) \
    asm volatile("cp.async.cg.shared.global [%0], [%1], 16;" :: "r"(d), "l"(s) : "memory")
#define CP_COMMIT() asm volatile("cp.async.commit_group;" ::: "memory")
#define CP_WAIT(n)  asm volatile("cp.async.wait_group %0;" :: "n"(n) : "memory")

__device__ __forceinline__ float warp_sum(float v) {
#pragma unroll
    for (int o = 16; o > 0; o >>= 1) v += __shfl_xor_sync(0xffffffffu, v, o);
    return v;
}
__device__ __forceinline__ float warp_max(float v) {
#pragma unroll
    for (int o = 16; o > 0; o >>= 1) v = fmaxf(v, __shfl_xor_sync(0xffffffffu, v, o));
    return v;
}

// =====================================================================
// Kernel 1: CPB-MLP bias table + logit scale  (tiny; one CTA)
// =====================================================================
__device__ __forceinline__ float cpb_coord(int i) {
    float x = (float)(i - 6) * (8.0f / 6.0f);
    return copysignf(log1pf(fabsf(x)) * 0.4808983469629878f, x);
}

__global__ void cpb_kernel(const float* __restrict__ logit_scale,
                           const float* __restrict__ w1,
                           const float* __restrict__ b1,
                           const float* __restrict__ w2,
                           float* __restrict__ bias_out,
                           float* __restrict__ scale_out)
{
    __shared__ float table[169][HEADS];
    const int tid = threadIdx.x;

    if (tid < HEADS) {
        float ls = logit_scale[tid];
        ls = fminf(ls, logf(100.0f));
        ls = fmaxf(ls, -100.0f);
        scale_out[tid] = expf(ls);
    }

    for (int e = tid; e < 169; e += blockDim.x) {
        const int i = e / 13, j = e % 13;
        const float c0 = cpb_coord(i);
        const float c1 = cpb_coord(j);
        float acc[HEADS];
#pragma unroll
        for (int hh = 0; hh < HEADS; hh++) acc[hh] = 0.0f;
        for (int kk = 0; kk < 512; kk++) {
            float hpre = c0 * w1[kk] + c1 * w1[512 + kk] + b1[kk];
            float g = 0.5f * hpre * (1.0f + erff(hpre * 0.7071067811865475f));
#pragma unroll
            for (int hh = 0; hh < HEADS; hh++) acc[hh] += g * w2[kk * 8 + hh];
        }
#pragma unroll
        for (int hh = 0; hh < HEADS; hh++) table[e][hh] = acc[hh];
    }
    __syncthreads();

    for (int idx = tid; idx < HEADS * NTOK * NTOK; idx += blockDim.x) {
        const int hh  = idx / (NTOK * NTOK);
        const int rem = idx % (NTOK * NTOK);
        const int r   = rem / NTOK;
        const int c   = rem % NTOK;
        const int dh  = (r / 7) - (c / 7) + 6;
        const int dw  = (r % 7) - (c % 7) + 6;
        const float v = table[dh * 13 + dw][hh];
        bias_out[idx] = 16.0f / (1.0f + __expf(-v));
    }
}

// =====================================================================
// Kernel 1b: split weights fp32 -> (hi,lo) bf16 chunks, swizzled layout
//   chunk(nt, kc) at (nt*8+kc)*16384; within: hi[kl][swz(nl*2,kl)] (8KB),
//   lo at +8192. kl=0..31 (k = kc*32+kl), nl=0..127 (n = nt*128+nl)
// =====================================================================
__global__ void wsplit_kernel(const float* __restrict__ wq, const float* __restrict__ wp,
                              unsigned char* __restrict__ oq, unsigned char* __restrict__ op)
{
    const int stride = gridDim.x * blockDim.x;
    const int t0 = blockIdx.x * blockDim.x + threadIdx.x;
    for (int idx = t0; idx < 256 * QKVCOL; idx += stride) {
        const int k = idx / QKVCOL, n = idx % QKVCOL;
        float f = wq[idx];
        __nv_bfloat16 h = __float2bfloat16_rn(f);
        __nv_bfloat16 l = __float2bfloat16_rn(f - __bfloat162float(h));
        const uint32_t off = (uint32_t)((n >> 7) * 8 + (k >> 5)) * 16384u
                           + (uint32_t)(k & 31) * 256u + swz((uint32_t)(n & 127) * 2u, (uint32_t)k);
        *(__nv_bfloat16*)(oq + off)        = h;
        *(__nv_bfloat16*)(oq + off + 8192) = l;
    }
    for (int idx = t0; idx < 256 * 256; idx += stride) {
        const int k = idx >> 8, n = idx & 255;
        float f = wp[idx];
        __nv_bfloat16 h = __float2bfloat16_rn(f);
        __nv_bfloat16 l = __float2bfloat16_rn(f - __bfloat162float(h));
        const uint32_t off = (uint32_t)((n >> 7) * 8 + (k >> 5)) * 16384u
                           + (uint32_t)(k & 31) * 256u + swz((uint32_t)(n & 127) * 2u, (uint32_t)k);
        *(__nv_bfloat16*)(op + off)        = h;
        *(__nv_bfloat16*)(op + off + 8192) = l;
    }
}

// =====================================================================
// Kernel 2/4: mma.sync bf16 split GEMM
//   C[M, NT*128] = A[M,256] @ W[256, NT*128] + bias, fp32 in/out,
//   3-product hi/lo split. CTA: 128 M-rows, NT N-tiles of 128.
//   A resident in swizzled SMEM (hi 64KB + lo 64KB); W streamed via
//   cp.async double-buffer (2 x 16KB).
// =====================================================================
#define SMW_OFF 131072
#define GEMM_SMEM (131072 + 32768)

__global__ __launch_bounds__(256, 1)
void gemm_mma(const float* __restrict__ A, const unsigned char* __restrict__ Wp,
              const float* __restrict__ bias, float* __restrict__ C, int NT)
{
    extern __shared__ char smem[];
    const uint32_t sb = s2u(smem);
    const int tid  = threadIdx.x;
    const int lane = tid & 31;
    const int w    = tid >> 5;
    const int row0 = blockIdx.x * 128;
    const int Ncols = NT * 128;

    // ---- A: fp32 -> hi/lo bf16, swizzled SMEM, 128 rows x 512B ----
    for (int i = tid; i < 8192; i += 256) {
        const int r  = i >> 6;
        const int c4 = (i & 63) << 2;
        float4 a = *(const float4*)(A + (size_t)(row0 + r) * 256 + c4);
        __nv_bfloat16 hx = __float2bfloat16_rn(a.x);
        __nv_bfloat16 hy = __float2bfloat16_rn(a.y);
        __nv_bfloat16 hz = __float2bfloat16_rn(a.z);
        __nv_bfloat16 hw = __float2bfloat16_rn(a.w);
        __nv_bfloat16 lx = __float2bfloat16_rn(a.x - __bfloat162float(hx));
        __nv_bfloat16 ly = __float2bfloat16_rn(a.y - __bfloat162float(hy));
        __nv_bfloat16 lz = __float2bfloat16_rn(a.z - __bfloat162float(hz));
        __nv_bfloat16 lw = __float2bfloat16_rn(a.w - __bfloat162float(hw));
        __nv_bfloat162 h01; h01.x = hx; h01.y = hy;
        __nv_bfloat162 h23; h23.x = hz; h23.y = hw;
        __nv_bfloat162 l01; l01.x = lx; l01.y = ly;
        __nv_bfloat162 l23; l23.x = lz; l23.y = lw;
        const uint32_t off = (uint32_t)r * 512u + swz((uint32_t)c4 * 2u, (uint32_t)r);
        uint2 hu; hu.x = *(uint32_t*)&h01; hu.y = *(uint32_t*)&h23;
        uint2 lu; lu.x = *(uint32_t*)&l01; lu.y = *(uint32_t*)&l23;
        *(uint2*)(smem + off)         = hu;
        *(uint2*)(smem + 65536 + off) = lu;
    }
    __syncthreads();

    const int wm = w & 1;        // m0 = wm*64
    const int wn = w >> 1;       // n0 = wn*32

    // prefetch chunk 0 into stage 0
    {
        const unsigned char* src = Wp;
#pragma unroll
        for (int j = 0; j < 4; j++)
            CP16(sb + SMW_OFF + (uint32_t)(tid * 16 + j * 4096), src + tid * 16 + j * 4096);
        CP_COMMIT();
    }

    const int NCH = NT * 8;

    for (int nt = 0; nt < NT; nt++) {
        float acc[4][4][4];
#pragma unroll
        for (int mf = 0; mf < 4; mf++)
#pragma unroll
            for (int nf = 0; nf < 4; nf++)
#pragma unroll
                for (int q = 0; q < 4; q++) acc[mf][nf][q] = 0.0f;

        for (int kc = 0; kc < 8; kc++) {
            const int gc = nt * 8 + kc;
            if (gc + 1 < NCH) {
                const unsigned char* src = Wp + (size_t)(gc + 1) * 16384;
                const uint32_t dst = sb + SMW_OFF + (uint32_t)(((gc + 1) & 1) * 16384);
#pragma unroll
                for (int j = 0; j < 4; j++)
                    CP16(dst + (uint32_t)(tid * 16 + j * 4096), src + tid * 16 + j * 4096);
                CP_COMMIT();
                CP_WAIT(1);
            } else {
                CP_WAIT(0);
            }
            __syncthreads();

            const uint32_t st = sb + SMW_OFF + (uint32_t)((gc & 1) * 16384);

#pragma unroll
            for (int ks = 0; ks < 2; ks++) {
                // A fragments (hi & lo)
                uint32_t ah[4][4], al[4][4];
                const int arow = wm * 64 + (lane & 15);
                const int kg   = kc * 32 + ks * 16 + ((lane >> 4) << 3);
#pragma unroll
                for (int mf = 0; mf < 4; mf++) {
                    const uint32_t r = (uint32_t)(arow + mf * 16);
                    const uint32_t addr = sb + r * 512u + swz((uint32_t)kg * 2u, r);
                    LDSM_X4(ah[mf], addr);
                    LDSM_X4(al[mf], addr + 65536u);
                }
                // B fragments (hi & lo): x4.trans gives two n8 frags each
                uint32_t bh[2][4], bl[2][4];
                const uint32_t krow = (uint32_t)(ks * 16 + ((lane >> 3) & 1) * 8 + (lane & 7));
#pragma unroll
                for (int nf2 = 0; nf2 < 2; nf2++) {
                    const uint32_t ncol = (uint32_t)(wn * 32 + nf2 * 16 + (lane >> 4) * 8);
                    const uint32_t addr = st + krow * 256u + swz(ncol * 2u, krow);
                    LDSM_X4T(bh[nf2], addr);
                    LDSM_X4T(bl[nf2], addr + 8192u);
                }
#pragma unroll
                for (int mf = 0; mf < 4; mf++)
#pragma unroll
                    for (int nf = 0; nf < 4; nf++) {
                        uint32_t* bph = &bh[nf >> 1][(nf & 1) * 2];
                        uint32_t* bpl = &bl[nf >> 1][(nf & 1) * 2];
                        MMA16816(acc[mf][nf], ah[mf], bph);   // hi*hi
                        MMA16816(acc[mf][nf], ah[mf], bpl);   // hi*lo
                        MMA16816(acc[mf][nf], al[mf], bph);   // lo*hi
                    }
            }
            __syncthreads();
        }

        // ---- epilogue: bias + direct stores (float2 per fragment row) ----
        const int g = lane >> 2, t = lane & 3;
#pragma unroll
        for (int nf = 0; nf < 4; nf++) {
            const int col = nt * 128 + wn * 32 + nf * 8 + t * 2;
            const float2 bv = *(const float2*)(bias + col);
#pragma unroll
            for (int mf = 0; mf < 4; mf++) {
                const int row = row0 + wm * 64 + mf * 16 + g;
                float2 v0 = make_float2(acc[mf][nf][0] + bv.x, acc[mf][nf][1] + bv.y);
                float2 v1 = make_float2(acc[mf][nf][2] + bv.x, acc[mf][nf][3] + bv.y);
                *(float2*)(C + (size_t)row * Ncols + col)       = v0;
                *(float2*)(C + (size_t)(row + 8) * Ncols + col) = v1;
            }
        }
    }
}

// =====================================================================
// Kernel 3: per-(window,head) cosine attention (unchanged from R1)
// =====================================================================
__global__ __launch_bounds__(128) void attn_kernel(
    const float* __restrict__ qkv,
    const float* __restrict__ bias,
    const float* __restrict__ scale,
    float* __restrict__ attn_out)
{
    const int b = blockIdx.x;
    const int h = blockIdx.y;

    __shared__ float qs[NTOK][36];
    __shared__ float ks[64][36];
    __shared__ float vs[NTOK][36];
    __shared__ float Pt[NTOK][52];

    const int tid  = threadIdx.x;
    const int lane = tid & 31;
    const int w    = tid >> 5;

    const float* base = qkv + (size_t)b * NTOK * QKVCOL + h * HD;

    for (int idx = tid; idx < NTOK * 8; idx += 128) {
        const int t  = idx >> 3;
        const int d4 = (idx & 7) * 4;
        const float* row = base + (size_t)t * QKVCOL;
        *(float4*)&qs[t][d4] = *(const float4*)(row + 0   + d4);
        *(float4*)&ks[t][d4] = *(const float4*)(row + 256 + d4);
        *(float4*)&vs[t][d4] = *(const float4*)(row + 512 + d4);
    }
    for (int idx = tid; idx < (64 - NTOK) * 36; idx += 128)
        ks[NTOK + idx / 36][idx % 36] = 0.0f;
    __syncthreads();

    const float sc = scale[h];

    for (int r = w; r < NTOK; r += 4) {
        float qv = qs[r][lane];
        float kv = ks[r][lane];
        float qn = warp_sum(qv * qv);
        float kn = warp_sum(kv * kv);
        qs[r][lane] = qv * (rsqrtf(qn) * sc);
        ks[r][lane] = kv * rsqrtf(kn);
    }
    __syncthreads();

    const float* brow = bias + (size_t)h * NTOK * NTOK;
    for (int r = w; r < NTOK; r += 4) {
        const int j  = lane;
        const int j2 = lane + 32;
        float s1 = 0.0f, s2 = 0.0f;
#pragma unroll
        for (int kk4 = 0; kk4 < HD; kk4 += 4) {
            float4 qv = *(const float4*)&qs[r][kk4];
            float4 k1 = *(const float4*)&ks[j][kk4];
            float4 k2 = *(const float4*)&ks[j2][kk4];
            s1 += qv.x * k1.x + qv.y * k1.y + qv.z * k1.z + qv.w * k1.w;
            s2 += qv.x * k2.x + qv.y * k2.y + qv.z * k2.z + qv.w * k2.w;
        }
        s1 += brow[r * NTOK + j];
        s2 = (j2 < NTOK) ? (s2 + brow[r * NTOK + j2]) : -1e30f;

        float mx = warp_max(fmaxf(s1, s2));
        float p1 = __expf(s1 - mx);
        float p2 = (j2 < NTOK) ? __expf(s2 - mx) : 0.0f;
        float rs = 1.0f / warp_sum(p1 + p2);
        Pt[j][r] = p1 * rs;
        if (j2 < NTOK) Pt[j2][r] = p2 * rs;
    }
    __syncthreads();

    float* obase = attn_out + (size_t)b * NTOK * DIMF + h * HD;
    for (int g = w; g < 13; g += 4) {
        const int r0 = g * 4;
        float a0 = 0.f, a1 = 0.f, a2 = 0.f, a3 = 0.f;
#pragma unroll 7
        for (int j = 0; j < NTOK; j++) {
            const float vj = vs[j][lane];
            float4 p = *(const float4*)&Pt[j][r0];
            a0 += p.x * vj;  a1 += p.y * vj;
            a2 += p.z * vj;  a3 += p.w * vj;
        }
        const int rem = NTOK - r0;
        float* o = obase + (size_t)r0 * DIMF;
        o[lane] = a0;
        if (rem > 1) o[DIMF + lane]     = a1;
        if (rem > 2) o[2 * DIMF + lane] = a2;
        if (rem > 3) o[3 * DIMF + lane] = a3;
    }
}

// =====================================================================
// launch
// =====================================================================
extern "C" void kernel_launch(void* const* d_in, const int* in_sizes, int n_in,
                              void* d_out, int out_size)
{
    const float* x           = (const float*)d_in[0];
    const float* qkv_w       = (const float*)d_in[1];
    const float* qkv_b       = (const float*)d_in[2];
    const float* proj_w      = (const float*)d_in[3];
    const float* proj_b      = (const float*)d_in[4];
    const float* logit_scale = (const float*)d_in[5];
    const float* cpb_w1      = (const float*)d_in[6];
    const float* cpb_b1      = (const float*)d_in[7];
    const float* cpb_w2      = (const float*)d_in[8];
    float* out = (float*)d_out;

    float *qkvbuf, *attnbuf, *biasbuf, *scalebuf;
    unsigned char *wqbuf, *wpbuf;
    cudaGetSymbolAddress((void**)&qkvbuf,   g_qkv);
    cudaGetSymbolAddress((void**)&attnbuf,  g_attn);
    cudaGetSymbolAddress((void**)&biasbuf,  g_bias);
    cudaGetSymbolAddress((void**)&scalebuf, g_scale);
    cudaGetSymbolAddress((void**)&wqbuf,    g_wq);
    cudaGetSymbolAddress((void**)&wpbuf,    g_wp);

    cudaFuncSetAttribute(gemm_mma, cudaFuncAttributeMaxDynamicSharedMemorySize, GEMM_SMEM);

    // 1) CPB bias + logit scale, and weight hi/lo split (tiny)
    cpb_kernel<<<1, 256>>>(logit_scale, cpb_w1, cpb_b1, cpb_w2, biasbuf, scalebuf);
    wsplit_kernel<<<128, 256>>>(qkv_w, proj_w, wqbuf, wpbuf);

    // 2) QKV GEMM (mma.sync bf16 split): [100352,256]@[256,768]+b -> g_qkv
    gemm_mma<<<MROWS / 128, 256, GEMM_SMEM>>>(x, wqbuf, qkv_b, qkvbuf, 6);

    // 3) attention per (window, head)
    attn_kernel<<<dim3(B_WIN, HEADS), 128>>>(qkvbuf, biasbuf, scalebuf, attnbuf);

    // 4) proj GEMM: [100352,256]@[256,256]+b -> out
    gemm_mma<<<MROWS / 128, 256, GEMM_SMEM>>>(attnbuf, wpbuf, proj_b, out, 2);
}

// round 4
// speedup vs baseline: 1.6695x; 1.1177x over previous
#include <cuda_runtime.h>
#include <cuda_bf16.h>
#include <cstdint>

// ---------------- problem constants ----------------
#define B_WIN  2048
#define NTOK   49
#define DIMF   256
#define HEADS  8
#define HD     32
#define MROWS  (B_WIN * NTOK)        // 100352
#define QKVCOL 768

// ---------------- scratch (static device globals; no allocation) ----------------
__device__ float g_qkv [MROWS * QKVCOL];    // 308 MB
__device__ float g_attn[MROWS * DIMF];      // 103 MB
__device__ float g_bias[HEADS * 64 * 56];   // padded [8][64][56]; pad rows/cols stay 0
__device__ float g_scale[HEADS];
// pre-split GEMM weights (chunked, swizzled; see wsplit_kernel)
__device__ unsigned char g_wq[48 * 16384];
__device__ unsigned char g_wp[16 * 16384];

// ---------------- helpers ----------------
static __device__ __forceinline__ uint32_t s2u(const void* p) {
    uint32_t a;
    asm("{ .reg .u64 t; cvta.to.shared.u64 t, %1; cvt.u32.u64 %0, t; }" : "=r"(a) : "l"(p));
    return a;
}

// swizzle within a 128-byte segment (16B granularity)
static __device__ __forceinline__ uint32_t swz(uint32_t byte_in_row, uint32_t row) {
    return (byte_in_row & ~0x7Fu) | ((byte_in_row & 0x7Fu) ^ ((row & 7u) << 4));
}

#define LDSM_X4(r, a)                                                        \
    asm volatile("ldmatrix.sync.aligned.m8n8.x4.shared.b16 {%0,%1,%2,%3}, [%4];" \
        : "=r"((r)[0]), "=r"((r)[1]), "=r"((r)[2]), "=r"((r)[3]) : "r"(a))

#define LDSM_X4T(r, a)                                                       \
    asm volatile("ldmatrix.sync.aligned.m8n8.x4.trans.shared.b16 {%0,%1,%2,%3}, [%4];" \
        : "=r"((r)[0]), "=r"((r)[1]), "=r"((r)[2]), "=r"((r)[3]) : "r"(a))

#define MMA16816(c, a, b)                                                    \
    asm volatile("mma.sync.aligned.m16n8k16.row.col.f32.bf16.bf16.f32 "      \
        "{%0,%1,%2,%3}, {%4,%5,%6,%7}, {%8,%9}, {%0,%1,%2,%3};"              \
        : "+f"((c)[0]), "+f"((c)[1]), "+f"((c)[2]), "+f"((c)[3])             \
        : "r"((a)[0]), "r"((a)[1]), "r"((a)[2]), "r"((a)[3]),                \
          "r"((b)[0]), "r"((b)[1]))

#define CP16(d, s) \
    asm volatile("cp.async.cg.shared.global [%0], [%1], 16;" :: "r"(d), "l"(s) : "memory")
#define CP_COMMIT() asm volatile("cp.async.commit_group;" ::: "memory")
#define CP_WAIT(n)  asm volatile("cp.async.wait_group %0;" :: "n"(n) : "memory")

// pack two fp32 -> bf16x2 register: lo = x, hi = y
static __device__ __forceinline__ uint32_t pk2(float x, float y) {
    uint32_t r;
    asm("cvt.rn.bf16x2.f32 %0, %1, %2;" : "=r"(r) : "f"(y), "f"(x));
    return r;
}
static __device__ __forceinline__ float rbf(float x) {   // round-to-bf16 value
    return __bfloat162float(__float2bfloat16_rn(x));
}

// =====================================================================
// Kernel 1: CPB-MLP bias table + logit scale  (tiny; one CTA)
//   writes padded bias [8][64][56]; entries outside [49][49] remain 0
// =====================================================================
__device__ __forceinline__ float cpb_coord(int i) {
    float x = (float)(i - 6) * (8.0f / 6.0f);
    return copysignf(log1pf(fabsf(x)) * 0.4808983469629878f, x);
}

__global__ void cpb_kernel(const float* __restrict__ logit_scale,
                           const float* __restrict__ w1,
                           const float* __restrict__ b1,
                           const float* __restrict__ w2,
                           float* __restrict__ bias_out,   // [8][64][56]
                           float* __restrict__ scale_out)
{
    __shared__ float table[169][HEADS];
    const int tid = threadIdx.x;

    if (tid < HEADS) {
        float ls = logit_scale[tid];
        ls = fminf(ls, logf(100.0f));
        ls = fmaxf(ls, -100.0f);
        scale_out[tid] = expf(ls);
    }

    for (int e = tid; e < 169; e += blockDim.x) {
        const int i = e / 13, j = e % 13;
        const float c0 = cpb_coord(i);
        const float c1 = cpb_coord(j);
        float acc[HEADS];
#pragma unroll
        for (int hh = 0; hh < HEADS; hh++) acc[hh] = 0.0f;
        for (int kk = 0; kk < 512; kk++) {
            float hpre = c0 * w1[kk] + c1 * w1[512 + kk] + b1[kk];
            float g = 0.5f * hpre * (1.0f + erff(hpre * 0.7071067811865475f));
#pragma unroll
            for (int hh = 0; hh < HEADS; hh++) acc[hh] += g * w2[kk * 8 + hh];
        }
#pragma unroll
        for (int hh = 0; hh < HEADS; hh++) table[e][hh] = acc[hh];
    }
    __syncthreads();

    for (int idx = tid; idx < HEADS * NTOK * NTOK; idx += blockDim.x) {
        const int hh  = idx / (NTOK * NTOK);
        const int rem = idx % (NTOK * NTOK);
        const int r   = rem / NTOK;
        const int c   = rem % NTOK;
        const int dh  = (r / 7) - (c / 7) + 6;
        const int dw  = (r % 7) - (c % 7) + 6;
        const float v = table[dh * 13 + dw][hh];
        bias_out[hh * 3584 + r * 56 + c] = 16.0f / (1.0f + __expf(-v));
    }
}

// =====================================================================
// Kernel 1b: split weights fp32 -> (hi,lo) bf16 chunks, swizzled layout
// =====================================================================
__global__ void wsplit_kernel(const float* __restrict__ wq, const float* __restrict__ wp,
                              unsigned char* __restrict__ oq, unsigned char* __restrict__ op)
{
    const int stride = gridDim.x * blockDim.x;
    const int t0 = blockIdx.x * blockDim.x + threadIdx.x;
    for (int idx = t0; idx < 256 * QKVCOL; idx += stride) {
        const int k = idx / QKVCOL, n = idx % QKVCOL;
        float f = wq[idx];
        __nv_bfloat16 h = __float2bfloat16_rn(f);
        __nv_bfloat16 l = __float2bfloat16_rn(f - __bfloat162float(h));
        const uint32_t off = (uint32_t)((n >> 7) * 8 + (k >> 5)) * 16384u
                           + (uint32_t)(k & 31) * 256u + swz((uint32_t)(n & 127) * 2u, (uint32_t)k);
        *(__nv_bfloat16*)(oq + off)        = h;
        *(__nv_bfloat16*)(oq + off + 8192) = l;
    }
    for (int idx = t0; idx < 256 * 256; idx += stride) {
        const int k = idx >> 8, n = idx & 255;
        float f = wp[idx];
        __nv_bfloat16 h = __float2bfloat16_rn(f);
        __nv_bfloat16 l = __float2bfloat16_rn(f - __bfloat162float(h));
        const uint32_t off = (uint32_t)((n >> 7) * 8 + (k >> 5)) * 16384u
                           + (uint32_t)(k & 31) * 256u + swz((uint32_t)(n & 127) * 2u, (uint32_t)k);
        *(__nv_bfloat16*)(op + off)        = h;
        *(__nv_bfloat16*)(op + off + 8192) = l;
    }
}

// =====================================================================
// Kernel 2/4: mma.sync bf16 split GEMM (unchanged from R3)
// =====================================================================
#define SMW_OFF 131072
#define GEMM_SMEM (131072 + 32768)

__global__ __launch_bounds__(256, 1)
void gemm_mma(const float* __restrict__ A, const unsigned char* __restrict__ Wp,
              const float* __restrict__ bias, float* __restrict__ C, int NT)
{
    extern __shared__ char smem[];
    const uint32_t sb = s2u(smem);
    const int tid  = threadIdx.x;
    const int lane = tid & 31;
    const int w    = tid >> 5;
    const int row0 = blockIdx.x * 128;
    const int Ncols = NT * 128;

    for (int i = tid; i < 8192; i += 256) {
        const int r  = i >> 6;
        const int c4 = (i & 63) << 2;
        float4 a = *(const float4*)(A + (size_t)(row0 + r) * 256 + c4);
        float hx = rbf(a.x), hy = rbf(a.y), hz = rbf(a.z), hw = rbf(a.w);
        const uint32_t off = (uint32_t)r * 512u + swz((uint32_t)c4 * 2u, (uint32_t)r);
        uint2 hu; hu.x = pk2(hx, hy); hu.y = pk2(hz, hw);
        uint2 lu; lu.x = pk2(a.x - hx, a.y - hy); lu.y = pk2(a.z - hz, a.w - hw);
        *(uint2*)(smem + off)         = hu;
        *(uint2*)(smem + 65536 + off) = lu;
    }
    __syncthreads();

    const int wm = w & 1;
    const int wn = w >> 1;

    {
        const unsigned char* src = Wp;
#pragma unroll
        for (int j = 0; j < 4; j++)
            CP16(sb + SMW_OFF + (uint32_t)(tid * 16 + j * 4096), src + tid * 16 + j * 4096);
        CP_COMMIT();
    }

    const int NCH = NT * 8;

    for (int nt = 0; nt < NT; nt++) {
        float acc[4][4][4];
#pragma unroll
        for (int mf = 0; mf < 4; mf++)
#pragma unroll
            for (int nf = 0; nf < 4; nf++)
#pragma unroll
                for (int q = 0; q < 4; q++) acc[mf][nf][q] = 0.0f;

        for (int kc = 0; kc < 8; kc++) {
            const int gc = nt * 8 + kc;
            if (gc + 1 < NCH) {
                const unsigned char* src = Wp + (size_t)(gc + 1) * 16384;
                const uint32_t dst = sb + SMW_OFF + (uint32_t)(((gc + 1) & 1) * 16384);
#pragma unroll
                for (int j = 0; j < 4; j++)
                    CP16(dst + (uint32_t)(tid * 16 + j * 4096), src + tid * 16 + j * 4096);
                CP_COMMIT();
                CP_WAIT(1);
            } else {
                CP_WAIT(0);
            }
            __syncthreads();

            const uint32_t st = sb + SMW_OFF + (uint32_t)((gc & 1) * 16384);

#pragma unroll
            for (int ks = 0; ks < 2; ks++) {
                uint32_t ah[4][4], al[4][4];
                const int arow = wm * 64 + (lane & 15);
                const int kg   = kc * 32 + ks * 16 + ((lane >> 4) << 3);
#pragma unroll
                for (int mf = 0; mf < 4; mf++) {
                    const uint32_t r = (uint32_t)(arow + mf * 16);
                    const uint32_t addr = sb + r * 512u + swz((uint32_t)kg * 2u, r);
                    LDSM_X4(ah[mf], addr);
                    LDSM_X4(al[mf], addr + 65536u);
                }
                uint32_t bh[2][4], bl[2][4];
                const uint32_t krow = (uint32_t)(ks * 16 + ((lane >> 3) & 1) * 8 + (lane & 7));
#pragma unroll
                for (int nf2 = 0; nf2 < 2; nf2++) {
                    const uint32_t ncol = (uint32_t)(wn * 32 + nf2 * 16 + (lane >> 4) * 8);
                    const uint32_t addr = st + krow * 256u + swz(ncol * 2u, krow);
                    LDSM_X4T(bh[nf2], addr);
                    LDSM_X4T(bl[nf2], addr + 8192u);
                }
#pragma unroll
                for (int mf = 0; mf < 4; mf++)
#pragma unroll
                    for (int nf = 0; nf < 4; nf++) {
                        uint32_t* bph = &bh[nf >> 1][(nf & 1) * 2];
                        uint32_t* bpl = &bl[nf >> 1][(nf & 1) * 2];
                        MMA16816(acc[mf][nf], ah[mf], bph);
                        MMA16816(acc[mf][nf], ah[mf], bpl);
                        MMA16816(acc[mf][nf], al[mf], bph);
                    }
            }
            __syncthreads();
        }

        const int g = lane >> 2, t = lane & 3;
#pragma unroll
        for (int nf = 0; nf < 4; nf++) {
            const int col = nt * 128 + wn * 32 + nf * 8 + t * 2;
            const float2 bv = *(const float2*)(bias + col);
#pragma unroll
            for (int mf = 0; mf < 4; mf++) {
                const int row = row0 + wm * 64 + mf * 16 + g;
                float2 v0 = make_float2(acc[mf][nf][0] + bv.x, acc[mf][nf][1] + bv.y);
                float2 v1 = make_float2(acc[mf][nf][2] + bv.x, acc[mf][nf][3] + bv.y);
                *(float2*)(C + (size_t)row * Ncols + col)       = v0;
                *(float2*)(C + (size_t)(row + 8) * Ncols + col) = v1;
            }
        }
    }
}

// =====================================================================
// Kernel 3: tensor-core window attention
//   CTA = one window (256 threads, 8 warps; warp w = head w).
//   SMEM: Q,K,V each [64 rows][8 heads x 32 dims] bf16 hi+lo, swizzled.
//   QK^T and PV via mma.m16n8k16 with 3-product hi/lo split.
// =====================================================================
#define SQH 0
#define SQL 32768
#define SKH 65536
#define SKL 98304
#define SVH 131072
#define SVL 163840
#define ATTN_SMEM 196608

__global__ __launch_bounds__(256, 1)
void attn_tc(const float* __restrict__ qkv,
             const float* __restrict__ bias,    // [8][64][56] padded
             const float* __restrict__ scale,
             float* __restrict__ attn_out)
{
    extern __shared__ char smem[];
    const uint32_t sb = s2u(smem);
    const int b    = blockIdx.x;
    const int tid  = threadIdx.x;
    const int lane = tid & 31;
    const int wrp  = tid >> 5;

    // ---- zero pad rows 49..63 of all 6 regions ----
    for (int i = tid; i < 6 * 15 * 32; i += 256) {
        const int reg = i / (15 * 32);
        const int rem = i % (15 * 32);
        const int r   = 49 + rem / 32;
        const int c   = rem % 32;
        *(uint4*)(smem + reg * 32768 + r * 512 + c * 16) = make_uint4(0, 0, 0, 0);
    }

    // ---- load + normalize + split q,k ; split v ----
    {
        const float* wb = qkv + (size_t)b * NTOK * QKVCOL;
        const int team = tid >> 3, l8 = tid & 7;
        for (int it = team; it < 392; it += 32) {
            const int tok = it >> 3, hh = it & 7;
            const float* rowp = wb + (size_t)tok * QKVCOL + hh * HD + l8 * 4;
            float4 q = *(const float4*)(rowp);
            float4 k = *(const float4*)(rowp + 256);
            float4 v = *(const float4*)(rowp + 512);
            float qss = q.x*q.x + q.y*q.y + q.z*q.z + q.w*q.w;
            float kss = k.x*k.x + k.y*k.y + k.z*k.z + k.w*k.w;
#pragma unroll
            for (int o = 4; o > 0; o >>= 1) {
                qss += __shfl_xor_sync(0xffffffffu, qss, o);
                kss += __shfl_xor_sync(0xffffffffu, kss, o);
            }
            const float qr = rsqrtf(qss) * __ldg(scale + hh);
            const float kr = rsqrtf(kss);
            q.x *= qr; q.y *= qr; q.z *= qr; q.w *= qr;
            k.x *= kr; k.y *= kr; k.z *= kr; k.w *= kr;

            const uint32_t off = (uint32_t)tok * 512u
                               + swz((uint32_t)(hh * 64 + l8 * 8), (uint32_t)tok);
            // q
            {
                float hx = rbf(q.x), hy = rbf(q.y), hz = rbf(q.z), hw = rbf(q.w);
                uint2 hu; hu.x = pk2(hx, hy); hu.y = pk2(hz, hw);
                uint2 lu; lu.x = pk2(q.x - hx, q.y - hy); lu.y = pk2(q.z - hz, q.w - hw);
                *(uint2*)(smem + SQH + off) = hu;
                *(uint2*)(smem + SQL + off) = lu;
            }
            // k
            {
                float hx = rbf(k.x), hy = rbf(k.y), hz = rbf(k.z), hw = rbf(k.w);
                uint2 hu; hu.x = pk2(hx, hy); hu.y = pk2(hz, hw);
                uint2 lu; lu.x = pk2(k.x - hx, k.y - hy); lu.y = pk2(k.z - hz, k.w - hw);
                *(uint2*)(smem + SKH + off) = hu;
                *(uint2*)(smem + SKL + off) = lu;
            }
            // v
            {
                float hx = rbf(v.x), hy = rbf(v.y), hz = rbf(v.z), hw = rbf(v.w);
                uint2 hu; hu.x = pk2(hx, hy); hu.y = pk2(hz, hw);
                uint2 lu; lu.x = pk2(v.x - hx, v.y - hy); lu.y = pk2(v.z - hz, v.w - hw);
                *(uint2*)(smem + SVH + off) = hu;
                *(uint2*)(smem + SVL + off) = lu;
            }
        }
    }
    __syncthreads();

    // ---- per-warp head compute ----
    const int h = wrp;
    const float* bslab = bias + h * 3584;
    float* obase = attn_out + (size_t)b * NTOK * DIMF + h * HD;
    const int qrow = lane >> 2;
    const int qc   = (lane & 3) * 2;

    for (int mh = 0; mh < 2; mh++) {
        const int m0 = mh * 32;

        float S[2][7][4];
#pragma unroll
        for (int a = 0; a < 2; a++)
#pragma unroll
            for (int n = 0; n < 7; n++)
#pragma unroll
                for (int q = 0; q < 4; q++) S[a][n][q] = 0.0f;

        // ---- S = Qn * Kn^T (3-product split) ----
#pragma unroll
        for (int ks = 0; ks < 2; ks++) {
            uint32_t ah[2][4], al[2][4];
            {
                const int rr = m0 + ((lane >> 3) & 1) * 8 + (lane & 7);
                const int cb = h * 64 + ks * 32 + (lane >> 4) * 16;
#pragma unroll
                for (int mf2 = 0; mf2 < 2; mf2++) {
                    const uint32_t r = (uint32_t)(rr + mf2 * 16);
                    const uint32_t ad = sb + SQH + r * 512u + swz((uint32_t)cb, r);
                    LDSM_X4(ah[mf2], ad);
                    LDSM_X4(al[mf2], ad + 32768u);
                }
            }
#pragma unroll
            for (int ng = 0; ng < 4; ng++) {
                uint32_t bh[4], bl[4];
                const uint32_t r = (uint32_t)(ng * 16 + (lane & 7) + ((lane >> 4) << 3));
                const uint32_t cb = (uint32_t)(h * 64 + ks * 32 + ((lane >> 3) & 1) * 16);
                const uint32_t ad = sb + SKH + r * 512u + swz(cb, r);
                LDSM_X4(bh, ad);
                LDSM_X4(bl, ad + 32768u);
#pragma unroll
                for (int mf2 = 0; mf2 < 2; mf2++) {
                    MMA16816(S[mf2][2 * ng], ah[mf2], bh);
                    MMA16816(S[mf2][2 * ng], ah[mf2], bl);
                    MMA16816(S[mf2][2 * ng], al[mf2], bh);
                    if (ng < 3) {
                        MMA16816(S[mf2][2 * ng + 1], ah[mf2], bh + 2);
                        MMA16816(S[mf2][2 * ng + 1], ah[mf2], bl + 2);
                        MMA16816(S[mf2][2 * ng + 1], al[mf2], bh + 2);
                    }
                }
            }
        }

        // ---- softmax (in fragment registers) ----
#pragma unroll
        for (int mf2 = 0; mf2 < 2; mf2++) {
            const int r0 = m0 + mf2 * 16 + qrow;
            float mx0 = -1e30f, mx1 = -1e30f;
#pragma unroll
            for (int nf = 0; nf < 7; nf++) {
                const int c0 = nf * 8 + qc;
                const float2 b0 = *(const float2*)(bslab + r0 * 56 + c0);
                const float2 b1 = *(const float2*)(bslab + (r0 + 8) * 56 + c0);
                S[mf2][nf][0] = (c0     < 49) ? S[mf2][nf][0] + b0.x : -1e30f;
                S[mf2][nf][1] = (c0 + 1 < 49) ? S[mf2][nf][1] + b0.y : -1e30f;
                S[mf2][nf][2] = (c0     < 49) ? S[mf2][nf][2] + b1.x : -1e30f;
                S[mf2][nf][3] = (c0 + 1 < 49) ? S[mf2][nf][3] + b1.y : -1e30f;
                mx0 = fmaxf(mx0, fmaxf(S[mf2][nf][0], S[mf2][nf][1]));
                mx1 = fmaxf(mx1, fmaxf(S[mf2][nf][2], S[mf2][nf][3]));
            }
#pragma unroll
            for (int o = 1; o < 4; o <<= 1) {
                mx0 = fmaxf(mx0, __shfl_xor_sync(0xffffffffu, mx0, o));
                mx1 = fmaxf(mx1, __shfl_xor_sync(0xffffffffu, mx1, o));
            }
            float rs0 = 0.0f, rs1 = 0.0f;
#pragma unroll
            for (int nf = 0; nf < 7; nf++) {
                float p0 = __expf(S[mf2][nf][0] - mx0);
                float p1 = __expf(S[mf2][nf][1] - mx0);
                float p2 = __expf(S[mf2][nf][2] - mx1);
                float p3 = __expf(S[mf2][nf][3] - mx1);
                S[mf2][nf][0] = p0; S[mf2][nf][1] = p1;
                S[mf2][nf][2] = p2; S[mf2][nf][3] = p3;
                rs0 += p0 + p1;  rs1 += p2 + p3;
            }
#pragma unroll
            for (int o = 1; o < 4; o <<= 1) {
                rs0 += __shfl_xor_sync(0xffffffffu, rs0, o);
                rs1 += __shfl_xor_sync(0xffffffffu, rs1, o);
            }
            const float iv0 = 1.0f / rs0, iv1 = 1.0f / rs1;
#pragma unroll
            for (int nf = 0; nf < 7; nf++) {
                S[mf2][nf][0] *= iv0; S[mf2][nf][1] *= iv0;
                S[mf2][nf][2] *= iv1; S[mf2][nf][3] *= iv1;
            }
        }

        // ---- O = P * V (3-product split; P->A-frag is register packing) ----
        float O[2][4][4];
#pragma unroll
        for (int a = 0; a < 2; a++)
#pragma unroll
            for (int n = 0; n < 4; n++)
#pragma unroll
                for (int q = 0; q < 4; q++) O[a][n][q] = 0.0f;

#pragma unroll
        for (int kt = 0; kt < 4; kt++) {
            uint32_t ph[2][4], pl[2][4];
#pragma unroll
            for (int mf2 = 0; mf2 < 2; mf2++) {
                const int nfA = 2 * kt;
                float pa0 = S[mf2][nfA][0], pa1 = S[mf2][nfA][1];
                float pa2 = S[mf2][nfA][2], pa3 = S[mf2][nfA][3];
                float pb0 = 0.f, pb1 = 0.f, pb2 = 0.f, pb3 = 0.f;
                if (kt < 3) {
                    pb0 = S[mf2][nfA + 1][0]; pb1 = S[mf2][nfA + 1][1];
                    pb2 = S[mf2][nfA + 1][2]; pb3 = S[mf2][nfA + 1][3];
                }
                const float ha0 = rbf(pa0), ha1 = rbf(pa1), ha2 = rbf(pa2), ha3 = rbf(pa3);
                const float hb0 = rbf(pb0), hb1 = rbf(pb1), hb2 = rbf(pb2), hb3 = rbf(pb3);
                ph[mf2][0] = pk2(ha0, ha1);  ph[mf2][1] = pk2(ha2, ha3);
                ph[mf2][2] = pk2(hb0, hb1);  ph[mf2][3] = pk2(hb2, hb3);
                pl[mf2][0] = pk2(pa0 - ha0, pa1 - ha1);
                pl[mf2][1] = pk2(pa2 - ha2, pa3 - ha3);
                pl[mf2][2] = pk2(pb0 - hb0, pb1 - hb1);
                pl[mf2][3] = pk2(pb2 - hb2, pb3 - hb3);
            }
#pragma unroll
            for (int vg = 0; vg < 2; vg++) {
                uint32_t vh[4], vl[4];
                const uint32_t kr = (uint32_t)(kt * 16 + ((lane >> 3) & 1) * 8 + (lane & 7));
                const uint32_t cb = (uint32_t)(h * 64 + (vg * 16 + (lane >> 4) * 8) * 2);
                const uint32_t ad = sb + SVH + kr * 512u + swz(cb, kr);
                LDSM_X4T(vh, ad);
                LDSM_X4T(vl, ad + 32768u);
#pragma unroll
                for (int mf2 = 0; mf2 < 2; mf2++)
#pragma unroll
                    for (int nn = 0; nn < 2; nn++) {
                        float* oo = O[mf2][vg * 2 + nn];
                        MMA16816(oo, ph[mf2], vh + nn * 2);
                        MMA16816(oo, ph[mf2], vl + nn * 2);
                        MMA16816(oo, pl[mf2], vh + nn * 2);
                    }
            }
        }

        // ---- store O rows < 49 ----
#pragma unroll
        for (int mf2 = 0; mf2 < 2; mf2++) {
            const int r0 = m0 + mf2 * 16 + qrow;
#pragma unroll
            for (int nf = 0; nf < 4; nf++) {
                const int c = nf * 8 + qc;
                if (r0 < NTOK)
                    *(float2*)(obase + (size_t)r0 * DIMF + c) =
                        make_float2(O[mf2][nf][0], O[mf2][nf][1]);
                if (r0 + 8 < NTOK)
                    *(float2*)(obase + (size_t)(r0 + 8) * DIMF + c) =
                        make_float2(O[mf2][nf][2], O[mf2][nf][3]);
            }
        }
    }
}

// =====================================================================
// launch
// =====================================================================
extern "C" void kernel_launch(void* const* d_in, const int* in_sizes, int n_in,
                              void* d_out, int out_size)
{
    const float* x           = (const float*)d_in[0];
    const float* qkv_w       = (const float*)d_in[1];
    const float* qkv_b       = (const float*)d_in[2];
    const float* proj_w      = (const float*)d_in[3];
    const float* proj_b      = (const float*)d_in[4];
    const float* logit_scale = (const float*)d_in[5];
    const float* cpb_w1      = (const float*)d_in[6];
    const float* cpb_b1      = (const float*)d_in[7];
    const float* cpb_w2      = (const float*)d_in[8];
    float* out = (float*)d_out;

    float *qkvbuf, *attnbuf, *biasbuf, *scalebuf;
    unsigned char *wqbuf, *wpbuf;
    cudaGetSymbolAddress((void**)&qkvbuf,   g_qkv);
    cudaGetSymbolAddress((void**)&attnbuf,  g_attn);
    cudaGetSymbolAddress((void**)&biasbuf,  g_bias);
    cudaGetSymbolAddress((void**)&scalebuf, g_scale);
    cudaGetSymbolAddress((void**)&wqbuf,    g_wq);
    cudaGetSymbolAddress((void**)&wpbuf,    g_wp);

    cudaFuncSetAttribute(gemm_mma, cudaFuncAttributeMaxDynamicSharedMemorySize, GEMM_SMEM);
    cudaFuncSetAttribute(attn_tc,  cudaFuncAttributeMaxDynamicSharedMemorySize, ATTN_SMEM);

    cpb_kernel<<<1, 256>>>(logit_scale, cpb_w1, cpb_b1, cpb_w2, biasbuf, scalebuf);
    wsplit_kernel<<<128, 256>>>(qkv_w, proj_w, wqbuf, wpbuf);

    gemm_mma<<<MROWS / 128, 256, GEMM_SMEM>>>(x, wqbuf, qkv_b, qkvbuf, 6);

    attn_tc<<<B_WIN, 256, ATTN_SMEM>>>(qkvbuf, biasbuf, scalebuf, attnbuf);

    gemm_mma<<<MROWS / 128, 256, GEMM_SMEM>>>(attnbuf, wpbuf, proj_b, out, 2);
}

// round 5
// speedup vs baseline: 1.9026x; 1.1396x over previous
#include <cuda_runtime.h>
#include <cuda_bf16.h>
#include <cstdint>

// ---------------- problem constants ----------------
#define B_WIN  2048
#define NTOK   49
#define DIMF   256
#define HEADS  8
#define HD     32
#define MROWS  (B_WIN * NTOK)        // 100352
#define QKVCOL 768

// ---------------- scratch ----------------
__device__ float g_qkv [MROWS * QKVCOL];
__device__ float g_attn[MROWS * DIMF];
__device__ float g_bias[HEADS * 64 * 56];   // padded [8][64][56]; pads stay 0
__device__ float g_scale[HEADS];
__device__ unsigned char g_wq[48 * 16384];
__device__ unsigned char g_wp[16 * 16384];

// ---------------- helpers ----------------
static __device__ __forceinline__ uint32_t s2u(const void* p) {
    uint32_t a;
    asm("{ .reg .u64 t; cvta.to.shared.u64 t, %1; cvt.u32.u64 %0, t; }" : "=r"(a) : "l"(p));
    return a;
}
// swizzle for 128B-multiple row strides (16B granularity within 128B segment)
static __device__ __forceinline__ uint32_t swz(uint32_t byte_in_row, uint32_t row) {
    return (byte_in_row & ~0x7Fu) | ((byte_in_row & 0x7Fu) ^ ((row & 7u) << 4));
}
// swizzle for 64B row stride: permute 16B chunk index (0..3) by (row>>1)&3
static __device__ __forceinline__ uint32_t swz64(uint32_t c, uint32_t row) {
    return (c & 0xFu) | (((((c >> 4) ^ ((row >> 1) & 3u))) & 3u) << 4);
}

#define LDSM_X4(r, a)                                                        \
    asm volatile("ldmatrix.sync.aligned.m8n8.x4.shared.b16 {%0,%1,%2,%3}, [%4];" \
        : "=r"((r)[0]), "=r"((r)[1]), "=r"((r)[2]), "=r"((r)[3]) : "r"(a))
#define LDSM_X4T(r, a)                                                       \
    asm volatile("ldmatrix.sync.aligned.m8n8.x4.trans.shared.b16 {%0,%1,%2,%3}, [%4];" \
        : "=r"((r)[0]), "=r"((r)[1]), "=r"((r)[2]), "=r"((r)[3]) : "r"(a))
#define MMA16816(c, a, b)                                                    \
    asm volatile("mma.sync.aligned.m16n8k16.row.col.f32.bf16.bf16.f32 "      \
        "{%0,%1,%2,%3}, {%4,%5,%6,%7}, {%8,%9}, {%0,%1,%2,%3};"              \
        : "+f"((c)[0]), "+f"((c)[1]), "+f"((c)[2]), "+f"((c)[3])             \
        : "r"((a)[0]), "r"((a)[1]), "r"((a)[2]), "r"((a)[3]),                \
          "r"((b)[0]), "r"((b)[1]))
#define CP16(d, s) \
    asm volatile("cp.async.cg.shared.global [%0], [%1], 16;" :: "r"(d), "l"(s) : "memory")
#define CP_COMMIT() asm volatile("cp.async.commit_group;" ::: "memory")
#define CP_WAIT(n)  asm volatile("cp.async.wait_group %0;" :: "n"(n) : "memory")

static __device__ __forceinline__ uint32_t pk2(float x, float y) {
    uint32_t r;
    asm("cvt.rn.bf16x2.f32 %0, %1, %2;" : "=r"(r) : "f"(y), "f"(x));
    return r;
}
static __device__ __forceinline__ float rbf(float x) {
    return __bfloat162float(__float2bfloat16_rn(x));
}

// =====================================================================
// Kernel 1: CPB-MLP bias table + logit scale
// =====================================================================
__device__ __forceinline__ float cpb_coord(int i) {
    float x = (float)(i - 6) * (8.0f / 6.0f);
    return copysignf(log1pf(fabsf(x)) * 0.4808983469629878f, x);
}

__global__ void cpb_kernel(const float* __restrict__ logit_scale,
                           const float* __restrict__ w1,
                           const float* __restrict__ b1,
                           const float* __restrict__ w2,
                           float* __restrict__ bias_out,
                           float* __restrict__ scale_out)
{
    __shared__ float table[169][HEADS];
    const int tid = threadIdx.x;

    if (tid < HEADS) {
        float ls = logit_scale[tid];
        ls = fminf(ls, logf(100.0f));
        ls = fmaxf(ls, -100.0f);
        scale_out[tid] = expf(ls);
    }
    for (int e = tid; e < 169; e += blockDim.x) {
        const int i = e / 13, j = e % 13;
        const float c0 = cpb_coord(i);
        const float c1 = cpb_coord(j);
        float acc[HEADS];
#pragma unroll
        for (int hh = 0; hh < HEADS; hh++) acc[hh] = 0.0f;
        for (int kk = 0; kk < 512; kk++) {
            float hpre = c0 * w1[kk] + c1 * w1[512 + kk] + b1[kk];
            float g = 0.5f * hpre * (1.0f + erff(hpre * 0.7071067811865475f));
#pragma unroll
            for (int hh = 0; hh < HEADS; hh++) acc[hh] += g * w2[kk * 8 + hh];
        }
#pragma unroll
        for (int hh = 0; hh < HEADS; hh++) table[e][hh] = acc[hh];
    }
    __syncthreads();

    for (int idx = tid; idx < HEADS * NTOK * NTOK; idx += blockDim.x) {
        const int hh  = idx / (NTOK * NTOK);
        const int rem = idx % (NTOK * NTOK);
        const int r   = rem / NTOK;
        const int c   = rem % NTOK;
        const int dh  = (r / 7) - (c / 7) + 6;
        const int dw  = (r % 7) - (c % 7) + 6;
        const float v = table[dh * 13 + dw][hh];
        bias_out[hh * 3584 + r * 56 + c] = 16.0f / (1.0f + __expf(-v));
    }
}

// =====================================================================
// Kernel 1b: split weights fp32 -> hi/lo bf16 chunks, swizzled
// =====================================================================
__global__ void wsplit_kernel(const float* __restrict__ wq, const float* __restrict__ wp,
                              unsigned char* __restrict__ oq, unsigned char* __restrict__ op)
{
    const int stride = gridDim.x * blockDim.x;
    const int t0 = blockIdx.x * blockDim.x + threadIdx.x;
    for (int idx = t0; idx < 256 * QKVCOL; idx += stride) {
        const int k = idx / QKVCOL, n = idx % QKVCOL;
        float f = wq[idx];
        __nv_bfloat16 h = __float2bfloat16_rn(f);
        __nv_bfloat16 l = __float2bfloat16_rn(f - __bfloat162float(h));
        const uint32_t off = (uint32_t)((n >> 7) * 8 + (k >> 5)) * 16384u
                           + (uint32_t)(k & 31) * 256u + swz((uint32_t)(n & 127) * 2u, (uint32_t)k);
        *(__nv_bfloat16*)(oq + off)        = h;
        *(__nv_bfloat16*)(oq + off + 8192) = l;
    }
    for (int idx = t0; idx < 256 * 256; idx += stride) {
        const int k = idx >> 8, n = idx & 255;
        float f = wp[idx];
        __nv_bfloat16 h = __float2bfloat16_rn(f);
        __nv_bfloat16 l = __float2bfloat16_rn(f - __bfloat162float(h));
        const uint32_t off = (uint32_t)((n >> 7) * 8 + (k >> 5)) * 16384u
                           + (uint32_t)(k & 31) * 256u + swz((uint32_t)(n & 127) * 2u, (uint32_t)k);
        *(__nv_bfloat16*)(op + off)        = h;
        *(__nv_bfloat16*)(op + off + 8192) = l;
    }
}

// =====================================================================
// Kernel 2/4: mma.sync split-bf16 GEMM — M-tile 64, 3-stage cp.async,
//   2 CTAs/SM. smem: A hi 32KB | A lo 32KB | 3 x 16KB W stages = 112KB.
// =====================================================================
#define SMW_OFF 65536
#define GEMM_SMEM (65536 + 3 * 16384)

__global__ __launch_bounds__(256, 2)
void gemm_mma(const float* __restrict__ A, const unsigned char* __restrict__ Wp,
              const float* __restrict__ bias, float* __restrict__ C, int NT)
{
    extern __shared__ char smem[];
    const uint32_t sb = s2u(smem);
    const int tid  = threadIdx.x;
    const int lane = tid & 31;
    const int w    = tid >> 5;
    const int row0 = blockIdx.x * 64;
    const int Ncols = NT * 128;

    // A: fp32 -> hi/lo bf16, 64 rows x 512B, swizzled
    for (int i = tid; i < 4096; i += 256) {
        const int r  = i >> 6;
        const int c4 = (i & 63) << 2;
        float4 a = *(const float4*)(A + (size_t)(row0 + r) * 256 + c4);
        float hx = rbf(a.x), hy = rbf(a.y), hz = rbf(a.z), hw = rbf(a.w);
        const uint32_t off = (uint32_t)r * 512u + swz((uint32_t)c4 * 2u, (uint32_t)r);
        uint2 hu; hu.x = pk2(hx, hy); hu.y = pk2(hz, hw);
        uint2 lu; lu.x = pk2(a.x - hx, a.y - hy); lu.y = pk2(a.z - hz, a.w - hw);
        *(uint2*)(smem + off)         = hu;
        *(uint2*)(smem + 32768 + off) = lu;
    }

    const int wm = w & 1;        // m0 = wm*32
    const int wn = w >> 1;       // n0 = wn*32

    const int NCH = NT * 8;

    // prefetch chunks 0,1
#pragma unroll
    for (int pf = 0; pf < 2; pf++) {
        const unsigned char* src = Wp + (size_t)pf * 16384;
        const uint32_t dst = sb + SMW_OFF + (uint32_t)pf * 16384u;
#pragma unroll
        for (int j = 0; j < 4; j++)
            CP16(dst + (uint32_t)(tid * 16 + j * 4096), src + tid * 16 + j * 4096);
        CP_COMMIT();
    }
    __syncthreads();   // A-tile also ready

    float acc[2][4][4];
    int nt = 0;
#pragma unroll
    for (int mf = 0; mf < 2; mf++)
#pragma unroll
        for (int nf = 0; nf < 4; nf++)
#pragma unroll
            for (int q = 0; q < 4; q++) acc[mf][nf][q] = 0.0f;

    for (int gc = 0; gc < NCH; gc++) {
        // prefetch gc+2
        if (gc + 2 < NCH) {
            const unsigned char* src = Wp + (size_t)(gc + 2) * 16384;
            const uint32_t dst = sb + SMW_OFF + (uint32_t)(((gc + 2) % 3) * 16384);
#pragma unroll
            for (int j = 0; j < 4; j++)
                CP16(dst + (uint32_t)(tid * 16 + j * 4096), src + tid * 16 + j * 4096);
        }
        CP_COMMIT();
        CP_WAIT(2);
        __syncthreads();

        const uint32_t st = sb + SMW_OFF + (uint32_t)((gc % 3) * 16384);
        const int kc = gc & 7;

#pragma unroll
        for (int ks = 0; ks < 2; ks++) {
            uint32_t ah[2][4], al[2][4];
            const int arow = wm * 32 + ((lane >> 3) & 1) * 8 + (lane & 7);
            const int kg   = kc * 32 + ks * 16 + ((lane >> 4) << 3);
#pragma unroll
            for (int mf = 0; mf < 2; mf++) {
                const uint32_t r = (uint32_t)(arow + mf * 16);
                const uint32_t addr = sb + r * 512u + swz((uint32_t)kg * 2u, r);
                LDSM_X4(ah[mf], addr);
                LDSM_X4(al[mf], addr + 32768u);
            }
            uint32_t bh[2][4], bl[2][4];
            const uint32_t krow = (uint32_t)(ks * 16 + ((lane >> 3) & 1) * 8 + (lane & 7));
#pragma unroll
            for (int nf2 = 0; nf2 < 2; nf2++) {
                const uint32_t ncol = (uint32_t)(wn * 32 + nf2 * 16 + (lane >> 4) * 8);
                const uint32_t addr = st + krow * 256u + swz(ncol * 2u, krow);
                LDSM_X4T(bh[nf2], addr);
                LDSM_X4T(bl[nf2], addr + 8192u);
            }
#pragma unroll
            for (int mf = 0; mf < 2; mf++)
#pragma unroll
                for (int nf = 0; nf < 4; nf++) {
                    uint32_t* bph = &bh[nf >> 1][(nf & 1) * 2];
                    uint32_t* bpl = &bl[nf >> 1][(nf & 1) * 2];
                    MMA16816(acc[mf][nf], ah[mf], bph);
                    MMA16816(acc[mf][nf], ah[mf], bpl);
                    MMA16816(acc[mf][nf], al[mf], bph);
                }
        }
        __syncthreads();

        if (kc == 7) {
            // epilogue for this N-tile
            const int g = lane >> 2, t = lane & 3;
#pragma unroll
            for (int nf = 0; nf < 4; nf++) {
                const int col = nt * 128 + wn * 32 + nf * 8 + t * 2;
                const float2 bv = *(const float2*)(bias + col);
#pragma unroll
                for (int mf = 0; mf < 2; mf++) {
                    const int row = row0 + wm * 32 + mf * 16 + g;
                    float2 v0 = make_float2(acc[mf][nf][0] + bv.x, acc[mf][nf][1] + bv.y);
                    float2 v1 = make_float2(acc[mf][nf][2] + bv.x, acc[mf][nf][3] + bv.y);
                    *(float2*)(C + (size_t)row * Ncols + col)       = v0;
                    *(float2*)(C + (size_t)(row + 8) * Ncols + col) = v1;
                }
            }
            nt++;
#pragma unroll
            for (int mf = 0; mf < 2; mf++)
#pragma unroll
                for (int nf = 0; nf < 4; nf++)
#pragma unroll
                    for (int q = 0; q < 4; q++) acc[mf][nf][q] = 0.0f;
        }
    }
}

// =====================================================================
// Kernel 3: tensor-core window attention, 512 threads (2 warps/head)
//   per-head smem (56 rows x 64B each): QH QL KH KL VH VL = 21504 B
// =====================================================================
#define AHEAD 21504
#define AQH 0
#define AQL 3584
#define AKH 7168
#define AKL 10752
#define AVH 14336
#define AVL 17920
#define ATTN_SMEM (8 * AHEAD + 512)

__global__ __launch_bounds__(512, 1)
void attn_tc(const float* __restrict__ qkv,
             const float* __restrict__ bias,
             const float* __restrict__ scale,
             float* __restrict__ attn_out)
{
    extern __shared__ char smem[];
    const uint32_t sb = s2u(smem);
    const int b    = blockIdx.x;
    const int tid  = threadIdx.x;
    const int lane = tid & 31;
    const int wrp  = tid >> 5;

    // zero V pad rows 49..55 (hi & lo, all heads) + 512B tail
    {
        int i = tid;
        if (i < 448) {
            const int head = i / 56, rem = i % 56;
            const int half = rem / 28, rr = 49 + (rem % 28) / 4, c16 = (rem & 3) * 16;
            *(uint4*)(smem + head * AHEAD + (half ? AVL : AVH) + rr * 64 + c16) =
                make_uint4(0, 0, 0, 0);
        } else if (i < 480) {
            *(uint4*)(smem + 8 * AHEAD + (i - 448) * 16) = make_uint4(0, 0, 0, 0);
        }
    }

    // cooperative load + normalize + hi/lo split
    {
        const float* wb = qkv + (size_t)b * NTOK * QKVCOL;
        const int team = tid >> 3, l8 = tid & 7;
        for (int it = team; it < 392; it += 64) {
            const int tok = it >> 3, hh = it & 7;
            const float* rowp = wb + (size_t)tok * QKVCOL + hh * HD + l8 * 4;
            float4 q = *(const float4*)(rowp);
            float4 k = *(const float4*)(rowp + 256);
            float4 v = *(const float4*)(rowp + 512);
            float qss = q.x*q.x + q.y*q.y + q.z*q.z + q.w*q.w;
            float kss = k.x*k.x + k.y*k.y + k.z*k.z + k.w*k.w;
#pragma unroll
            for (int o = 4; o > 0; o >>= 1) {
                qss += __shfl_xor_sync(0xffffffffu, qss, o);
                kss += __shfl_xor_sync(0xffffffffu, kss, o);
            }
            const float qr = rsqrtf(qss) * __ldg(scale + hh);
            const float kr = rsqrtf(kss);
            q.x *= qr; q.y *= qr; q.z *= qr; q.w *= qr;
            k.x *= kr; k.y *= kr; k.z *= kr; k.w *= kr;

            const uint32_t base = (uint32_t)hh * AHEAD + (uint32_t)tok * 64u
                                + swz64((uint32_t)l8 * 8u, (uint32_t)tok);
            {
                float hx = rbf(q.x), hy = rbf(q.y), hz = rbf(q.z), hw = rbf(q.w);
                uint2 hu; hu.x = pk2(hx, hy); hu.y = pk2(hz, hw);
                uint2 lu; lu.x = pk2(q.x - hx, q.y - hy); lu.y = pk2(q.z - hz, q.w - hw);
                *(uint2*)(smem + AQH + base) = hu;
                *(uint2*)(smem + AQL + base) = lu;
            }
            {
                float hx = rbf(k.x), hy = rbf(k.y), hz = rbf(k.z), hw = rbf(k.w);
                uint2 hu; hu.x = pk2(hx, hy); hu.y = pk2(hz, hw);
                uint2 lu; lu.x = pk2(k.x - hx, k.y - hy); lu.y = pk2(k.z - hz, k.w - hw);
                *(uint2*)(smem + AKH + base) = hu;
                *(uint2*)(smem + AKL + base) = lu;
            }
            {
                float hx = rbf(v.x), hy = rbf(v.y), hz = rbf(v.z), hw = rbf(v.w);
                uint2 hu; hu.x = pk2(hx, hy); hu.y = pk2(hz, hw);
                uint2 lu; lu.x = pk2(v.x - hx, v.y - hy); lu.y = pk2(v.z - hz, v.w - hw);
                *(uint2*)(smem + AVH + base) = hu;
                *(uint2*)(smem + AVL + base) = lu;
            }
        }
    }
    __syncthreads();

    // per-warp: head h, 32-row half; two 16-row chunks
    const int h  = wrp >> 1;
    const int m0base = (wrp & 1) * 32;
    const uint32_t hb = sb + (uint32_t)h * AHEAD;
    const float* bslab = bias + h * 3584;
    float* obase = attn_out + (size_t)b * NTOK * DIMF + h * HD;
    const int qrow = lane >> 2;
    const int qc   = (lane & 3) * 2;

#pragma unroll
    for (int mc = 0; mc < 2; mc++) {
        const int m0 = m0base + mc * 16;

        float S[7][4];
#pragma unroll
        for (int n = 0; n < 7; n++)
#pragma unroll
            for (int q = 0; q < 4; q++) S[n][q] = 0.0f;

        // ---- S = Qn Kn^T ----
#pragma unroll
        for (int ks = 0; ks < 2; ks++) {
            uint32_t ah[4], al[4];
            {
                const uint32_t r = (uint32_t)(m0 + ((lane >> 3) & 1) * 8 + (lane & 7));
                const uint32_t cb = (uint32_t)(ks * 32 + (lane >> 4) * 16);
                const uint32_t ad = hb + AQH + r * 64u + swz64(cb, r);
                LDSM_X4(ah, ad);
                LDSM_X4(al, ad + (AQL - AQH));
            }
#pragma unroll
            for (int ng = 0; ng < 4; ng++) {
                uint32_t bh[4], bl[4];
                const uint32_t r = (uint32_t)(ng * 16 + (lane & 7) + ((lane >> 4) << 3));
                const uint32_t cb = (uint32_t)(ks * 32 + ((lane >> 3) & 1) * 16);
                const uint32_t ad = hb + AKH + r * 64u + swz64(cb, r);
                LDSM_X4(bh, ad);
                LDSM_X4(bl, ad + (AKL - AKH));
                MMA16816(S[2 * ng], ah, bh);
                MMA16816(S[2 * ng], ah, bl);
                MMA16816(S[2 * ng], al, bh);
                if (ng < 3) {
                    MMA16816(S[2 * ng + 1], ah, bh + 2);
                    MMA16816(S[2 * ng + 1], ah, bl + 2);
                    MMA16816(S[2 * ng + 1], al, bh + 2);
                }
            }
        }

        // ---- softmax ----
        {
            const int r0 = m0 + qrow;
            float mx0 = -1e30f, mx1 = -1e30f;
#pragma unroll
            for (int nf = 0; nf < 7; nf++) {
                const int c0 = nf * 8 + qc;
                const float2 b0 = *(const float2*)(bslab + r0 * 56 + c0);
                const float2 b1 = *(const float2*)(bslab + (r0 + 8) * 56 + c0);
                S[nf][0] = (c0     < 49) ? S[nf][0] + b0.x : -1e30f;
                S[nf][1] = (c0 + 1 < 49) ? S[nf][1] + b0.y : -1e30f;
                S[nf][2] = (c0     < 49) ? S[nf][2] + b1.x : -1e30f;
                S[nf][3] = (c0 + 1 < 49) ? S[nf][3] + b1.y : -1e30f;
                mx0 = fmaxf(mx0, fmaxf(S[nf][0], S[nf][1]));
                mx1 = fmaxf(mx1, fmaxf(S[nf][2], S[nf][3]));
            }
#pragma unroll
            for (int o = 1; o < 4; o <<= 1) {
                mx0 = fmaxf(mx0, __shfl_xor_sync(0xffffffffu, mx0, o));
                mx1 = fmaxf(mx1, __shfl_xor_sync(0xffffffffu, mx1, o));
            }
            float rs0 = 0.0f, rs1 = 0.0f;
#pragma unroll
            for (int nf = 0; nf < 7; nf++) {
                float p0 = __expf(S[nf][0] - mx0);
                float p1 = __expf(S[nf][1] - mx0);
                float p2 = __expf(S[nf][2] - mx1);
                float p3 = __expf(S[nf][3] - mx1);
                S[nf][0] = p0; S[nf][1] = p1; S[nf][2] = p2; S[nf][3] = p3;
                rs0 += p0 + p1;  rs1 += p2 + p3;
            }
#pragma unroll
            for (int o = 1; o < 4; o <<= 1) {
                rs0 += __shfl_xor_sync(0xffffffffu, rs0, o);
                rs1 += __shfl_xor_sync(0xffffffffu, rs1, o);
            }
            const float iv0 = 1.0f / rs0, iv1 = 1.0f / rs1;
#pragma unroll
            for (int nf = 0; nf < 7; nf++) {
                S[nf][0] *= iv0; S[nf][1] *= iv0;
                S[nf][2] *= iv1; S[nf][3] *= iv1;
            }
        }

        // ---- O = P V ----
        float O[4][4];
#pragma unroll
        for (int n = 0; n < 4; n++)
#pragma unroll
            for (int q = 0; q < 4; q++) O[n][q] = 0.0f;

#pragma unroll
        for (int kt = 0; kt < 4; kt++) {
            uint32_t ph[4], pl[4];
            {
                float pa0 = S[2*kt][0], pa1 = S[2*kt][1], pa2 = S[2*kt][2], pa3 = S[2*kt][3];
                float pb0 = 0.f, pb1 = 0.f, pb2 = 0.f, pb3 = 0.f;
                if (kt < 3) {
                    pb0 = S[2*kt+1][0]; pb1 = S[2*kt+1][1];
                    pb2 = S[2*kt+1][2]; pb3 = S[2*kt+1][3];
                }
                const float ha0 = rbf(pa0), ha1 = rbf(pa1), ha2 = rbf(pa2), ha3 = rbf(pa3);
                const float hb0 = rbf(pb0), hb1 = rbf(pb1), hb2 = rbf(pb2), hb3 = rbf(pb3);
                ph[0] = pk2(ha0, ha1);  ph[1] = pk2(ha2, ha3);
                ph[2] = pk2(hb0, hb1);  ph[3] = pk2(hb2, hb3);
                pl[0] = pk2(pa0 - ha0, pa1 - ha1);
                pl[1] = pk2(pa2 - ha2, pa3 - ha3);
                pl[2] = pk2(pb0 - hb0, pb1 - hb1);
                pl[3] = pk2(pb2 - hb2, pb3 - hb3);
            }
#pragma unroll
            for (int vg = 0; vg < 2; vg++) {
                uint32_t vh[4], vl[4];
                const uint32_t kr = (uint32_t)(kt * 16 + ((lane >> 3) & 1) * 8 + (lane & 7));
                const uint32_t cb = (uint32_t)(vg * 32 + (lane >> 4) * 16);
                const uint32_t ad = hb + AVH + kr * 64u + swz64(cb, kr);
                LDSM_X4T(vh, ad);
                LDSM_X4T(vl, ad + (AVL - AVH));
#pragma unroll
                for (int nn = 0; nn < 2; nn++) {
                    float* oo = O[vg * 2 + nn];
                    MMA16816(oo, ph, vh + nn * 2);
                    MMA16816(oo, ph, vl + nn * 2);
                    MMA16816(oo, pl, vh + nn * 2);
                }
            }
        }

        // ---- store rows < 49 ----
        {
            const int r0 = m0 + qrow;
#pragma unroll
            for (int nf = 0; nf < 4; nf++) {
                const int c = nf * 8 + qc;
                if (r0 < NTOK)
                    *(float2*)(obase + (size_t)r0 * DIMF + c) = make_float2(O[nf][0], O[nf][1]);
                if (r0 + 8 < NTOK)
                    *(float2*)(obase + (size_t)(r0 + 8) * DIMF + c) = make_float2(O[nf][2], O[nf][3]);
            }
        }
    }
}

// =====================================================================
// launch
// =====================================================================
extern "C" void kernel_launch(void* const* d_in, const int* in_sizes, int n_in,
                              void* d_out, int out_size)
{
    const float* x           = (const float*)d_in[0];
    const float* qkv_w       = (const float*)d_in[1];
    const float* qkv_b       = (const float*)d_in[2];
    const float* proj_w      = (const float*)d_in[3];
    const float* proj_b      = (const float*)d_in[4];
    const float* logit_scale = (const float*)d_in[5];
    const float* cpb_w1      = (const float*)d_in[6];
    const float* cpb_b1      = (const float*)d_in[7];
    const float* cpb_w2      = (const float*)d_in[8];
    float* out = (float*)d_out;

    float *qkvbuf, *attnbuf, *biasbuf, *scalebuf;
    unsigned char *wqbuf, *wpbuf;
    cudaGetSymbolAddress((void**)&qkvbuf,   g_qkv);
    cudaGetSymbolAddress((void**)&attnbuf,  g_attn);
    cudaGetSymbolAddress((void**)&biasbuf,  g_bias);
    cudaGetSymbolAddress((void**)&scalebuf, g_scale);
    cudaGetSymbolAddress((void**)&wqbuf,    g_wq);
    cudaGetSymbolAddress((void**)&wpbuf,    g_wp);

    cudaFuncSetAttribute(gemm_mma, cudaFuncAttributeMaxDynamicSharedMemorySize, GEMM_SMEM);
    cudaFuncSetAttribute(attn_tc,  cudaFuncAttributeMaxDynamicSharedMemorySize, ATTN_SMEM);

    cpb_kernel<<<1, 256>>>(logit_scale, cpb_w1, cpb_b1, cpb_w2, biasbuf, scalebuf);
    wsplit_kernel<<<128, 256>>>(qkv_w, proj_w, wqbuf, wpbuf);

    gemm_mma<<<MROWS / 64, 256, GEMM_SMEM>>>(x, wqbuf, qkv_b, qkvbuf, 6);

    attn_tc<<<B_WIN, 512, ATTN_SMEM>>>(qkvbuf, biasbuf, scalebuf, attnbuf);

    gemm_mma<<<MROWS / 64, 256, GEMM_SMEM>>>(attnbuf, wpbuf, proj_b, out, 2);
}

// round 6
// speedup vs baseline: 1.9573x; 1.0287x over previous
#include <cuda_runtime.h>
#include <cuda_bf16.h>
#include <cuda_fp16.h>
#include <cstdint>

// ---------------- problem constants ----------------
#define B_WIN  2048
#define NTOK   49
#define DIMF   256
#define HEADS  8
#define HD     32
#define MROWS  (B_WIN * NTOK)        // 100352
#define QKVCOL 768

#define LOSC   2048.0f               // lo-term pre-scale (keeps fp16 normal)
#define LOINV  4.8828125e-4f         // 1/2048

// ---------------- scratch ----------------
__device__ float g_qkv [MROWS * QKVCOL];
__device__ float g_attn[MROWS * DIMF];
__device__ float g_bias[HEADS * 64 * 56];   // padded [8][64][56]; pads stay 0
__device__ float g_scale[HEADS];
__device__ unsigned char g_wq[48 * 16384];  // fp16 hi/lo chunks
__device__ unsigned char g_wp[16 * 16384];

// ---------------- helpers ----------------
static __device__ __forceinline__ uint32_t s2u(const void* p) {
    uint32_t a;
    asm("{ .reg .u64 t; cvta.to.shared.u64 t, %1; cvt.u32.u64 %0, t; }" : "=r"(a) : "l"(p));
    return a;
}
static __device__ __forceinline__ uint32_t swz(uint32_t byte_in_row, uint32_t row) {
    return (byte_in_row & ~0x7Fu) | ((byte_in_row & 0x7Fu) ^ ((row & 7u) << 4));
}
static __device__ __forceinline__ uint32_t swz64(uint32_t c, uint32_t row) {
    return (c & 0xFu) | (((((c >> 4) ^ ((row >> 1) & 3u))) & 3u) << 4);
}

#define LDSM_X4(r, a)                                                        \
    asm volatile("ldmatrix.sync.aligned.m8n8.x4.shared.b16 {%0,%1,%2,%3}, [%4];" \
        : "=r"((r)[0]), "=r"((r)[1]), "=r"((r)[2]), "=r"((r)[3]) : "r"(a))
#define LDSM_X4T(r, a)                                                       \
    asm volatile("ldmatrix.sync.aligned.m8n8.x4.trans.shared.b16 {%0,%1,%2,%3}, [%4];" \
        : "=r"((r)[0]), "=r"((r)[1]), "=r"((r)[2]), "=r"((r)[3]) : "r"(a))

// bf16 in, f32 accum (attention)
#define MMA_BF(c, a, b)                                                      \
    asm volatile("mma.sync.aligned.m16n8k16.row.col.f32.bf16.bf16.f32 "      \
        "{%0,%1,%2,%3}, {%4,%5,%6,%7}, {%8,%9}, {%0,%1,%2,%3};"              \
        : "+f"((c)[0]), "+f"((c)[1]), "+f"((c)[2]), "+f"((c)[3])             \
        : "r"((a)[0]), "r"((a)[1]), "r"((a)[2]), "r"((a)[3]),                \
          "r"((b)[0]), "r"((b)[1]))
// fp16 in, f32 accum (GEMM hi*hi)
#define MMA_FH(c, a, b)                                                      \
    asm volatile("mma.sync.aligned.m16n8k16.row.col.f32.f16.f16.f32 "        \
        "{%0,%1,%2,%3}, {%4,%5,%6,%7}, {%8,%9}, {%0,%1,%2,%3};"              \
        : "+f"((c)[0]), "+f"((c)[1]), "+f"((c)[2]), "+f"((c)[3])             \
        : "r"((a)[0]), "r"((a)[1]), "r"((a)[2]), "r"((a)[3]),                \
          "r"((b)[0]), "r"((b)[1]))
// fp16 in, f16 accum (GEMM cross terms)
#define MMA_HH(c2, a, b)                                                     \
    asm volatile("mma.sync.aligned.m16n8k16.row.col.f16.f16.f16.f16 "        \
        "{%0,%1}, {%2,%3,%4,%5}, {%6,%7}, {%0,%1};"                          \
        : "+r"((c2)[0]), "+r"((c2)[1])                                       \
        : "r"((a)[0]), "r"((a)[1]), "r"((a)[2]), "r"((a)[3]),                \
          "r"((b)[0]), "r"((b)[1]))

#define CP16(d, s) \
    asm volatile("cp.async.cg.shared.global [%0], [%1], 16;" :: "r"(d), "l"(s) : "memory")
#define CP_COMMIT() asm volatile("cp.async.commit_group;" ::: "memory")
#define CP_WAIT(n)  asm volatile("cp.async.wait_group %0;" :: "n"(n) : "memory")

static __device__ __forceinline__ uint32_t pk2(float x, float y) {   // bf16x2
    uint32_t r;
    asm("cvt.rn.bf16x2.f32 %0, %1, %2;" : "=r"(r) : "f"(y), "f"(x));
    return r;
}
static __device__ __forceinline__ uint32_t pk2h(float x, float y) {  // f16x2
    uint32_t r;
    asm("cvt.rn.f16x2.f32 %0, %1, %2;" : "=r"(r) : "f"(y), "f"(x));
    return r;
}
static __device__ __forceinline__ float rbf(float x) {
    return __bfloat162float(__float2bfloat16_rn(x));
}
static __device__ __forceinline__ float rhf(float x) {
    return __half2float(__float2half_rn(x));
}

// =====================================================================
// Kernel 1: CPB-MLP bias table + logit scale
// =====================================================================
__device__ __forceinline__ float cpb_coord(int i) {
    float x = (float)(i - 6) * (8.0f / 6.0f);
    return copysignf(log1pf(fabsf(x)) * 0.4808983469629878f, x);
}

__global__ void cpb_kernel(const float* __restrict__ logit_scale,
                           const float* __restrict__ w1,
                           const float* __restrict__ b1,
                           const float* __restrict__ w2,
                           float* __restrict__ bias_out,
                           float* __restrict__ scale_out)
{
    __shared__ float table[169][HEADS];
    const int tid = threadIdx.x;

    if (tid < HEADS) {
        float ls = logit_scale[tid];
        ls = fminf(ls, logf(100.0f));
        ls = fmaxf(ls, -100.0f);
        scale_out[tid] = expf(ls);
    }
    for (int e = tid; e < 169; e += blockDim.x) {
        const int i = e / 13, j = e % 13;
        const float c0 = cpb_coord(i);
        const float c1 = cpb_coord(j);
        float acc[HEADS];
#pragma unroll
        for (int hh = 0; hh < HEADS; hh++) acc[hh] = 0.0f;
        for (int kk = 0; kk < 512; kk++) {
            float hpre = c0 * w1[kk] + c1 * w1[512 + kk] + b1[kk];
            float g = 0.5f * hpre * (1.0f + erff(hpre * 0.7071067811865475f));
#pragma unroll
            for (int hh = 0; hh < HEADS; hh++) acc[hh] += g * w2[kk * 8 + hh];
        }
#pragma unroll
        for (int hh = 0; hh < HEADS; hh++) table[e][hh] = acc[hh];
    }
    __syncthreads();

    for (int idx = tid; idx < HEADS * NTOK * NTOK; idx += blockDim.x) {
        const int hh  = idx / (NTOK * NTOK);
        const int rem = idx % (NTOK * NTOK);
        const int r   = rem / NTOK;
        const int c   = rem % NTOK;
        const int dh  = (r / 7) - (c / 7) + 6;
        const int dw  = (r % 7) - (c % 7) + 6;
        const float v = table[dh * 13 + dw][hh];
        bias_out[hh * 3584 + r * 56 + c] = 16.0f / (1.0f + __expf(-v));
    }
}

// =====================================================================
// Kernel 1b: split weights fp32 -> hi/lo fp16 chunks (lo pre-scaled x2048)
// =====================================================================
__global__ void wsplit_kernel(const float* __restrict__ wq, const float* __restrict__ wp,
                              unsigned char* __restrict__ oq, unsigned char* __restrict__ op)
{
    const int stride = gridDim.x * blockDim.x;
    const int t0 = blockIdx.x * blockDim.x + threadIdx.x;
    for (int idx = t0; idx < 256 * QKVCOL; idx += stride) {
        const int k = idx / QKVCOL, n = idx % QKVCOL;
        float f = wq[idx];
        __half h = __float2half_rn(f);
        __half l = __float2half_rn((f - __half2float(h)) * LOSC);
        const uint32_t off = (uint32_t)((n >> 7) * 8 + (k >> 5)) * 16384u
                           + (uint32_t)(k & 31) * 256u + swz((uint32_t)(n & 127) * 2u, (uint32_t)k);
        *(__half*)(oq + off)        = h;
        *(__half*)(oq + off + 8192) = l;
    }
    for (int idx = t0; idx < 256 * 256; idx += stride) {
        const int k = idx >> 8, n = idx & 255;
        float f = wp[idx];
        __half h = __float2half_rn(f);
        __half l = __float2half_rn((f - __half2float(h)) * LOSC);
        const uint32_t off = (uint32_t)((n >> 7) * 8 + (k >> 5)) * 16384u
                           + (uint32_t)(k & 31) * 256u + swz((uint32_t)(n & 127) * 2u, (uint32_t)k);
        *(__half*)(op + off)        = h;
        *(__half*)(op + off + 8192) = l;
    }
}

// =====================================================================
// Kernel 2/4: fp16-split GEMM. hi*hi in f32-accum MMA; (hi*lo + lo*hi)
//   (lo pre-scaled x2048) in f16-accum MMA, rescaled at epilogue.
// =====================================================================
#define SMW_OFF 65536
#define GEMM_SMEM (65536 + 3 * 16384)

__global__ __launch_bounds__(256, 2)
void gemm_mma(const float* __restrict__ A, const unsigned char* __restrict__ Wp,
              const float* __restrict__ bias, float* __restrict__ C, int NT)
{
    extern __shared__ char smem[];
    const uint32_t sb = s2u(smem);
    const int tid  = threadIdx.x;
    const int lane = tid & 31;
    const int w    = tid >> 5;
    const int row0 = blockIdx.x * 64;
    const int Ncols = NT * 128;

    // A: fp32 -> hi/lo fp16 (lo x2048), 64 rows x 512B, swizzled
    for (int i = tid; i < 4096; i += 256) {
        const int r  = i >> 6;
        const int c4 = (i & 63) << 2;
        float4 a = *(const float4*)(A + (size_t)(row0 + r) * 256 + c4);
        float hx = rhf(a.x), hy = rhf(a.y), hz = rhf(a.z), hw = rhf(a.w);
        const uint32_t off = (uint32_t)r * 512u + swz((uint32_t)c4 * 2u, (uint32_t)r);
        uint2 hu; hu.x = pk2h(hx, hy); hu.y = pk2h(hz, hw);
        uint2 lu;
        lu.x = pk2h((a.x - hx) * LOSC, (a.y - hy) * LOSC);
        lu.y = pk2h((a.z - hz) * LOSC, (a.w - hw) * LOSC);
        *(uint2*)(smem + off)         = hu;
        *(uint2*)(smem + 32768 + off) = lu;
    }

    const int wm = w & 1;        // m0 = wm*32
    const int wn = w >> 1;       // n0 = wn*32

    const int NCH = NT * 8;

#pragma unroll
    for (int pf = 0; pf < 2; pf++) {
        const unsigned char* src = Wp + (size_t)pf * 16384;
        const uint32_t dst = sb + SMW_OFF + (uint32_t)pf * 16384u;
#pragma unroll
        for (int j = 0; j < 4; j++)
            CP16(dst + (uint32_t)(tid * 16 + j * 4096), src + tid * 16 + j * 4096);
        CP_COMMIT();
    }
    __syncthreads();

    float    acc [2][4][4];
    uint32_t acch[2][4][2];
    int nt = 0;
#pragma unroll
    for (int mf = 0; mf < 2; mf++)
#pragma unroll
        for (int nf = 0; nf < 4; nf++) {
#pragma unroll
            for (int q = 0; q < 4; q++) acc[mf][nf][q] = 0.0f;
            acch[mf][nf][0] = 0u; acch[mf][nf][1] = 0u;
        }

    for (int gc = 0; gc < NCH; gc++) {
        if (gc + 2 < NCH) {
            const unsigned char* src = Wp + (size_t)(gc + 2) * 16384;
            const uint32_t dst = sb + SMW_OFF + (uint32_t)(((gc + 2) % 3) * 16384);
#pragma unroll
            for (int j = 0; j < 4; j++)
                CP16(dst + (uint32_t)(tid * 16 + j * 4096), src + tid * 16 + j * 4096);
        }
        CP_COMMIT();
        CP_WAIT(2);
        __syncthreads();

        const uint32_t st = sb + SMW_OFF + (uint32_t)((gc % 3) * 16384);
        const int kc = gc & 7;

#pragma unroll
        for (int ks = 0; ks < 2; ks++) {
            uint32_t ah[2][4], al[2][4];
            const int arow = wm * 32 + ((lane >> 3) & 1) * 8 + (lane & 7);
            const int kg   = kc * 32 + ks * 16 + ((lane >> 4) << 3);
#pragma unroll
            for (int mf = 0; mf < 2; mf++) {
                const uint32_t r = (uint32_t)(arow + mf * 16);
                const uint32_t addr = sb + r * 512u + swz((uint32_t)kg * 2u, r);
                LDSM_X4(ah[mf], addr);
                LDSM_X4(al[mf], addr + 32768u);
            }
            uint32_t bh[2][4], bl[2][4];
            const uint32_t krow = (uint32_t)(ks * 16 + ((lane >> 3) & 1) * 8 + (lane & 7));
#pragma unroll
            for (int nf2 = 0; nf2 < 2; nf2++) {
                const uint32_t ncol = (uint32_t)(wn * 32 + nf2 * 16 + (lane >> 4) * 8);
                const uint32_t addr = st + krow * 256u + swz(ncol * 2u, krow);
                LDSM_X4T(bh[nf2], addr);
                LDSM_X4T(bl[nf2], addr + 8192u);
            }
#pragma unroll
            for (int mf = 0; mf < 2; mf++)
#pragma unroll
                for (int nf = 0; nf < 4; nf++) {
                    uint32_t* bph = &bh[nf >> 1][(nf & 1) * 2];
                    uint32_t* bpl = &bl[nf >> 1][(nf & 1) * 2];
                    MMA_FH(acc[mf][nf], ah[mf], bph);     // hi*hi  (f32 accum)
                    MMA_HH(acch[mf][nf], ah[mf], bpl);    // hi*lo' (f16 accum)
                    MMA_HH(acch[mf][nf], al[mf], bph);    // lo'*hi (f16 accum)
                }
        }
        __syncthreads();

        if (kc == 7) {
            const int g = lane >> 2, t = lane & 3;
#pragma unroll
            for (int nf = 0; nf < 4; nf++) {
                const int col = nt * 128 + wn * 32 + nf * 8 + t * 2;
                const float2 bv = *(const float2*)(bias + col);
#pragma unroll
                for (int mf = 0; mf < 2; mf++) {
                    const int row = row0 + wm * 32 + mf * 16 + g;
                    float2 c01 = __half22float2(*(const __half2*)&acch[mf][nf][0]);
                    float2 c23 = __half22float2(*(const __half2*)&acch[mf][nf][1]);
                    float2 v0 = make_float2(acc[mf][nf][0] + c01.x * LOINV + bv.x,
                                            acc[mf][nf][1] + c01.y * LOINV + bv.y);
                    float2 v1 = make_float2(acc[mf][nf][2] + c23.x * LOINV + bv.x,
                                            acc[mf][nf][3] + c23.y * LOINV + bv.y);
                    *(float2*)(C + (size_t)row * Ncols + col)       = v0;
                    *(float2*)(C + (size_t)(row + 8) * Ncols + col) = v1;
                }
            }
            nt++;
#pragma unroll
            for (int mf = 0; mf < 2; mf++)
#pragma unroll
                for (int nf = 0; nf < 4; nf++) {
#pragma unroll
                    for (int q = 0; q < 4; q++) acc[mf][nf][q] = 0.0f;
                    acch[mf][nf][0] = 0u; acch[mf][nf][1] = 0u;
                }
        }
    }
}

// =====================================================================
// Kernel 3: tensor-core window attention — 4 heads/CTA, grid (2048, 2),
//   256 threads (2 warps/head), smem ~84.5 KB -> 2 CTAs/SM.
// =====================================================================
#define AHEAD 21504
#define AQH 0
#define AQL 3584
#define AKH 7168
#define AKL 10752
#define AVH 14336
#define AVL 17920
#define ATTN_SMEM (4 * AHEAD + 512)

__global__ __launch_bounds__(256, 2)
void attn_tc(const float* __restrict__ qkv,
             const float* __restrict__ bias,
             const float* __restrict__ scale,
             float* __restrict__ attn_out)
{
    extern __shared__ char smem[];
    const uint32_t sb = s2u(smem);
    const int b    = blockIdx.x;
    const int hg   = blockIdx.y;          // head group: heads hg*4 .. hg*4+3
    const int tid  = threadIdx.x;
    const int lane = tid & 31;
    const int wrp  = tid >> 5;

    // zero V pad rows 49..55 (hi & lo, 4 head slots) + 512B tail
    {
        int i = tid;
        if (i < 224) {
            const int slot = i / 56, rem = i % 56;
            const int half = rem / 28, rr = 49 + (rem % 28) / 4, c16 = (rem & 3) * 16;
            *(uint4*)(smem + slot * AHEAD + (half ? AVL : AVH) + rr * 64 + c16) =
                make_uint4(0, 0, 0, 0);
        } else if (i < 256) {
            *(uint4*)(smem + 4 * AHEAD + (i - 224) * 16) = make_uint4(0, 0, 0, 0);
        }
    }

    // cooperative load + normalize + hi/lo bf16 split (4 heads)
    {
        const float* wb = qkv + (size_t)b * NTOK * QKVCOL;
        const int team = tid >> 3, l8 = tid & 7;
        for (int it = team; it < 196; it += 32) {
            const int tok = it >> 2, slot = it & 3;
            const int hh  = hg * 4 + slot;
            const float* rowp = wb + (size_t)tok * QKVCOL + hh * HD + l8 * 4;
            float4 q = *(const float4*)(rowp);
            float4 k = *(const float4*)(rowp + 256);
            float4 v = *(const float4*)(rowp + 512);
            float qss = q.x*q.x + q.y*q.y + q.z*q.z + q.w*q.w;
            float kss = k.x*k.x + k.y*k.y + k.z*k.z + k.w*k.w;
#pragma unroll
            for (int o = 4; o > 0; o >>= 1) {
                qss += __shfl_xor_sync(0xffffffffu, qss, o);
                kss += __shfl_xor_sync(0xffffffffu, kss, o);
            }
            const float qr = rsqrtf(qss) * __ldg(scale + hh);
            const float kr = rsqrtf(kss);
            q.x *= qr; q.y *= qr; q.z *= qr; q.w *= qr;
            k.x *= kr; k.y *= kr; k.z *= kr; k.w *= kr;

            const uint32_t base = (uint32_t)slot * AHEAD + (uint32_t)tok * 64u
                                + swz64((uint32_t)l8 * 8u, (uint32_t)tok);
            {
                float hx = rbf(q.x), hy = rbf(q.y), hz = rbf(q.z), hw = rbf(q.w);
                uint2 hu; hu.x = pk2(hx, hy); hu.y = pk2(hz, hw);
                uint2 lu; lu.x = pk2(q.x - hx, q.y - hy); lu.y = pk2(q.z - hz, q.w - hw);
                *(uint2*)(smem + AQH + base) = hu;
                *(uint2*)(smem + AQL + base) = lu;
            }
            {
                float hx = rbf(k.x), hy = rbf(k.y), hz = rbf(k.z), hw = rbf(k.w);
                uint2 hu; hu.x = pk2(hx, hy); hu.y = pk2(hz, hw);
                uint2 lu; lu.x = pk2(k.x - hx, k.y - hy); lu.y = pk2(k.z - hz, k.w - hw);
                *(uint2*)(smem + AKH + base) = hu;
                *(uint2*)(smem + AKL + base) = lu;
            }
            {
                float hx = rbf(v.x), hy = rbf(v.y), hz = rbf(v.z), hw = rbf(v.w);
                uint2 hu; hu.x = pk2(hx, hy); hu.y = pk2(hz, hw);
                uint2 lu; lu.x = pk2(v.x - hx, v.y - hy); lu.y = pk2(v.z - hz, v.w - hw);
                *(uint2*)(smem + AVH + base) = hu;
                *(uint2*)(smem + AVL + base) = lu;
            }
        }
    }
    __syncthreads();

    const int slot = wrp >> 1;
    const int h    = hg * 4 + slot;
    const int m0base = (wrp & 1) * 32;
    const uint32_t hb = sb + (uint32_t)slot * AHEAD;
    const float* bslab = bias + h * 3584;
    float* obase = attn_out + (size_t)b * NTOK * DIMF + h * HD;
    const int qrow = lane >> 2;
    const int qc   = (lane & 3) * 2;

#pragma unroll
    for (int mc = 0; mc < 2; mc++) {
        const int m0 = m0base + mc * 16;

        float S[7][4];
#pragma unroll
        for (int n = 0; n < 7; n++)
#pragma unroll
            for (int q = 0; q < 4; q++) S[n][q] = 0.0f;

#pragma unroll
        for (int ks = 0; ks < 2; ks++) {
            uint32_t ah[4], al[4];
            {
                const uint32_t r = (uint32_t)(m0 + ((lane >> 3) & 1) * 8 + (lane & 7));
                const uint32_t cb = (uint32_t)(ks * 32 + (lane >> 4) * 16);
                const uint32_t ad = hb + AQH + r * 64u + swz64(cb, r);
                LDSM_X4(ah, ad);
                LDSM_X4(al, ad + (AQL - AQH));
            }
#pragma unroll
            for (int ng = 0; ng < 4; ng++) {
                uint32_t bh[4], bl[4];
                const uint32_t r = (uint32_t)(ng * 16 + (lane & 7) + ((lane >> 4) << 3));
                const uint32_t cb = (uint32_t)(ks * 32 + ((lane >> 3) & 1) * 16);
                const uint32_t ad = hb + AKH + r * 64u + swz64(cb, r);
                LDSM_X4(bh, ad);
                LDSM_X4(bl, ad + (AKL - AKH));
                MMA_BF(S[2 * ng], ah, bh);
                MMA_BF(S[2 * ng], ah, bl);
                MMA_BF(S[2 * ng], al, bh);
                if (ng < 3) {
                    MMA_BF(S[2 * ng + 1], ah, bh + 2);
                    MMA_BF(S[2 * ng + 1], ah, bl + 2);
                    MMA_BF(S[2 * ng + 1], al, bh + 2);
                }
            }
        }

        // softmax
        {
            const int r0 = m0 + qrow;
            float mx0 = -1e30f, mx1 = -1e30f;
#pragma unroll
            for (int nf = 0; nf < 7; nf++) {
                const int c0 = nf * 8 + qc;
                const float2 b0 = *(const float2*)(bslab + r0 * 56 + c0);
                const float2 b1 = *(const float2*)(bslab + (r0 + 8) * 56 + c0);
                S[nf][0] = (c0     < 49) ? S[nf][0] + b0.x : -1e30f;
                S[nf][1] = (c0 + 1 < 49) ? S[nf][1] + b0.y : -1e30f;
                S[nf][2] = (c0     < 49) ? S[nf][2] + b1.x : -1e30f;
                S[nf][3] = (c0 + 1 < 49) ? S[nf][3] + b1.y : -1e30f;
                mx0 = fmaxf(mx0, fmaxf(S[nf][0], S[nf][1]));
                mx1 = fmaxf(mx1, fmaxf(S[nf][2], S[nf][3]));
            }
#pragma unroll
            for (int o = 1; o < 4; o <<= 1) {
                mx0 = fmaxf(mx0, __shfl_xor_sync(0xffffffffu, mx0, o));
                mx1 = fmaxf(mx1, __shfl_xor_sync(0xffffffffu, mx1, o));
            }
            float rs0 = 0.0f, rs1 = 0.0f;
#pragma unroll
            for (int nf = 0; nf < 7; nf++) {
                float p0 = __expf(S[nf][0] - mx0);
                float p1 = __expf(S[nf][1] - mx0);
                float p2 = __expf(S[nf][2] - mx1);
                float p3 = __expf(S[nf][3] - mx1);
                S[nf][0] = p0; S[nf][1] = p1; S[nf][2] = p2; S[nf][3] = p3;
                rs0 += p0 + p1;  rs1 += p2 + p3;
            }
#pragma unroll
            for (int o = 1; o < 4; o <<= 1) {
                rs0 += __shfl_xor_sync(0xffffffffu, rs0, o);
                rs1 += __shfl_xor_sync(0xffffffffu, rs1, o);
            }
            const float iv0 = 1.0f / rs0, iv1 = 1.0f / rs1;
#pragma unroll
            for (int nf = 0; nf < 7; nf++) {
                S[nf][0] *= iv0; S[nf][1] *= iv0;
                S[nf][2] *= iv1; S[nf][3] *= iv1;
            }
        }

        // O = P V
        float O[4][4];
#pragma unroll
        for (int n = 0; n < 4; n++)
#pragma unroll
            for (int q = 0; q < 4; q++) O[n][q] = 0.0f;

#pragma unroll
        for (int kt = 0; kt < 4; kt++) {
            uint32_t ph[4], pl[4];
            {
                float pa0 = S[2*kt][0], pa1 = S[2*kt][1], pa2 = S[2*kt][2], pa3 = S[2*kt][3];
                float pb0 = 0.f, pb1 = 0.f, pb2 = 0.f, pb3 = 0.f;
                if (kt < 3) {
                    pb0 = S[2*kt+1][0]; pb1 = S[2*kt+1][1];
                    pb2 = S[2*kt+1][2]; pb3 = S[2*kt+1][3];
                }
                const float ha0 = rbf(pa0), ha1 = rbf(pa1), ha2 = rbf(pa2), ha3 = rbf(pa3);
                const float hb0 = rbf(pb0), hb1 = rbf(pb1), hb2 = rbf(pb2), hb3 = rbf(pb3);
                ph[0] = pk2(ha0, ha1);  ph[1] = pk2(ha2, ha3);
                ph[2] = pk2(hb0, hb1);  ph[3] = pk2(hb2, hb3);
                pl[0] = pk2(pa0 - ha0, pa1 - ha1);
                pl[1] = pk2(pa2 - ha2, pa3 - ha3);
                pl[2] = pk2(pb0 - hb0, pb1 - hb1);
                pl[3] = pk2(pb2 - hb2, pb3 - hb3);
            }
#pragma unroll
            for (int vg = 0; vg < 2; vg++) {
                uint32_t vh[4], vl[4];
                const uint32_t kr = (uint32_t)(kt * 16 + ((lane >> 3) & 1) * 8 + (lane & 7));
                const uint32_t cb = (uint32_t)(vg * 32 + (lane >> 4) * 16);
                const uint32_t ad = hb + AVH + kr * 64u + swz64(cb, kr);
                LDSM_X4T(vh, ad);
                LDSM_X4T(vl, ad + (AVL - AVH));
#pragma unroll
                for (int nn = 0; nn < 2; nn++) {
                    float* oo = O[vg * 2 + nn];
                    MMA_BF(oo, ph, vh + nn * 2);
                    MMA_BF(oo, ph, vl + nn * 2);
                    MMA_BF(oo, pl, vh + nn * 2);
                }
            }
        }

        // store rows < 49
        {
            const int r0 = m0 + qrow;
#pragma unroll
            for (int nf = 0; nf < 4; nf++) {
                const int c = nf * 8 + qc;
                if (r0 < NTOK)
                    *(float2*)(obase + (size_t)r0 * DIMF + c) = make_float2(O[nf][0], O[nf][1]);
                if (r0 + 8 < NTOK)
                    *(float2*)(obase + (size_t)(r0 + 8) * DIMF + c) = make_float2(O[nf][2], O[nf][3]);
            }
        }
    }
}

// =====================================================================
// launch
// =====================================================================
extern "C" void kernel_launch(void* const* d_in, const int* in_sizes, int n_in,
                              void* d_out, int out_size)
{
    const float* x           = (const float*)d_in[0];
    const float* qkv_w       = (const float*)d_in[1];
    const float* qkv_b       = (const float*)d_in[2];
    const float* proj_w      = (const float*)d_in[3];
    const float* proj_b      = (const float*)d_in[4];
    const float* logit_scale = (const float*)d_in[5];
    const float* cpb_w1      = (const float*)d_in[6];
    const float* cpb_b1      = (const float*)d_in[7];
    const float* cpb_w2      = (const float*)d_in[8];
    float* out = (float*)d_out;

    float *qkvbuf, *attnbuf, *biasbuf, *scalebuf;
    unsigned char *wqbuf, *wpbuf;
    cudaGetSymbolAddress((void**)&qkvbuf,   g_qkv);
    cudaGetSymbolAddress((void**)&attnbuf,  g_attn);
    cudaGetSymbolAddress((void**)&biasbuf,  g_bias);
    cudaGetSymbolAddress((void**)&scalebuf, g_scale);
    cudaGetSymbolAddress((void**)&wqbuf,    g_wq);
    cudaGetSymbolAddress((void**)&wpbuf,    g_wp);

    cudaFuncSetAttribute(gemm_mma, cudaFuncAttributeMaxDynamicSharedMemorySize, GEMM_SMEM);
    cudaFuncSetAttribute(attn_tc,  cudaFuncAttributeMaxDynamicSharedMemorySize, ATTN_SMEM);

    cpb_kernel<<<1, 256>>>(logit_scale, cpb_w1, cpb_b1, cpb_w2, biasbuf, scalebuf);
    wsplit_kernel<<<128, 256>>>(qkv_w, proj_w, wqbuf, wpbuf);

    gemm_mma<<<MROWS / 64, 256, GEMM_SMEM>>>(x, wqbuf, qkv_b, qkvbuf, 6);

    attn_tc<<<dim3(B_WIN, 2), 256, ATTN_SMEM>>>(qkvbuf, biasbuf, scalebuf, attnbuf);

    gemm_mma<<<MROWS / 64, 256, GEMM_SMEM>>>(attnbuf, wpbuf, proj_b, out, 2);
}

// round 7
// speedup vs baseline: 2.1909x; 1.1194x over previous
#include <cuda_runtime.h>
#include <cuda_bf16.h>
#include <cuda_fp16.h>
#include <cstdint>

// ---------------- problem constants ----------------
#define B_WIN  2048
#define NTOK   49
#define DIMF   256
#define HEADS  8
#define HD     32
#define MROWS  (B_WIN * NTOK)        // 100352
#define QKVCOL 768

#define LOSC   2048.0f               // lo-term pre-scale (keeps fp16 normal)
#define LOINV  4.8828125e-4f         // 1/2048

// ---------------- scratch ----------------
__device__ float g_qkv [MROWS * QKVCOL];
__device__ float g_attn[MROWS * DIMF];
__device__ float g_bias[HEADS * 64 * 56];   // padded [8][64][56]; pads stay 0
__device__ float g_scale[HEADS];
__device__ unsigned char g_wq[48 * 16384];  // fp16 hi/lo chunks
__device__ unsigned char g_wp[16 * 16384];

// ---------------- helpers ----------------
static __device__ __forceinline__ uint32_t s2u(const void* p) {
    uint32_t a;
    asm("{ .reg .u64 t; cvta.to.shared.u64 t, %1; cvt.u32.u64 %0, t; }" : "=r"(a) : "l"(p));
    return a;
}
static __device__ __forceinline__ uint32_t swz(uint32_t byte_in_row, uint32_t row) {
    return (byte_in_row & ~0x7Fu) | ((byte_in_row & 0x7Fu) ^ ((row & 7u) << 4));
}
static __device__ __forceinline__ uint32_t swz64(uint32_t c, uint32_t row) {
    return (c & 0xFu) | (((((c >> 4) ^ ((row >> 1) & 3u))) & 3u) << 4);
}

#define LDSM_X4(r, a)                                                        \
    asm volatile("ldmatrix.sync.aligned.m8n8.x4.shared.b16 {%0,%1,%2,%3}, [%4];" \
        : "=r"((r)[0]), "=r"((r)[1]), "=r"((r)[2]), "=r"((r)[3]) : "r"(a))
#define LDSM_X4T(r, a)                                                       \
    asm volatile("ldmatrix.sync.aligned.m8n8.x4.trans.shared.b16 {%0,%1,%2,%3}, [%4];" \
        : "=r"((r)[0]), "=r"((r)[1]), "=r"((r)[2]), "=r"((r)[3]) : "r"(a))

// bf16 in, f32 accum (attention)
#define MMA_BF(c, a, b)                                                      \
    asm volatile("mma.sync.aligned.m16n8k16.row.col.f32.bf16.bf16.f32 "      \
        "{%0,%1,%2,%3}, {%4,%5,%6,%7}, {%8,%9}, {%0,%1,%2,%3};"              \
        : "+f"((c)[0]), "+f"((c)[1]), "+f"((c)[2]), "+f"((c)[3])             \
        : "r"((a)[0]), "r"((a)[1]), "r"((a)[2]), "r"((a)[3]),                \
          "r"((b)[0]), "r"((b)[1]))
// fp16 in, f32 accum (GEMM hi*hi)
#define MMA_FH(c, a, b)                                                      \
    asm volatile("mma.sync.aligned.m16n8k16.row.col.f32.f16.f16.f32 "        \
        "{%0,%1,%2,%3}, {%4,%5,%6,%7}, {%8,%9}, {%0,%1,%2,%3};"              \
        : "+f"((c)[0]), "+f"((c)[1]), "+f"((c)[2]), "+f"((c)[3])             \
        : "r"((a)[0]), "r"((a)[1]), "r"((a)[2]), "r"((a)[3]),                \
          "r"((b)[0]), "r"((b)[1]))
// fp16 in, f16 accum (GEMM cross term)
#define MMA_HH(c2, a, b)                                                     \
    asm volatile("mma.sync.aligned.m16n8k16.row.col.f16.f16.f16.f16 "        \
        "{%0,%1}, {%2,%3,%4,%5}, {%6,%7}, {%0,%1};"                          \
        : "+r"((c2)[0]), "+r"((c2)[1])                                       \
        : "r"((a)[0]), "r"((a)[1]), "r"((a)[2]), "r"((a)[3]),                \
          "r"((b)[0]), "r"((b)[1]))

#define CP16(d, s) \
    asm volatile("cp.async.cg.shared.global [%0], [%1], 16;" :: "r"(d), "l"(s) : "memory")
#define CP_COMMIT() asm volatile("cp.async.commit_group;" ::: "memory")
#define CP_WAIT(n)  asm volatile("cp.async.wait_group %0;" :: "n"(n) : "memory")

static __device__ __forceinline__ uint32_t pk2(float x, float y) {   // bf16x2
    uint32_t r;
    asm("cvt.rn.bf16x2.f32 %0, %1, %2;" : "=r"(r) : "f"(y), "f"(x));
    return r;
}
static __device__ __forceinline__ uint32_t pk2h(float x, float y) {  // f16x2
    uint32_t r;
    asm("cvt.rn.f16x2.f32 %0, %1, %2;" : "=r"(r) : "f"(y), "f"(x));
    return r;
}
static __device__ __forceinline__ float rbf(float x) {
    return __bfloat162float(__float2bfloat16_rn(x));
}

// =====================================================================
// Kernel 1: CPB-MLP bias table + logit scale
// =====================================================================
__device__ __forceinline__ float cpb_coord(int i) {
    float x = (float)(i - 6) * (8.0f / 6.0f);
    return copysignf(log1pf(fabsf(x)) * 0.4808983469629878f, x);
}

__global__ void cpb_kernel(const float* __restrict__ logit_scale,
                           const float* __restrict__ w1,
                           const float* __restrict__ b1,
                           const float* __restrict__ w2,
                           float* __restrict__ bias_out,
                           float* __restrict__ scale_out)
{
    __shared__ float table[169][HEADS];
    const int tid = threadIdx.x;

    if (tid < HEADS) {
        float ls = logit_scale[tid];
        ls = fminf(ls, logf(100.0f));
        ls = fmaxf(ls, -100.0f);
        scale_out[tid] = expf(ls);
    }
    for (int e = tid; e < 169; e += blockDim.x) {
        const int i = e / 13, j = e % 13;
        const float c0 = cpb_coord(i);
        const float c1 = cpb_coord(j);
        float acc[HEADS];
#pragma unroll
        for (int hh = 0; hh < HEADS; hh++) acc[hh] = 0.0f;
        for (int kk = 0; kk < 512; kk++) {
            float hpre = c0 * w1[kk] + c1 * w1[512 + kk] + b1[kk];
            float g = 0.5f * hpre * (1.0f + erff(hpre * 0.7071067811865475f));
#pragma unroll
            for (int hh = 0; hh < HEADS; hh++) acc[hh] += g * w2[kk * 8 + hh];
        }
#pragma unroll
        for (int hh = 0; hh < HEADS; hh++) table[e][hh] = acc[hh];
    }
    __syncthreads();

    for (int idx = tid; idx < HEADS * NTOK * NTOK; idx += blockDim.x) {
        const int hh  = idx / (NTOK * NTOK);
        const int rem = idx % (NTOK * NTOK);
        const int r   = rem / NTOK;
        const int c   = rem % NTOK;
        const int dh  = (r / 7) - (c / 7) + 6;
        const int dw  = (r % 7) - (c % 7) + 6;
        const float v = table[dh * 13 + dw][hh];
        bias_out[hh * 3584 + r * 56 + c] = 16.0f / (1.0f + __expf(-v));
    }
}

// =====================================================================
// Kernel 1b: split weights fp32 -> hi/lo fp16 chunks (lo pre-scaled x2048)
// =====================================================================
__global__ void wsplit_kernel(const float* __restrict__ wq, const float* __restrict__ wp,
                              unsigned char* __restrict__ oq, unsigned char* __restrict__ op)
{
    const int stride = gridDim.x * blockDim.x;
    const int t0 = blockIdx.x * blockDim.x + threadIdx.x;
    for (int idx = t0; idx < 256 * QKVCOL; idx += stride) {
        const int k = idx / QKVCOL, n = idx % QKVCOL;
        float f = wq[idx];
        __half h = __float2half_rn(f);
        __half l = __float2half_rn((f - __half2float(h)) * LOSC);
        const uint32_t off = (uint32_t)((n >> 7) * 8 + (k >> 5)) * 16384u
                           + (uint32_t)(k & 31) * 256u + swz((uint32_t)(n & 127) * 2u, (uint32_t)k);
        *(__half*)(oq + off)        = h;
        *(__half*)(oq + off + 8192) = l;
    }
    for (int idx = t0; idx < 256 * 256; idx += stride) {
        const int k = idx >> 8, n = idx & 255;
        float f = wp[idx];
        __half h = __float2half_rn(f);
        __half l = __float2half_rn((f - __half2float(h)) * LOSC);
        const uint32_t off = (uint32_t)((n >> 7) * 8 + (k >> 5)) * 16384u
                           + (uint32_t)(k & 31) * 256u + swz((uint32_t)(n & 127) * 2u, (uint32_t)k);
        *(__half*)(op + off)        = h;
        *(__half*)(op + off + 8192) = l;
    }
}

// =====================================================================
// Kernel 2/4: 2-product fp16 GEMM.  D = A16*Whi (f32 acc) + A16*Wlo'
//   (f16 acc, lo pre-scaled x2048, rescaled at epilogue).
//   A plain fp16 in smem (32KB); W 4-stage cp.async pipeline (64KB).
// =====================================================================
#define SMW_OFF 32768
#define GEMM_SMEM (32768 + 4 * 16384)

__global__ __launch_bounds__(256, 2)
void gemm_mma(const float* __restrict__ A, const unsigned char* __restrict__ Wp,
              const float* __restrict__ bias, float* __restrict__ C, int NT)
{
    extern __shared__ char smem[];
    const uint32_t sb = s2u(smem);
    const int tid  = threadIdx.x;
    const int lane = tid & 31;
    const int w    = tid >> 5;
    const int row0 = blockIdx.x * 64;
    const int Ncols = NT * 128;

    // A: fp32 -> fp16, 64 rows x 512B, swizzled
    for (int i = tid; i < 4096; i += 256) {
        const int r  = i >> 6;
        const int c4 = (i & 63) << 2;
        float4 a = *(const float4*)(A + (size_t)(row0 + r) * 256 + c4);
        const uint32_t off = (uint32_t)r * 512u + swz((uint32_t)c4 * 2u, (uint32_t)r);
        uint2 hu; hu.x = pk2h(a.x, a.y); hu.y = pk2h(a.z, a.w);
        *(uint2*)(smem + off) = hu;
    }

    const int wm = w & 1;        // m0 = wm*32
    const int wn = w >> 1;       // n0 = wn*32

    const int NCH = NT * 8;

    // prefetch chunks 0,1,2
#pragma unroll
    for (int pf = 0; pf < 3; pf++) {
        const unsigned char* src = Wp + (size_t)pf * 16384;
        const uint32_t dst = sb + SMW_OFF + (uint32_t)pf * 16384u;
#pragma unroll
        for (int j = 0; j < 4; j++)
            CP16(dst + (uint32_t)(tid * 16 + j * 4096), src + tid * 16 + j * 4096);
        CP_COMMIT();
    }
    __syncthreads();

    float    acc [2][4][4];
    uint32_t acch[2][4][2];
    int nt = 0;
#pragma unroll
    for (int mf = 0; mf < 2; mf++)
#pragma unroll
        for (int nf = 0; nf < 4; nf++) {
#pragma unroll
            for (int q = 0; q < 4; q++) acc[mf][nf][q] = 0.0f;
            acch[mf][nf][0] = 0u; acch[mf][nf][1] = 0u;
        }

    for (int gc = 0; gc < NCH; gc++) {
        if (gc + 3 < NCH) {
            const unsigned char* src = Wp + (size_t)(gc + 3) * 16384;
            const uint32_t dst = sb + SMW_OFF + (uint32_t)(((gc + 3) & 3) * 16384);
#pragma unroll
            for (int j = 0; j < 4; j++)
                CP16(dst + (uint32_t)(tid * 16 + j * 4096), src + tid * 16 + j * 4096);
        }
        CP_COMMIT();
        CP_WAIT(3);
        __syncthreads();

        const uint32_t st = sb + SMW_OFF + (uint32_t)((gc & 3) * 16384);
        const int kc = gc & 7;

#pragma unroll
        for (int ks = 0; ks < 2; ks++) {
            uint32_t ah[2][4];
            const int arow = wm * 32 + ((lane >> 3) & 1) * 8 + (lane & 7);
            const int kg   = kc * 32 + ks * 16 + ((lane >> 4) << 3);
#pragma unroll
            for (int mf = 0; mf < 2; mf++) {
                const uint32_t r = (uint32_t)(arow + mf * 16);
                LDSM_X4(ah[mf], sb + r * 512u + swz((uint32_t)kg * 2u, r));
            }
            uint32_t bh[2][4], bl[2][4];
            const uint32_t krow = (uint32_t)(ks * 16 + ((lane >> 3) & 1) * 8 + (lane & 7));
#pragma unroll
            for (int nf2 = 0; nf2 < 2; nf2++) {
                const uint32_t ncol = (uint32_t)(wn * 32 + nf2 * 16 + (lane >> 4) * 8);
                const uint32_t addr = st + krow * 256u + swz(ncol * 2u, krow);
                LDSM_X4T(bh[nf2], addr);
                LDSM_X4T(bl[nf2], addr + 8192u);
            }
#pragma unroll
            for (int mf = 0; mf < 2; mf++)
#pragma unroll
                for (int nf = 0; nf < 4; nf++) {
                    uint32_t* bph = &bh[nf >> 1][(nf & 1) * 2];
                    uint32_t* bpl = &bl[nf >> 1][(nf & 1) * 2];
                    MMA_FH(acc[mf][nf], ah[mf], bph);     // A*hi  (f32 accum)
                    MMA_HH(acch[mf][nf], ah[mf], bpl);    // A*lo' (f16 accum)
                }
        }
        __syncthreads();

        if (kc == 7) {
            const int g = lane >> 2, t = lane & 3;
#pragma unroll
            for (int nf = 0; nf < 4; nf++) {
                const int col = nt * 128 + wn * 32 + nf * 8 + t * 2;
                const float2 bv = *(const float2*)(bias + col);
#pragma unroll
                for (int mf = 0; mf < 2; mf++) {
                    const int row = row0 + wm * 32 + mf * 16 + g;
                    float2 c01 = __half22float2(*(const __half2*)&acch[mf][nf][0]);
                    float2 c23 = __half22float2(*(const __half2*)&acch[mf][nf][1]);
                    float2 v0 = make_float2(acc[mf][nf][0] + c01.x * LOINV + bv.x,
                                            acc[mf][nf][1] + c01.y * LOINV + bv.y);
                    float2 v1 = make_float2(acc[mf][nf][2] + c23.x * LOINV + bv.x,
                                            acc[mf][nf][3] + c23.y * LOINV + bv.y);
                    *(float2*)(C + (size_t)row * Ncols + col)       = v0;
                    *(float2*)(C + (size_t)(row + 8) * Ncols + col) = v1;
                }
            }
            nt++;
#pragma unroll
            for (int mf = 0; mf < 2; mf++)
#pragma unroll
                for (int nf = 0; nf < 4; nf++) {
#pragma unroll
                    for (int q = 0; q < 4; q++) acc[mf][nf][q] = 0.0f;
                    acch[mf][nf][0] = 0u; acch[mf][nf][1] = 0u;
                }
        }
    }
}

// =====================================================================
// Kernel 3: tensor-core window attention — 4 heads/CTA, grid (2048, 2),
//   256 threads (2 warps/head), 2 CTAs/SM.  (unchanged from R6)
// =====================================================================
#define AHEAD 21504
#define AQH 0
#define AQL 3584
#define AKH 7168
#define AKL 10752
#define AVH 14336
#define AVL 17920
#define ATTN_SMEM (4 * AHEAD + 512)

__global__ __launch_bounds__(256, 2)
void attn_tc(const float* __restrict__ qkv,
             const float* __restrict__ bias,
             const float* __restrict__ scale,
             float* __restrict__ attn_out)
{
    extern __shared__ char smem[];
    const uint32_t sb = s2u(smem);
    const int b    = blockIdx.x;
    const int hg   = blockIdx.y;
    const int tid  = threadIdx.x;
    const int lane = tid & 31;
    const int wrp  = tid >> 5;

    {
        int i = tid;
        if (i < 224) {
            const int slot = i / 56, rem = i % 56;
            const int half = rem / 28, rr = 49 + (rem % 28) / 4, c16 = (rem & 3) * 16;
            *(uint4*)(smem + slot * AHEAD + (half ? AVL : AVH) + rr * 64 + c16) =
                make_uint4(0, 0, 0, 0);
        } else if (i < 256) {
            *(uint4*)(smem + 4 * AHEAD + (i - 224) * 16) = make_uint4(0, 0, 0, 0);
        }
    }

    {
        const float* wb = qkv + (size_t)b * NTOK * QKVCOL;
        const int team = tid >> 3, l8 = tid & 7;
        for (int it = team; it < 196; it += 32) {
            const int tok = it >> 2, slot = it & 3;
            const int hh  = hg * 4 + slot;
            const float* rowp = wb + (size_t)tok * QKVCOL + hh * HD + l8 * 4;
            float4 q = *(const float4*)(rowp);
            float4 k = *(const float4*)(rowp + 256);
            float4 v = *(const float4*)(rowp + 512);
            float qss = q.x*q.x + q.y*q.y + q.z*q.z + q.w*q.w;
            float kss = k.x*k.x + k.y*k.y + k.z*k.z + k.w*k.w;
#pragma unroll
            for (int o = 4; o > 0; o >>= 1) {
                qss += __shfl_xor_sync(0xffffffffu, qss, o);
                kss += __shfl_xor_sync(0xffffffffu, kss, o);
            }
            const float qr = rsqrtf(qss) * __ldg(scale + hh);
            const float kr = rsqrtf(kss);
            q.x *= qr; q.y *= qr; q.z *= qr; q.w *= qr;
            k.x *= kr; k.y *= kr; k.z *= kr; k.w *= kr;

            const uint32_t base = (uint32_t)slot * AHEAD + (uint32_t)tok * 64u
                                + swz64((uint32_t)l8 * 8u, (uint32_t)tok);
            {
                float hx = rbf(q.x), hy = rbf(q.y), hz = rbf(q.z), hw = rbf(q.w);
                uint2 hu; hu.x = pk2(hx, hy); hu.y = pk2(hz, hw);
                uint2 lu; lu.x = pk2(q.x - hx, q.y - hy); lu.y = pk2(q.z - hz, q.w - hw);
                *(uint2*)(smem + AQH + base) = hu;
                *(uint2*)(smem + AQL + base) = lu;
            }
            {
                float hx = rbf(k.x), hy = rbf(k.y), hz = rbf(k.z), hw = rbf(k.w);
                uint2 hu; hu.x = pk2(hx, hy); hu.y = pk2(hz, hw);
                uint2 lu; lu.x = pk2(k.x - hx, k.y - hy); lu.y = pk2(k.z - hz, k.w - hw);
                *(uint2*)(smem + AKH + base) = hu;
                *(uint2*)(smem + AKL + base) = lu;
            }
            {
                float hx = rbf(v.x), hy = rbf(v.y), hz = rbf(v.z), hw = rbf(v.w);
                uint2 hu; hu.x = pk2(hx, hy); hu.y = pk2(hz, hw);
                uint2 lu; lu.x = pk2(v.x - hx, v.y - hy); lu.y = pk2(v.z - hz, v.w - hw);
                *(uint2*)(smem + AVH + base) = hu;
                *(uint2*)(smem + AVL + base) = lu;
            }
        }
    }
    __syncthreads();

    const int slot = wrp >> 1;
    const int h    = hg * 4 + slot;
    const int m0base = (wrp & 1) * 32;
    const uint32_t hb = sb + (uint32_t)slot * AHEAD;
    const float* bslab = bias + h * 3584;
    float* obase = attn_out + (size_t)b * NTOK * DIMF + h * HD;
    const int qrow = lane >> 2;
    const int qc   = (lane & 3) * 2;

#pragma unroll
    for (int mc = 0; mc < 2; mc++) {
        const int m0 = m0base + mc * 16;

        float S[7][4];
#pragma unroll
        for (int n = 0; n < 7; n++)
#pragma unroll
            for (int q = 0; q < 4; q++) S[n][q] = 0.0f;

#pragma unroll
        for (int ks = 0; ks < 2; ks++) {
            uint32_t ah[4], al[4];
            {
                const uint32_t r = (uint32_t)(m0 + ((lane >> 3) & 1) * 8 + (lane & 7));
                const uint32_t cb = (uint32_t)(ks * 32 + (lane >> 4) * 16);
                const uint32_t ad = hb + AQH + r * 64u + swz64(cb, r);
                LDSM_X4(ah, ad);
                LDSM_X4(al, ad + (AQL - AQH));
            }
#pragma unroll
            for (int ng = 0; ng < 4; ng++) {
                uint32_t bh[4], bl[4];
                const uint32_t r = (uint32_t)(ng * 16 + (lane & 7) + ((lane >> 4) << 3));
                const uint32_t cb = (uint32_t)(ks * 32 + ((lane >> 3) & 1) * 16);
                const uint32_t ad = hb + AKH + r * 64u + swz64(cb, r);
                LDSM_X4(bh, ad);
                LDSM_X4(bl, ad + (AKL - AKH));
                MMA_BF(S[2 * ng], ah, bh);
                MMA_BF(S[2 * ng], ah, bl);
                MMA_BF(S[2 * ng], al, bh);
                if (ng < 3) {
                    MMA_BF(S[2 * ng + 1], ah, bh + 2);
                    MMA_BF(S[2 * ng + 1], ah, bl + 2);
                    MMA_BF(S[2 * ng + 1], al, bh + 2);
                }
            }
        }

        {
            const int r0 = m0 + qrow;
            float mx0 = -1e30f, mx1 = -1e30f;
#pragma unroll
            for (int nf = 0; nf < 7; nf++) {
                const int c0 = nf * 8 + qc;
                const float2 b0 = *(const float2*)(bslab + r0 * 56 + c0);
                const float2 b1 = *(const float2*)(bslab + (r0 + 8) * 56 + c0);
                S[nf][0] = (c0     < 49) ? S[nf][0] + b0.x : -1e30f;
                S[nf][1] = (c0 + 1 < 49) ? S[nf][1] + b0.y : -1e30f;
                S[nf][2] = (c0     < 49) ? S[nf][2] + b1.x : -1e30f;
                S[nf][3] = (c0 + 1 < 49) ? S[nf][3] + b1.y : -1e30f;
                mx0 = fmaxf(mx0, fmaxf(S[nf][0], S[nf][1]));
                mx1 = fmaxf(mx1, fmaxf(S[nf][2], S[nf][3]));
            }
#pragma unroll
            for (int o = 1; o < 4; o <<= 1) {
                mx0 = fmaxf(mx0, __shfl_xor_sync(0xffffffffu, mx0, o));
                mx1 = fmaxf(mx1, __shfl_xor_sync(0xffffffffu, mx1, o));
            }
            float rs0 = 0.0f, rs1 = 0.0f;
#pragma unroll
            for (int nf = 0; nf < 7; nf++) {
                float p0 = __expf(S[nf][0] - mx0);
                float p1 = __expf(S[nf][1] - mx0);
                float p2 = __expf(S[nf][2] - mx1);
                float p3 = __expf(S[nf][3] - mx1);
                S[nf][0] = p0; S[nf][1] = p1; S[nf][2] = p2; S[nf][3] = p3;
                rs0 += p0 + p1;  rs1 += p2 + p3;
            }
#pragma unroll
            for (int o = 1; o < 4; o <<= 1) {
                rs0 += __shfl_xor_sync(0xffffffffu, rs0, o);
                rs1 += __shfl_xor_sync(0xffffffffu, rs1, o);
            }
            const float iv0 = 1.0f / rs0, iv1 = 1.0f / rs1;
#pragma unroll
            for (int nf = 0; nf < 7; nf++) {
                S[nf][0] *= iv0; S[nf][1] *= iv0;
                S[nf][2] *= iv1; S[nf][3] *= iv1;
            }
        }

        float O[4][4];
#pragma unroll
        for (int n = 0; n < 4; n++)
#pragma unroll
            for (int q = 0; q < 4; q++) O[n][q] = 0.0f;

#pragma unroll
        for (int kt = 0; kt < 4; kt++) {
            uint32_t ph[4], pl[4];
            {
                float pa0 = S[2*kt][0], pa1 = S[2*kt][1], pa2 = S[2*kt][2], pa3 = S[2*kt][3];
                float pb0 = 0.f, pb1 = 0.f, pb2 = 0.f, pb3 = 0.f;
                if (kt < 3) {
                    pb0 = S[2*kt+1][0]; pb1 = S[2*kt+1][1];
                    pb2 = S[2*kt+1][2]; pb3 = S[2*kt+1][3];
                }
                const float ha0 = rbf(pa0), ha1 = rbf(pa1), ha2 = rbf(pa2), ha3 = rbf(pa3);
                const float hb0 = rbf(pb0), hb1 = rbf(pb1), hb2 = rbf(pb2), hb3 = rbf(pb3);
                ph[0] = pk2(ha0, ha1);  ph[1] = pk2(ha2, ha3);
                ph[2] = pk2(hb0, hb1);  ph[3] = pk2(hb2, hb3);
                pl[0] = pk2(pa0 - ha0, pa1 - ha1);
                pl[1] = pk2(pa2 - ha2, pa3 - ha3);
                pl[2] = pk2(pb0 - hb0, pb1 - hb1);
                pl[3] = pk2(pb2 - hb2, pb3 - hb3);
            }
#pragma unroll
            for (int vg = 0; vg < 2; vg++) {
                uint32_t vh[4], vl[4];
                const uint32_t kr = (uint32_t)(kt * 16 + ((lane >> 3) & 1) * 8 + (lane & 7));
                const uint32_t cb = (uint32_t)(vg * 32 + (lane >> 4) * 16);
                const uint32_t ad = hb + AVH + kr * 64u + swz64(cb, kr);
                LDSM_X4T(vh, ad);
                LDSM_X4T(vl, ad + (AVL - AVH));
#pragma unroll
                for (int nn = 0; nn < 2; nn++) {
                    float* oo = O[vg * 2 + nn];
                    MMA_BF(oo, ph, vh + nn * 2);
                    MMA_BF(oo, ph, vl + nn * 2);
                    MMA_BF(oo, pl, vh + nn * 2);
                }
            }
        }

        {
            const int r0 = m0 + qrow;
#pragma unroll
            for (int nf = 0; nf < 4; nf++) {
                const int c = nf * 8 + qc;
                if (r0 < NTOK)
                    *(float2*)(obase + (size_t)r0 * DIMF + c) = make_float2(O[nf][0], O[nf][1]);
                if (r0 + 8 < NTOK)
                    *(float2*)(obase + (size_t)(r0 + 8) * DIMF + c) = make_float2(O[nf][2], O[nf][3]);
            }
        }
    }
}

// =====================================================================
// launch
// =====================================================================
extern "C" void kernel_launch(void* const* d_in, const int* in_sizes, int n_in,
                              void* d_out, int out_size)
{
    const float* x           = (const float*)d_in[0];
    const float* qkv_w       = (const float*)d_in[1];
    const float* qkv_b       = (const float*)d_in[2];
    const float* proj_w      = (const float*)d_in[3];
    const float* proj_b      = (const float*)d_in[4];
    const float* logit_scale = (const float*)d_in[5];
    const float* cpb_w1      = (const float*)d_in[6];
    const float* cpb_b1      = (const float*)d_in[7];
    const float* cpb_w2      = (const float*)d_in[8];
    float* out = (float*)d_out;

    float *qkvbuf, *attnbuf, *biasbuf, *scalebuf;
    unsigned char *wqbuf, *wpbuf;
    cudaGetSymbolAddress((void**)&qkvbuf,   g_qkv);
    cudaGetSymbolAddress((void**)&attnbuf,  g_attn);
    cudaGetSymbolAddress((void**)&biasbuf,  g_bias);
    cudaGetSymbolAddress((void**)&scalebuf, g_scale);
    cudaGetSymbolAddress((void**)&wqbuf,    g_wq);
    cudaGetSymbolAddress((void**)&wpbuf,    g_wp);

    cudaFuncSetAttribute(gemm_mma, cudaFuncAttributeMaxDynamicSharedMemorySize, GEMM_SMEM);
    cudaFuncSetAttribute(attn_tc,  cudaFuncAttributeMaxDynamicSharedMemorySize, ATTN_SMEM);

    cpb_kernel<<<1, 256>>>(logit_scale, cpb_w1, cpb_b1, cpb_w2, biasbuf, scalebuf);
    wsplit_kernel<<<128, 256>>>(qkv_w, proj_w, wqbuf, wpbuf);

    gemm_mma<<<MROWS / 64, 256, GEMM_SMEM>>>(x, wqbuf, qkv_b, qkvbuf, 6);

    attn_tc<<<dim3(B_WIN, 2), 256, ATTN_SMEM>>>(qkvbuf, biasbuf, scalebuf, attnbuf);

    gemm_mma<<<MROWS / 64, 256, GEMM_SMEM>>>(attnbuf, wpbuf, proj_b, out, 2);
}

// round 8
// speedup vs baseline: 2.2493x; 1.0267x over previous
#include <cuda_runtime.h>
#include <cuda_bf16.h>
#include <cuda_fp16.h>
#include <cstdint>

// ---------------- problem constants ----------------
#define B_WIN  2048
#define NTOK   49
#define DIMF   256
#define HEADS  8
#define HD     32
#define MROWS  (B_WIN * NTOK)        // 100352
#define QKVCOL 768

#define LOSC   2048.0f               // lo-term pre-scale (keeps fp16 normal)
#define LOINV  4.8828125e-4f         // 1/2048

// ---------------- scratch ----------------
__device__ float g_qkv [MROWS * QKVCOL];
__device__ float g_attn[MROWS * DIMF];
__device__ float g_bias[HEADS * 64 * 56];   // padded [8][64][56]; pads stay 0
__device__ float g_scale[HEADS];
__device__ unsigned char g_wq[48 * 16384];  // fp16 hi/lo chunks
__device__ unsigned char g_wp[16 * 16384];

// ---------------- helpers ----------------
static __device__ __forceinline__ uint32_t s2u(const void* p) {
    uint32_t a;
    asm("{ .reg .u64 t; cvta.to.shared.u64 t, %1; cvt.u32.u64 %0, t; }" : "=r"(a) : "l"(p));
    return a;
}
static __device__ __forceinline__ uint32_t swz(uint32_t byte_in_row, uint32_t row) {
    return (byte_in_row & ~0x7Fu) | ((byte_in_row & 0x7Fu) ^ ((row & 7u) << 4));
}
static __device__ __forceinline__ uint32_t swz64(uint32_t c, uint32_t row) {
    return (c & 0xFu) | (((((c >> 4) ^ ((row >> 1) & 3u))) & 3u) << 4);
}

#define LDSM_X4(r, a)                                                        \
    asm volatile("ldmatrix.sync.aligned.m8n8.x4.shared.b16 {%0,%1,%2,%3}, [%4];" \
        : "=r"((r)[0]), "=r"((r)[1]), "=r"((r)[2]), "=r"((r)[3]) : "r"(a))
#define LDSM_X4T(r, a)                                                       \
    asm volatile("ldmatrix.sync.aligned.m8n8.x4.trans.shared.b16 {%0,%1,%2,%3}, [%4];" \
        : "=r"((r)[0]), "=r"((r)[1]), "=r"((r)[2]), "=r"((r)[3]) : "r"(a))

// bf16 in, f32 accum (attention)
#define MMA_BF(c, a, b)                                                      \
    asm volatile("mma.sync.aligned.m16n8k16.row.col.f32.bf16.bf16.f32 "      \
        "{%0,%1,%2,%3}, {%4,%5,%6,%7}, {%8,%9}, {%0,%1,%2,%3};"              \
        : "+f"((c)[0]), "+f"((c)[1]), "+f"((c)[2]), "+f"((c)[3])             \
        : "r"((a)[0]), "r"((a)[1]), "r"((a)[2]), "r"((a)[3]),                \
          "r"((b)[0]), "r"((b)[1]))
// fp16 in, f32 accum (GEMM hi product)
#define MMA_FH(c, a, b)                                                      \
    asm volatile("mma.sync.aligned.m16n8k16.row.col.f32.f16.f16.f32 "        \
        "{%0,%1,%2,%3}, {%4,%5,%6,%7}, {%8,%9}, {%0,%1,%2,%3};"              \
        : "+f"((c)[0]), "+f"((c)[1]), "+f"((c)[2]), "+f"((c)[3])             \
        : "r"((a)[0]), "r"((a)[1]), "r"((a)[2]), "r"((a)[3]),                \
          "r"((b)[0]), "r"((b)[1]))
// fp16 in, f16 accum (GEMM lo cross term)
#define MMA_HH(c2, a, b)                                                     \
    asm volatile("mma.sync.aligned.m16n8k16.row.col.f16.f16.f16.f16 "        \
        "{%0,%1}, {%2,%3,%4,%5}, {%6,%7}, {%0,%1};"                          \
        : "+r"((c2)[0]), "+r"((c2)[1])                                       \
        : "r"((a)[0]), "r"((a)[1]), "r"((a)[2]), "r"((a)[3]),                \
          "r"((b)[0]), "r"((b)[1]))

#define CP16(d, s) \
    asm volatile("cp.async.cg.shared.global [%0], [%1], 16;" :: "r"(d), "l"(s) : "memory")
#define CP_COMMIT() asm volatile("cp.async.commit_group;" ::: "memory")
#define CP_WAIT(n)  asm volatile("cp.async.wait_group %0;" :: "n"(n) : "memory")

static __device__ __forceinline__ uint32_t pk2(float x, float y) {   // bf16x2
    uint32_t r;
    asm("cvt.rn.bf16x2.f32 %0, %1, %2;" : "=r"(r) : "f"(y), "f"(x));
    return r;
}
static __device__ __forceinline__ uint32_t pk2h(float x, float y) {  // f16x2
    uint32_t r;
    asm("cvt.rn.f16x2.f32 %0, %1, %2;" : "=r"(r) : "f"(y), "f"(x));
    return r;
}
static __device__ __forceinline__ float rbf(float x) {
    return __bfloat162float(__float2bfloat16_rn(x));
}

// =====================================================================
// Kernel 1: CPB-MLP bias table + logit scale
// =====================================================================
__device__ __forceinline__ float cpb_coord(int i) {
    float x = (float)(i - 6) * (8.0f / 6.0f);
    return copysignf(log1pf(fabsf(x)) * 0.4808983469629878f, x);
}

__global__ void cpb_kernel(const float* __restrict__ logit_scale,
                           const float* __restrict__ w1,
                           const float* __restrict__ b1,
                           const float* __restrict__ w2,
                           float* __restrict__ bias_out,
                           float* __restrict__ scale_out)
{
    __shared__ float table[169][HEADS];
    const int tid = threadIdx.x;

    if (tid < HEADS) {
        float ls = logit_scale[tid];
        ls = fminf(ls, logf(100.0f));
        ls = fmaxf(ls, -100.0f);
        scale_out[tid] = expf(ls);
    }
    for (int e = tid; e < 169; e += blockDim.x) {
        const int i = e / 13, j = e % 13;
        const float c0 = cpb_coord(i);
        const float c1 = cpb_coord(j);
        float acc[HEADS];
#pragma unroll
        for (int hh = 0; hh < HEADS; hh++) acc[hh] = 0.0f;
        for (int kk = 0; kk < 512; kk++) {
            float hpre = c0 * w1[kk] + c1 * w1[512 + kk] + b1[kk];
            float g = 0.5f * hpre * (1.0f + erff(hpre * 0.7071067811865475f));
#pragma unroll
            for (int hh = 0; hh < HEADS; hh++) acc[hh] += g * w2[kk * 8 + hh];
        }
#pragma unroll
        for (int hh = 0; hh < HEADS; hh++) table[e][hh] = acc[hh];
    }
    __syncthreads();

    for (int idx = tid; idx < HEADS * NTOK * NTOK; idx += blockDim.x) {
        const int hh  = idx / (NTOK * NTOK);
        const int rem = idx % (NTOK * NTOK);
        const int r   = rem / NTOK;
        const int c   = rem % NTOK;
        const int dh  = (r / 7) - (c / 7) + 6;
        const int dw  = (r % 7) - (c % 7) + 6;
        const float v = table[dh * 13 + dw][hh];
        bias_out[hh * 3584 + r * 56 + c] = 16.0f / (1.0f + __expf(-v));
    }
}

// =====================================================================
// Kernel 1b: split weights fp32 -> hi/lo fp16 chunks (lo pre-scaled x2048)
// =====================================================================
__global__ void wsplit_kernel(const float* __restrict__ wq, const float* __restrict__ wp,
                              unsigned char* __restrict__ oq, unsigned char* __restrict__ op)
{
    const int stride = gridDim.x * blockDim.x;
    const int t0 = blockIdx.x * blockDim.x + threadIdx.x;
    for (int idx = t0; idx < 256 * QKVCOL; idx += stride) {
        const int k = idx / QKVCOL, n = idx % QKVCOL;
        float f = wq[idx];
        __half h = __float2half_rn(f);
        __half l = __float2half_rn((f - __half2float(h)) * LOSC);
        const uint32_t off = (uint32_t)((n >> 7) * 8 + (k >> 5)) * 16384u
                           + (uint32_t)(k & 31) * 256u + swz((uint32_t)(n & 127) * 2u, (uint32_t)k);
        *(__half*)(oq + off)        = h;
        *(__half*)(oq + off + 8192) = l;
    }
    for (int idx = t0; idx < 256 * 256; idx += stride) {
        const int k = idx >> 8, n = idx & 255;
        float f = wp[idx];
        __half h = __float2half_rn(f);
        __half l = __float2half_rn((f - __half2float(h)) * LOSC);
        const uint32_t off = (uint32_t)((n >> 7) * 8 + (k >> 5)) * 16384u
                           + (uint32_t)(k & 31) * 256u + swz((uint32_t)(n & 127) * 2u, (uint32_t)k);
        *(__half*)(op + off)        = h;
        *(__half*)(op + off + 8192) = l;
    }
}

// =====================================================================
// Kernel 2/4: 2-product fp16 GEMM, single-sync 4-stage pipeline.
//   iter gc: CP_WAIT(2) -> __syncthreads -> prefetch gc+3 -> compute gc
// =====================================================================
#define SMW_OFF 32768
#define GEMM_SMEM (32768 + 4 * 16384)

__global__ __launch_bounds__(256, 2)
void gemm_mma(const float* __restrict__ A, const unsigned char* __restrict__ Wp,
              const float* __restrict__ bias, float* __restrict__ C, int NT)
{
    extern __shared__ char smem[];
    const uint32_t sb = s2u(smem);
    const int tid  = threadIdx.x;
    const int lane = tid & 31;
    const int w    = tid >> 5;
    const int row0 = blockIdx.x * 64;
    const int Ncols = NT * 128;

    // A: fp32 -> fp16, 64 rows x 512B, swizzled
    for (int i = tid; i < 4096; i += 256) {
        const int r  = i >> 6;
        const int c4 = (i & 63) << 2;
        float4 a = *(const float4*)(A + (size_t)(row0 + r) * 256 + c4);
        const uint32_t off = (uint32_t)r * 512u + swz((uint32_t)c4 * 2u, (uint32_t)r);
        uint2 hu; hu.x = pk2h(a.x, a.y); hu.y = pk2h(a.z, a.w);
        *(uint2*)(smem + off) = hu;
    }

    const int wm = w & 1;        // m0 = wm*32
    const int wn = w >> 1;       // n0 = wn*32

    const int NCH = NT * 8;

    // prefetch chunks 0,1,2 into stages 0,1,2
#pragma unroll
    for (int pf = 0; pf < 3; pf++) {
        const unsigned char* src = Wp + (size_t)pf * 16384;
        const uint32_t dst = sb + SMW_OFF + (uint32_t)pf * 16384u;
#pragma unroll
        for (int j = 0; j < 4; j++)
            CP16(dst + (uint32_t)(tid * 16 + j * 4096), src + tid * 16 + j * 4096);
        CP_COMMIT();
    }
    __syncthreads();   // A-tile visible to all warps

    float    acc [2][4][4];
    uint32_t acch[2][4][2];
    int nt = 0;
#pragma unroll
    for (int mf = 0; mf < 2; mf++)
#pragma unroll
        for (int nf = 0; nf < 4; nf++) {
#pragma unroll
            for (int q = 0; q < 4; q++) acc[mf][nf][q] = 0.0f;
            acch[mf][nf][0] = 0u; acch[mf][nf][1] = 0u;
        }

    for (int gc = 0; gc < NCH; gc++) {
        CP_WAIT(2);          // chunk gc landed (per-thread)
        __syncthreads();     // all warps done with chunk gc-1; data of gc visible

        // prefetch gc+3 into the stage freed by gc-1
        if (gc + 3 < NCH) {
            const unsigned char* src = Wp + (size_t)(gc + 3) * 16384;
            const uint32_t dst = sb + SMW_OFF + (uint32_t)(((gc + 3) & 3) * 16384);
#pragma unroll
            for (int j = 0; j < 4; j++)
                CP16(dst + (uint32_t)(tid * 16 + j * 4096), src + tid * 16 + j * 4096);
        }
        CP_COMMIT();

        const uint32_t st = sb + SMW_OFF + (uint32_t)((gc & 3) * 16384);
        const int kc = gc & 7;

#pragma unroll
        for (int ks = 0; ks < 2; ks++) {
            uint32_t ah[2][4];
            const int arow = wm * 32 + ((lane >> 3) & 1) * 8 + (lane & 7);
            const int kg   = kc * 32 + ks * 16 + ((lane >> 4) << 3);
#pragma unroll
            for (int mf = 0; mf < 2; mf++) {
                const uint32_t r = (uint32_t)(arow + mf * 16);
                LDSM_X4(ah[mf], sb + r * 512u + swz((uint32_t)kg * 2u, r));
            }
            uint32_t bh[2][4], bl[2][4];
            const uint32_t krow = (uint32_t)(ks * 16 + ((lane >> 3) & 1) * 8 + (lane & 7));
#pragma unroll
            for (int nf2 = 0; nf2 < 2; nf2++) {
                const uint32_t ncol = (uint32_t)(wn * 32 + nf2 * 16 + (lane >> 4) * 8);
                const uint32_t addr = st + krow * 256u + swz(ncol * 2u, krow);
                LDSM_X4T(bh[nf2], addr);
                LDSM_X4T(bl[nf2], addr + 8192u);
            }
#pragma unroll
            for (int mf = 0; mf < 2; mf++)
#pragma unroll
                for (int nf = 0; nf < 4; nf++) {
                    uint32_t* bph = &bh[nf >> 1][(nf & 1) * 2];
                    uint32_t* bpl = &bl[nf >> 1][(nf & 1) * 2];
                    MMA_FH(acc[mf][nf], ah[mf], bph);     // A*hi  (f32 accum)
                    MMA_HH(acch[mf][nf], ah[mf], bpl);    // A*lo' (f16 accum)
                }
        }

        if (kc == 7) {
            const int g = lane >> 2, t = lane & 3;
#pragma unroll
            for (int nf = 0; nf < 4; nf++) {
                const int col = nt * 128 + wn * 32 + nf * 8 + t * 2;
                const float2 bv = *(const float2*)(bias + col);
#pragma unroll
                for (int mf = 0; mf < 2; mf++) {
                    const int row = row0 + wm * 32 + mf * 16 + g;
                    float2 c01 = __half22float2(*(const __half2*)&acch[mf][nf][0]);
                    float2 c23 = __half22float2(*(const __half2*)&acch[mf][nf][1]);
                    float2 v0 = make_float2(acc[mf][nf][0] + c01.x * LOINV + bv.x,
                                            acc[mf][nf][1] + c01.y * LOINV + bv.y);
                    float2 v1 = make_float2(acc[mf][nf][2] + c23.x * LOINV + bv.x,
                                            acc[mf][nf][3] + c23.y * LOINV + bv.y);
                    *(float2*)(C + (size_t)row * Ncols + col)       = v0;
                    *(float2*)(C + (size_t)(row + 8) * Ncols + col) = v1;
                }
            }
            nt++;
#pragma unroll
            for (int mf = 0; mf < 2; mf++)
#pragma unroll
                for (int nf = 0; nf < 4; nf++) {
#pragma unroll
                    for (int q = 0; q < 4; q++) acc[mf][nf][q] = 0.0f;
                    acch[mf][nf][0] = 0u; acch[mf][nf][1] = 0u;
                }
        }
    }
}

// =====================================================================
// Kernel 3: tensor-core window attention — 4 heads/CTA, grid (2048, 2),
//   256 threads (2 warps/head), 2 CTAs/SM. Bias preloaded into S-init.
// =====================================================================
#define AHEAD 21504
#define AQH 0
#define AQL 3584
#define AKH 7168
#define AKL 10752
#define AVH 14336
#define AVL 17920
#define ATTN_SMEM (4 * AHEAD + 512)

__global__ __launch_bounds__(256, 2)
void attn_tc(const float* __restrict__ qkv,
             const float* __restrict__ bias,
             const float* __restrict__ scale,
             float* __restrict__ attn_out)
{
    extern __shared__ char smem[];
    const uint32_t sb = s2u(smem);
    const int b    = blockIdx.x;
    const int hg   = blockIdx.y;
    const int tid  = threadIdx.x;
    const int lane = tid & 31;
    const int wrp  = tid >> 5;

    {
        int i = tid;
        if (i < 224) {
            const int slot = i / 56, rem = i % 56;
            const int half = rem / 28, rr = 49 + (rem % 28) / 4, c16 = (rem & 3) * 16;
            *(uint4*)(smem + slot * AHEAD + (half ? AVL : AVH) + rr * 64 + c16) =
                make_uint4(0, 0, 0, 0);
        } else if (i < 256) {
            *(uint4*)(smem + 4 * AHEAD + (i - 224) * 16) = make_uint4(0, 0, 0, 0);
        }
    }

    {
        const float* wb = qkv + (size_t)b * NTOK * QKVCOL;
        const int team = tid >> 3, l8 = tid & 7;
        for (int it = team; it < 196; it += 32) {
            const int tok = it >> 2, slot = it & 3;
            const int hh  = hg * 4 + slot;
            const float* rowp = wb + (size_t)tok * QKVCOL + hh * HD + l8 * 4;
            float4 q = *(const float4*)(rowp);
            float4 k = *(const float4*)(rowp + 256);
            float4 v = *(const float4*)(rowp + 512);
            float qss = q.x*q.x + q.y*q.y + q.z*q.z + q.w*q.w;
            float kss = k.x*k.x + k.y*k.y + k.z*k.z + k.w*k.w;
#pragma unroll
            for (int o = 4; o > 0; o >>= 1) {
                qss += __shfl_xor_sync(0xffffffffu, qss, o);
                kss += __shfl_xor_sync(0xffffffffu, kss, o);
            }
            const float qr = rsqrtf(qss) * __ldg(scale + hh);
            const float kr = rsqrtf(kss);
            q.x *= qr; q.y *= qr; q.z *= qr; q.w *= qr;
            k.x *= kr; k.y *= kr; k.z *= kr; k.w *= kr;

            const uint32_t base = (uint32_t)slot * AHEAD + (uint32_t)tok * 64u
                                + swz64((uint32_t)l8 * 8u, (uint32_t)tok);
            {
                float hx = rbf(q.x), hy = rbf(q.y), hz = rbf(q.z), hw = rbf(q.w);
                uint2 hu; hu.x = pk2(hx, hy); hu.y = pk2(hz, hw);
                uint2 lu; lu.x = pk2(q.x - hx, q.y - hy); lu.y = pk2(q.z - hz, q.w - hw);
                *(uint2*)(smem + AQH + base) = hu;
                *(uint2*)(smem + AQL + base) = lu;
            }
            {
                float hx = rbf(k.x), hy = rbf(k.y), hz = rbf(k.z), hw = rbf(k.w);
                uint2 hu; hu.x = pk2(hx, hy); hu.y = pk2(hz, hw);
                uint2 lu; lu.x = pk2(k.x - hx, k.y - hy); lu.y = pk2(k.z - hz, k.w - hw);
                *(uint2*)(smem + AKH + base) = hu;
                *(uint2*)(smem + AKL + base) = lu;
            }
            {
                float hx = rbf(v.x), hy = rbf(v.y), hz = rbf(v.z), hw = rbf(v.w);
                uint2 hu; hu.x = pk2(hx, hy); hu.y = pk2(hz, hw);
                uint2 lu; lu.x = pk2(v.x - hx, v.y - hy); lu.y = pk2(v.z - hz, v.w - hw);
                *(uint2*)(smem + AVH + base) = hu;
                *(uint2*)(smem + AVL + base) = lu;
            }
        }
    }
    __syncthreads();

    const int slot = wrp >> 1;
    const int h    = hg * 4 + slot;
    const int m0base = (wrp & 1) * 32;
    const uint32_t hb = sb + (uint32_t)slot * AHEAD;
    const float* bslab = bias + h * 3584;
    float* obase = attn_out + (size_t)b * NTOK * DIMF + h * HD;
    const int qrow = lane >> 2;
    const int qc   = (lane & 3) * 2;

#pragma unroll
    for (int mc = 0; mc < 2; mc++) {
        const int m0 = m0base + mc * 16;
        const int r0 = m0 + qrow;

        // ---- init S with bias (pads read 0); loads hide under QK MMAs ----
        float S[7][4];
#pragma unroll
        for (int nf = 0; nf < 7; nf++) {
            const int c0 = nf * 8 + qc;
            const float2 b0 = *(const float2*)(bslab + r0 * 56 + c0);
            const float2 b1 = *(const float2*)(bslab + (r0 + 8) * 56 + c0);
            S[nf][0] = b0.x; S[nf][1] = b0.y;
            S[nf][2] = b1.x; S[nf][3] = b1.y;
        }

#pragma unroll
        for (int ks = 0; ks < 2; ks++) {
            uint32_t ah[4], al[4];
            {
                const uint32_t r = (uint32_t)(m0 + ((lane >> 3) & 1) * 8 + (lane & 7));
                const uint32_t cb = (uint32_t)(ks * 32 + (lane >> 4) * 16);
                const uint32_t ad = hb + AQH + r * 64u + swz64(cb, r);
                LDSM_X4(ah, ad);
                LDSM_X4(al, ad + (AQL - AQH));
            }
#pragma unroll
            for (int ng = 0; ng < 4; ng++) {
                uint32_t bh[4], bl[4];
                const uint32_t r = (uint32_t)(ng * 16 + (lane & 7) + ((lane >> 4) << 3));
                const uint32_t cb = (uint32_t)(ks * 32 + ((lane >> 3) & 1) * 16);
                const uint32_t ad = hb + AKH + r * 64u + swz64(cb, r);
                LDSM_X4(bh, ad);
                LDSM_X4(bl, ad + (AKL - AKH));
                MMA_BF(S[2 * ng], ah, bh);
                MMA_BF(S[2 * ng], ah, bl);
                MMA_BF(S[2 * ng], al, bh);
                if (ng < 3) {
                    MMA_BF(S[2 * ng + 1], ah, bh + 2);
                    MMA_BF(S[2 * ng + 1], ah, bl + 2);
                    MMA_BF(S[2 * ng + 1], al, bh + 2);
                }
            }
        }

        // ---- mask + softmax ----
        {
            float mx0 = -1e30f, mx1 = -1e30f;
#pragma unroll
            for (int nf = 0; nf < 7; nf++) {
                const int c0 = nf * 8 + qc;
                S[nf][0] = (c0     < 49) ? S[nf][0] : -1e30f;
                S[nf][1] = (c0 + 1 < 49) ? S[nf][1] : -1e30f;
                S[nf][2] = (c0     < 49) ? S[nf][2] : -1e30f;
                S[nf][3] = (c0 + 1 < 49) ? S[nf][3] : -1e30f;
                mx0 = fmaxf(mx0, fmaxf(S[nf][0], S[nf][1]));
                mx1 = fmaxf(mx1, fmaxf(S[nf][2], S[nf][3]));
            }
#pragma unroll
            for (int o = 1; o < 4; o <<= 1) {
                mx0 = fmaxf(mx0, __shfl_xor_sync(0xffffffffu, mx0, o));
                mx1 = fmaxf(mx1, __shfl_xor_sync(0xffffffffu, mx1, o));
            }
            float rs0 = 0.0f, rs1 = 0.0f;
#pragma unroll
            for (int nf = 0; nf < 7; nf++) {
                float p0 = __expf(S[nf][0] - mx0);
                float p1 = __expf(S[nf][1] - mx0);
                float p2 = __expf(S[nf][2] - mx1);
                float p3 = __expf(S[nf][3] - mx1);
                S[nf][0] = p0; S[nf][1] = p1; S[nf][2] = p2; S[nf][3] = p3;
                rs0 += p0 + p1;  rs1 += p2 + p3;
            }
#pragma unroll
            for (int o = 1; o < 4; o <<= 1) {
                rs0 += __shfl_xor_sync(0xffffffffu, rs0, o);
                rs1 += __shfl_xor_sync(0xffffffffu, rs1, o);
            }
            const float iv0 = 1.0f / rs0, iv1 = 1.0f / rs1;
#pragma unroll
            for (int nf = 0; nf < 7; nf++) {
                S[nf][0] *= iv0; S[nf][1] *= iv0;
                S[nf][2] *= iv1; S[nf][3] *= iv1;
            }
        }

        float O[4][4];
#pragma unroll
        for (int n = 0; n < 4; n++)
#pragma unroll
            for (int q = 0; q < 4; q++) O[n][q] = 0.0f;

#pragma unroll
        for (int kt = 0; kt < 4; kt++) {
            uint32_t ph[4], pl[4];
            {
                float pa0 = S[2*kt][0], pa1 = S[2*kt][1], pa2 = S[2*kt][2], pa3 = S[2*kt][3];
                float pb0 = 0.f, pb1 = 0.f, pb2 = 0.f, pb3 = 0.f;
                if (kt < 3) {
                    pb0 = S[2*kt+1][0]; pb1 = S[2*kt+1][1];
                    pb2 = S[2*kt+1][2]; pb3 = S[2*kt+1][3];
                }
                const float ha0 = rbf(pa0), ha1 = rbf(pa1), ha2 = rbf(pa2), ha3 = rbf(pa3);
                const float hb0 = rbf(pb0), hb1 = rbf(pb1), hb2 = rbf(pb2), hb3 = rbf(pb3);
                ph[0] = pk2(ha0, ha1);  ph[1] = pk2(ha2, ha3);
                ph[2] = pk2(hb0, hb1);  ph[3] = pk2(hb2, hb3);
                pl[0] = pk2(pa0 - ha0, pa1 - ha1);
                pl[1] = pk2(pa2 - ha2, pa3 - ha3);
                pl[2] = pk2(pb0 - hb0, pb1 - hb1);
                pl[3] = pk2(pb2 - hb2, pb3 - hb3);
            }
#pragma unroll
            for (int vg = 0; vg < 2; vg++) {
                uint32_t vh[4], vl[4];
                const uint32_t kr = (uint32_t)(kt * 16 + ((lane >> 3) & 1) * 8 + (lane & 7));
                const uint32_t cb = (uint32_t)(vg * 32 + (lane >> 4) * 16);
                const uint32_t ad = hb + AVH + kr * 64u + swz64(cb, kr);
                LDSM_X4T(vh, ad);
                LDSM_X4T(vl, ad + (AVL - AVH));
#pragma unroll
                for (int nn = 0; nn < 2; nn++) {
                    float* oo = O[vg * 2 + nn];
                    MMA_BF(oo, ph, vh + nn * 2);
                    MMA_BF(oo, ph, vl + nn * 2);
                    MMA_BF(oo, pl, vh + nn * 2);
                }
            }
        }

        {
#pragma unroll
            for (int nf = 0; nf < 4; nf++) {
                const int c = nf * 8 + qc;
                if (r0 < NTOK)
                    *(float2*)(obase + (size_t)r0 * DIMF + c) = make_float2(O[nf][0], O[nf][1]);
                if (r0 + 8 < NTOK)
                    *(float2*)(obase + (size_t)(r0 + 8) * DIMF + c) = make_float2(O[nf][2], O[nf][3]);
            }
        }
    }
}

// =====================================================================
// launch
// =====================================================================
extern "C" void kernel_launch(void* const* d_in, const int* in_sizes, int n_in,
                              void* d_out, int out_size)
{
    const float* x           = (const float*)d_in[0];
    const float* qkv_w       = (const float*)d_in[1];
    const float* qkv_b       = (const float*)d_in[2];
    const float* proj_w      = (const float*)d_in[3];
    const float* proj_b      = (const float*)d_in[4];
    const float* logit_scale = (const float*)d_in[5];
    const float* cpb_w1      = (const float*)d_in[6];
    const float* cpb_b1      = (const float*)d_in[7];
    const float* cpb_w2      = (const float*)d_in[8];
    float* out = (float*)d_out;

    float *qkvbuf, *attnbuf, *biasbuf, *scalebuf;
    unsigned char *wqbuf, *wpbuf;
    cudaGetSymbolAddress((void**)&qkvbuf,   g_qkv);
    cudaGetSymbolAddress((void**)&attnbuf,  g_attn);
    cudaGetSymbolAddress((void**)&biasbuf,  g_bias);
    cudaGetSymbolAddress((void**)&scalebuf, g_scale);
    cudaGetSymbolAddress((void**)&wqbuf,    g_wq);
    cudaGetSymbolAddress((void**)&wpbuf,    g_wp);

    cudaFuncSetAttribute(gemm_mma, cudaFuncAttributeMaxDynamicSharedMemorySize, GEMM_SMEM);
    cudaFuncSetAttribute(attn_tc,  cudaFuncAttributeMaxDynamicSharedMemorySize, ATTN_SMEM);

    cpb_kernel<<<1, 256>>>(logit_scale, cpb_w1, cpb_b1, cpb_w2, biasbuf, scalebuf);
    wsplit_kernel<<<128, 256>>>(qkv_w, proj_w, wqbuf, wpbuf);

    gemm_mma<<<MROWS / 64, 256, GEMM_SMEM>>>(x, wqbuf, qkv_b, qkvbuf, 6);

    attn_tc<<<dim3(B_WIN, 2), 256, ATTN_SMEM>>>(qkvbuf, biasbuf, scalebuf, attnbuf);

    gemm_mma<<<MROWS / 64, 256, GEMM_SMEM>>>(attnbuf, wpbuf, proj_b, out, 2);
}

// round 10
// speedup vs baseline: 2.3790x; 1.0577x over previous
#include <cuda_runtime.h>
#include <cuda_bf16.h>
#include <cuda_fp16.h>
#include <cstdint>

// ---------------- problem constants ----------------
#define B_WIN  2048
#define NTOK   49
#define DIMF   256
#define HEADS  8
#define HD     32
#define MROWS  (B_WIN * NTOK)        // 100352
#define QKVCOL 768

#define LOSC   2048.0f               // lo-term pre-scale (keeps fp16 normal)
#define LOINV  4.8828125e-4f         // 1/2048

// ---------------- scratch ----------------
__device__ float g_qkv [MROWS * QKVCOL];
__device__ float g_attn[MROWS * DIMF];
__device__ float g_bias[HEADS * 64 * 56];   // padded [8][64][56]; pads stay 0
__device__ float g_scale[HEADS];
__device__ unsigned char g_wq[48 * 16384];  // fp16 hi/lo chunks
__device__ unsigned char g_wp[16 * 16384];

// ---------------- helpers ----------------
static __device__ __forceinline__ uint32_t s2u(const void* p) {
    uint32_t a;
    asm("{ .reg .u64 t; cvta.to.shared.u64 t, %1; cvt.u32.u64 %0, t; }" : "=r"(a) : "l"(p));
    return a;
}
static __device__ __forceinline__ uint32_t swz(uint32_t byte_in_row, uint32_t row) {
    return (byte_in_row & ~0x7Fu) | ((byte_in_row & 0x7Fu) ^ ((row & 7u) << 4));
}
static __device__ __forceinline__ uint32_t swz64(uint32_t c, uint32_t row) {
    return (c & 0xFu) | (((((c >> 4) ^ ((row >> 1) & 3u))) & 3u) << 4);
}

#define LDSM_X4(r, a)                                                        \
    asm volatile("ldmatrix.sync.aligned.m8n8.x4.shared.b16 {%0,%1,%2,%3}, [%4];" \
        : "=r"((r)[0]), "=r"((r)[1]), "=r"((r)[2]), "=r"((r)[3]) : "r"(a))
#define LDSM_X4T(r, a)                                                       \
    asm volatile("ldmatrix.sync.aligned.m8n8.x4.trans.shared.b16 {%0,%1,%2,%3}, [%4];" \
        : "=r"((r)[0]), "=r"((r)[1]), "=r"((r)[2]), "=r"((r)[3]) : "r"(a))

#define MMA_BF(c, a, b)                                                      \
    asm volatile("mma.sync.aligned.m16n8k16.row.col.f32.bf16.bf16.f32 "      \
        "{%0,%1,%2,%3}, {%4,%5,%6,%7}, {%8,%9}, {%0,%1,%2,%3};"              \
        : "+f"((c)[0]), "+f"((c)[1]), "+f"((c)[2]), "+f"((c)[3])             \
        : "r"((a)[0]), "r"((a)[1]), "r"((a)[2]), "r"((a)[3]),                \
          "r"((b)[0]), "r"((b)[1]))
#define MMA_FH(c, a, b)                                                      \
    asm volatile("mma.sync.aligned.m16n8k16.row.col.f32.f16.f16.f32 "        \
        "{%0,%1,%2,%3}, {%4,%5,%6,%7}, {%8,%9}, {%0,%1,%2,%3};"              \
        : "+f"((c)[0]), "+f"((c)[1]), "+f"((c)[2]), "+f"((c)[3])             \
        : "r"((a)[0]), "r"((a)[1]), "r"((a)[2]), "r"((a)[3]),                \
          "r"((b)[0]), "r"((b)[1]))
#define MMA_HH(c2, a, b)                                                     \
    asm volatile("mma.sync.aligned.m16n8k16.row.col.f16.f16.f16.f16 "        \
        "{%0,%1}, {%2,%3,%4,%5}, {%6,%7}, {%0,%1};"                          \
        : "+r"((c2)[0]), "+r"((c2)[1])                                       \
        : "r"((a)[0]), "r"((a)[1]), "r"((a)[2]), "r"((a)[3]),                \
          "r"((b)[0]), "r"((b)[1]))

#define CP16(d, s) \
    asm volatile("cp.async.cg.shared.global [%0], [%1], 16;" :: "r"(d), "l"(s) : "memory")
#define CP_COMMIT() asm volatile("cp.async.commit_group;" ::: "memory")
#define CP_WAIT(n)  asm volatile("cp.async.wait_group %0;" :: "n"(n) : "memory")

static __device__ __forceinline__ uint32_t pk2(float x, float y) {   // bf16x2
    uint32_t r;
    asm("cvt.rn.bf16x2.f32 %0, %1, %2;" : "=r"(r) : "f"(y), "f"(x));
    return r;
}
static __device__ __forceinline__ uint32_t pk2h(float x, float y) {  // f16x2
    uint32_t r;
    asm("cvt.rn.f16x2.f32 %0, %1, %2;" : "=r"(r) : "f"(y), "f"(x));
    return r;
}
static __device__ __forceinline__ float rbf(float x) {
    return __bfloat162float(__float2bfloat16_rn(x));
}

// =====================================================================
// Kernel 1: CPB-MLP bias table + logit scale
// =====================================================================
__device__ __forceinline__ float cpb_coord(int i) {
    float x = (float)(i - 6) * (8.0f / 6.0f);
    return copysignf(log1pf(fabsf(x)) * 0.4808983469629878f, x);
}

__global__ void cpb_kernel(const float* __restrict__ logit_scale,
                           const float* __restrict__ w1,
                           const float* __restrict__ b1,
                           const float* __restrict__ w2,
                           float* __restrict__ bias_out,
                           float* __restrict__ scale_out)
{
    __shared__ float table[169][HEADS];
    const int tid = threadIdx.x;

    if (tid < HEADS) {
        float ls = logit_scale[tid];
        ls = fminf(ls, logf(100.0f));
        ls = fmaxf(ls, -100.0f);
        scale_out[tid] = expf(ls);
    }
    for (int e = tid; e < 169; e += blockDim.x) {
        const int i = e / 13, j = e % 13;
        const float c0 = cpb_coord(i);
        const float c1 = cpb_coord(j);
        float acc[HEADS];
#pragma unroll
        for (int hh = 0; hh < HEADS; hh++) acc[hh] = 0.0f;
        for (int kk = 0; kk < 512; kk++) {
            float hpre = c0 * w1[kk] + c1 * w1[512 + kk] + b1[kk];
            float g = 0.5f * hpre * (1.0f + erff(hpre * 0.7071067811865475f));
#pragma unroll
            for (int hh = 0; hh < HEADS; hh++) acc[hh] += g * w2[kk * 8 + hh];
        }
#pragma unroll
        for (int hh = 0; hh < HEADS; hh++) table[e][hh] = acc[hh];
    }
    __syncthreads();

    for (int idx = tid; idx < HEADS * NTOK * NTOK; idx += blockDim.x) {
        const int hh  = idx / (NTOK * NTOK);
        const int rem = idx % (NTOK * NTOK);
        const int r   = rem / NTOK;
        const int c   = rem % NTOK;
        const int dh  = (r / 7) - (c / 7) + 6;
        const int dw  = (r % 7) - (c % 7) + 6;
        const float v = table[dh * 13 + dw][hh];
        bias_out[hh * 3584 + r * 56 + c] = 16.0f / (1.0f + __expf(-v));
    }
}

// =====================================================================
// Kernel 1b: split weights fp32 -> hi/lo fp16 chunks (lo pre-scaled x2048)
// =====================================================================
__global__ void wsplit_kernel(const float* __restrict__ wq, const float* __restrict__ wp,
                              unsigned char* __restrict__ oq, unsigned char* __restrict__ op)
{
    const int stride = gridDim.x * blockDim.x;
    const int t0 = blockIdx.x * blockDim.x + threadIdx.x;
    for (int idx = t0; idx < 256 * QKVCOL; idx += stride) {
        const int k = idx / QKVCOL, n = idx % QKVCOL;
        float f = wq[idx];
        __half h = __float2half_rn(f);
        __half l = __float2half_rn((f - __half2float(h)) * LOSC);
        const uint32_t off = (uint32_t)((n >> 7) * 8 + (k >> 5)) * 16384u
                           + (uint32_t)(k & 31) * 256u + swz((uint32_t)(n & 127) * 2u, (uint32_t)k);
        *(__half*)(oq + off)        = h;
        *(__half*)(oq + off + 8192) = l;
    }
    for (int idx = t0; idx < 256 * 256; idx += stride) {
        const int k = idx >> 8, n = idx & 255;
        float f = wp[idx];
        __half h = __float2half_rn(f);
        __half l = __float2half_rn((f - __half2float(h)) * LOSC);
        const uint32_t off = (uint32_t)((n >> 7) * 8 + (k >> 5)) * 16384u
                           + (uint32_t)(k & 31) * 256u + swz((uint32_t)(n & 127) * 2u, (uint32_t)k);
        *(__half*)(op + off)        = h;
        *(__half*)(op + off + 8192) = l;
    }
}

// =====================================================================
// Kernel 2/4: fp16 GEMM, single-sync 4-stage pipeline.
//   NPROD=2: A*Whi (f32 acc) + A*Wlo' (f16 acc).  NPROD=1: A*Whi only
//   (final proj layer — W rounding unamplified), copies only hi 8KB.
// =====================================================================
#define SMW_OFF 32768
#define GEMM_SMEM (32768 + 4 * 16384)

template<int NPROD>
__global__ __launch_bounds__(256, 2)
void gemm_mma(const float* __restrict__ A, const unsigned char* __restrict__ Wp,
              const float* __restrict__ bias, float* __restrict__ C, int NT)
{
    extern __shared__ char smem[];
    const uint32_t sb = s2u(smem);
    const int tid  = threadIdx.x;
    const int lane = tid & 31;
    const int w    = tid >> 5;
    const int row0 = blockIdx.x * 64;
    const int Ncols = NT * 128;
    const int NCP = (NPROD == 2) ? 4 : 2;    // 16KB or 8KB per chunk copy

    // A: fp32 -> fp16, 64 rows x 512B, swizzled
    for (int i = tid; i < 4096; i += 256) {
        const int r  = i >> 6;
        const int c4 = (i & 63) << 2;
        float4 a = *(const float4*)(A + (size_t)(row0 + r) * 256 + c4);
        const uint32_t off = (uint32_t)r * 512u + swz((uint32_t)c4 * 2u, (uint32_t)r);
        uint2 hu; hu.x = pk2h(a.x, a.y); hu.y = pk2h(a.z, a.w);
        *(uint2*)(smem + off) = hu;
    }

    const int wm = w & 1;        // m0 = wm*32
    const int wn = w >> 1;       // n0 = wn*32

    const int NCH = NT * 8;

    // prefetch chunks 0,1,2 into stages 0,1,2
#pragma unroll
    for (int pf = 0; pf < 3; pf++) {
        const unsigned char* src = Wp + (size_t)pf * 16384;
        const uint32_t dst = sb + SMW_OFF + (uint32_t)pf * 16384u;
#pragma unroll
        for (int j = 0; j < NCP; j++)
            CP16(dst + (uint32_t)(tid * 16 + j * 4096), src + tid * 16 + j * 4096);
        CP_COMMIT();
    }
    __syncthreads();   // A-tile visible to all warps

    float    acc [2][4][4];
    uint32_t acch[2][4][2];
    int nt = 0;
#pragma unroll
    for (int mf = 0; mf < 2; mf++)
#pragma unroll
        for (int nf = 0; nf < 4; nf++) {
#pragma unroll
            for (int q = 0; q < 4; q++) acc[mf][nf][q] = 0.0f;
            acch[mf][nf][0] = 0u; acch[mf][nf][1] = 0u;
        }

    for (int gc = 0; gc < NCH; gc++) {
        CP_WAIT(2);          // chunk gc landed (per-thread)
        __syncthreads();     // all warps done with chunk gc-1; data of gc visible

        if (gc + 3 < NCH) {
            const unsigned char* src = Wp + (size_t)(gc + 3) * 16384;
            const uint32_t dst = sb + SMW_OFF + (uint32_t)(((gc + 3) & 3) * 16384);
#pragma unroll
            for (int j = 0; j < NCP; j++)
                CP16(dst + (uint32_t)(tid * 16 + j * 4096), src + tid * 16 + j * 4096);
        }
        CP_COMMIT();

        const uint32_t st = sb + SMW_OFF + (uint32_t)((gc & 3) * 16384);
        const int kc = gc & 7;

#pragma unroll
        for (int ks = 0; ks < 2; ks++) {
            uint32_t ah[2][4];
            const int arow = wm * 32 + ((lane >> 3) & 1) * 8 + (lane & 7);
            const int kg   = kc * 32 + ks * 16 + ((lane >> 4) << 3);
#pragma unroll
            for (int mf = 0; mf < 2; mf++) {
                const uint32_t r = (uint32_t)(arow + mf * 16);
                LDSM_X4(ah[mf], sb + r * 512u + swz((uint32_t)kg * 2u, r));
            }
            uint32_t bh[2][4], bl[2][4];
            const uint32_t krow = (uint32_t)(ks * 16 + ((lane >> 3) & 1) * 8 + (lane & 7));
#pragma unroll
            for (int nf2 = 0; nf2 < 2; nf2++) {
                const uint32_t ncol = (uint32_t)(wn * 32 + nf2 * 16 + (lane >> 4) * 8);
                const uint32_t addr = st + krow * 256u + swz(ncol * 2u, krow);
                LDSM_X4T(bh[nf2], addr);
                if (NPROD == 2) LDSM_X4T(bl[nf2], addr + 8192u);
            }
#pragma unroll
            for (int mf = 0; mf < 2; mf++)
#pragma unroll
                for (int nf = 0; nf < 4; nf++) {
                    uint32_t* bph = &bh[nf >> 1][(nf & 1) * 2];
                    MMA_FH(acc[mf][nf], ah[mf], bph);     // A*hi  (f32 accum)
                    if (NPROD == 2) {
                        uint32_t* bpl = &bl[nf >> 1][(nf & 1) * 2];
                        MMA_HH(acch[mf][nf], ah[mf], bpl);    // A*lo' (f16 accum)
                    }
                }
        }

        if (kc == 7) {
            const int g = lane >> 2, t = lane & 3;
#pragma unroll
            for (int nf = 0; nf < 4; nf++) {
                const int col = nt * 128 + wn * 32 + nf * 8 + t * 2;
                const float2 bv = *(const float2*)(bias + col);
#pragma unroll
                for (int mf = 0; mf < 2; mf++) {
                    const int row = row0 + wm * 32 + mf * 16 + g;
                    float lo0 = 0.f, lo1 = 0.f, lo2 = 0.f, lo3 = 0.f;
                    if (NPROD == 2) {
                        float2 c01 = __half22float2(*(const __half2*)&acch[mf][nf][0]);
                        float2 c23 = __half22float2(*(const __half2*)&acch[mf][nf][1]);
                        lo0 = c01.x * LOINV; lo1 = c01.y * LOINV;
                        lo2 = c23.x * LOINV; lo3 = c23.y * LOINV;
                    }
                    float2 v0 = make_float2(acc[mf][nf][0] + lo0 + bv.x,
                                            acc[mf][nf][1] + lo1 + bv.y);
                    float2 v1 = make_float2(acc[mf][nf][2] + lo2 + bv.x,
                                            acc[mf][nf][3] + lo3 + bv.y);
                    *(float2*)(C + (size_t)row * Ncols + col)       = v0;
                    *(float2*)(C + (size_t)(row + 8) * Ncols + col) = v1;
                }
            }
            nt++;
#pragma unroll
            for (int mf = 0; mf < 2; mf++)
#pragma unroll
                for (int nf = 0; nf < 4; nf++) {
#pragma unroll
                    for (int q = 0; q < 4; q++) acc[mf][nf][q] = 0.0f;
                    acch[mf][nf][0] = 0u; acch[mf][nf][1] = 0u;
                }
        }
    }
}

// =====================================================================
// Kernel 3: tensor-core window attention — 4 heads/CTA, grid (2048, 2),
//   256 threads (2 warps/head), 2 CTAs/SM.
//   Loader: 4-thread teams, UNIFORM 4-round loop (shuffles never diverge).
// =====================================================================
#define AHEAD 21504
#define AQH 0
#define AQL 3584
#define AKH 7168
#define AKL 10752
#define AVH 14336
#define AVL 17920
#define ATTN_SMEM (4 * AHEAD + 512)

__global__ __launch_bounds__(256, 2)
void attn_tc(const float* __restrict__ qkv,
             const float* __restrict__ bias,
             const float* __restrict__ scale,
             float* __restrict__ attn_out)
{
    extern __shared__ char smem[];
    const uint32_t sb = s2u(smem);
    const int b    = blockIdx.x;
    const int hg   = blockIdx.y;
    const int tid  = threadIdx.x;
    const int lane = tid & 31;
    const int wrp  = tid >> 5;

    {
        int i = tid;
        if (i < 224) {
            const int slot = i / 56, rem = i % 56;
            const int half = rem / 28, rr = 49 + (rem % 28) / 4, c16 = (rem & 3) * 16;
            *(uint4*)(smem + slot * AHEAD + (half ? AVL : AVH) + rr * 64 + c16) =
                make_uint4(0, 0, 0, 0);
        } else if (i < 256) {
            *(uint4*)(smem + 4 * AHEAD + (i - 224) * 16) = make_uint4(0, 0, 0, 0);
        }
    }

    // loader: 4-thread teams, each thread owns 8 dims; uniform round count.
    {
        const float* wb = qkv + (size_t)b * NTOK * QKVCOL;
        const int team = tid >> 2, l4 = tid & 3;
#pragma unroll
        for (int it0 = 0; it0 < 256; it0 += 64) {
            const int it  = it0 + team;
            const bool act = (it < 196);            // whole 4-thread team uniform
            const int tok  = act ? (it >> 2) : 0;
            const int slot = it & 3;
            const int hh   = hg * 4 + (act ? slot : 0);
            const float* rowp = wb + (size_t)tok * QKVCOL + hh * HD + l4 * 8;

            float4 q0, q1, k0, k1, v0, v1;
            if (act) {
                q0 = *(const float4*)(rowp);
                q1 = *(const float4*)(rowp + 4);
                k0 = *(const float4*)(rowp + 256);
                k1 = *(const float4*)(rowp + 260);
                v0 = *(const float4*)(rowp + 512);
                v1 = *(const float4*)(rowp + 516);
            } else {
                q0 = q1 = k0 = k1 = v0 = v1 = make_float4(0.f, 0.f, 0.f, 0.f);
            }

            float qss = q0.x*q0.x + q0.y*q0.y + q0.z*q0.z + q0.w*q0.w
                      + q1.x*q1.x + q1.y*q1.y + q1.z*q1.z + q1.w*q1.w;
            float kss = k0.x*k0.x + k0.y*k0.y + k0.z*k0.z + k0.w*k0.w
                      + k1.x*k1.x + k1.y*k1.y + k1.z*k1.z + k1.w*k1.w;
            // all 32 lanes participate every round; o=1,2 mixes only within team
#pragma unroll
            for (int o = 1; o < 4; o <<= 1) {
                qss += __shfl_xor_sync(0xffffffffu, qss, o);
                kss += __shfl_xor_sync(0xffffffffu, kss, o);
            }
            if (act) {
                const float qr = rsqrtf(qss) * __ldg(scale + hh);
                const float kr = rsqrtf(kss);
                q0.x *= qr; q0.y *= qr; q0.z *= qr; q0.w *= qr;
                q1.x *= qr; q1.y *= qr; q1.z *= qr; q1.w *= qr;
                k0.x *= kr; k0.y *= kr; k0.z *= kr; k0.w *= kr;
                k1.x *= kr; k1.y *= kr; k1.z *= kr; k1.w *= kr;

                const uint32_t base = (uint32_t)slot * AHEAD + (uint32_t)tok * 64u
                                    + (uint32_t)((l4 ^ ((tok >> 1) & 3)) << 4);
                {
                    float h0 = rbf(q0.x), h1 = rbf(q0.y), h2 = rbf(q0.z), h3 = rbf(q0.w);
                    float h4 = rbf(q1.x), h5 = rbf(q1.y), h6 = rbf(q1.z), h7 = rbf(q1.w);
                    uint4 hu = make_uint4(pk2(h0,h1), pk2(h2,h3), pk2(h4,h5), pk2(h6,h7));
                    uint4 lu = make_uint4(pk2(q0.x-h0,q0.y-h1), pk2(q0.z-h2,q0.w-h3),
                                          pk2(q1.x-h4,q1.y-h5), pk2(q1.z-h6,q1.w-h7));
                    *(uint4*)(smem + AQH + base) = hu;
                    *(uint4*)(smem + AQL + base) = lu;
                }
                {
                    float h0 = rbf(k0.x), h1 = rbf(k0.y), h2 = rbf(k0.z), h3 = rbf(k0.w);
                    float h4 = rbf(k1.x), h5 = rbf(k1.y), h6 = rbf(k1.z), h7 = rbf(k1.w);
                    uint4 hu = make_uint4(pk2(h0,h1), pk2(h2,h3), pk2(h4,h5), pk2(h6,h7));
                    uint4 lu = make_uint4(pk2(k0.x-h0,k0.y-h1), pk2(k0.z-h2,k0.w-h3),
                                          pk2(k1.x-h4,k1.y-h5), pk2(k1.z-h6,k1.w-h7));
                    *(uint4*)(smem + AKH + base) = hu;
                    *(uint4*)(smem + AKL + base) = lu;
                }
                {
                    float h0 = rbf(v0.x), h1 = rbf(v0.y), h2 = rbf(v0.z), h3 = rbf(v0.w);
                    float h4 = rbf(v1.x), h5 = rbf(v1.y), h6 = rbf(v1.z), h7 = rbf(v1.w);
                    uint4 hu = make_uint4(pk2(h0,h1), pk2(h2,h3), pk2(h4,h5), pk2(h6,h7));
                    uint4 lu = make_uint4(pk2(v0.x-h0,v0.y-h1), pk2(v0.z-h2,v0.w-h3),
                                          pk2(v1.x-h4,v1.y-h5), pk2(v1.z-h6,v1.w-h7));
                    *(uint4*)(smem + AVH + base) = hu;
                    *(uint4*)(smem + AVL + base) = lu;
                }
            }
        }
    }
    __syncthreads();

    const int slot = wrp >> 1;
    const int h    = hg * 4 + slot;
    const int m0base = (wrp & 1) * 32;
    const uint32_t hb = sb + (uint32_t)slot * AHEAD;
    const float* bslab = bias + h * 3584;
    float* obase = attn_out + (size_t)b * NTOK * DIMF + h * HD;
    const int qrow = lane >> 2;
    const int qc   = (lane & 3) * 2;

#pragma unroll
    for (int mc = 0; mc < 2; mc++) {
        const int m0 = m0base + mc * 16;
        const int r0 = m0 + qrow;

        // init S with bias (pads read 0); loads hide under QK MMAs
        float S[7][4];
#pragma unroll
        for (int nf = 0; nf < 7; nf++) {
            const int c0 = nf * 8 + qc;
            const float2 b0 = *(const float2*)(bslab + r0 * 56 + c0);
            const float2 b1 = *(const float2*)(bslab + (r0 + 8) * 56 + c0);
            S[nf][0] = b0.x; S[nf][1] = b0.y;
            S[nf][2] = b1.x; S[nf][3] = b1.y;
        }

#pragma unroll
        for (int ks = 0; ks < 2; ks++) {
            uint32_t ah[4], al[4];
            {
                const uint32_t r = (uint32_t)(m0 + ((lane >> 3) & 1) * 8 + (lane & 7));
                const uint32_t cb = (uint32_t)(ks * 32 + (lane >> 4) * 16);
                const uint32_t ad = hb + AQH + r * 64u + swz64(cb, r);
                LDSM_X4(ah, ad);
                LDSM_X4(al, ad + (AQL - AQH));
            }
#pragma unroll
            for (int ng = 0; ng < 4; ng++) {
                uint32_t bh[4], bl[4];
                const uint32_t r = (uint32_t)(ng * 16 + (lane & 7) + ((lane >> 4) << 3));
                const uint32_t cb = (uint32_t)(ks * 32 + ((lane >> 3) & 1) * 16);
                const uint32_t ad = hb + AKH + r * 64u + swz64(cb, r);
                LDSM_X4(bh, ad);
                LDSM_X4(bl, ad + (AKL - AKH));
                MMA_BF(S[2 * ng], ah, bh);
                MMA_BF(S[2 * ng], ah, bl);
                MMA_BF(S[2 * ng], al, bh);
                if (ng < 3) {
                    MMA_BF(S[2 * ng + 1], ah, bh + 2);
                    MMA_BF(S[2 * ng + 1], ah, bl + 2);
                    MMA_BF(S[2 * ng + 1], al, bh + 2);
                }
            }
        }

        // mask + softmax
        {
            float mx0 = -1e30f, mx1 = -1e30f;
#pragma unroll
            for (int nf = 0; nf < 7; nf++) {
                const int c0 = nf * 8 + qc;
                S[nf][0] = (c0     < 49) ? S[nf][0] : -1e30f;
                S[nf][1] = (c0 + 1 < 49) ? S[nf][1] : -1e30f;
                S[nf][2] = (c0     < 49) ? S[nf][2] : -1e30f;
                S[nf][3] = (c0 + 1 < 49) ? S[nf][3] : -1e30f;
                mx0 = fmaxf(mx0, fmaxf(S[nf][0], S[nf][1]));
                mx1 = fmaxf(mx1, fmaxf(S[nf][2], S[nf][3]));
            }
#pragma unroll
            for (int o = 1; o < 4; o <<= 1) {
                mx0 = fmaxf(mx0, __shfl_xor_sync(0xffffffffu, mx0, o));
                mx1 = fmaxf(mx1, __shfl_xor_sync(0xffffffffu, mx1, o));
            }
            float rs0 = 0.0f, rs1 = 0.0f;
#pragma unroll
            for (int nf = 0; nf < 7; nf++) {
                float p0 = __expf(S[nf][0] - mx0);
                float p1 = __expf(S[nf][1] - mx0);
                float p2 = __expf(S[nf][2] - mx1);
                float p3 = __expf(S[nf][3] - mx1);
                S[nf][0] = p0; S[nf][1] = p1; S[nf][2] = p2; S[nf][3] = p3;
                rs0 += p0 + p1;  rs1 += p2 + p3;
            }
#pragma unroll
            for (int o = 1; o < 4; o <<= 1) {
                rs0 += __shfl_xor_sync(0xffffffffu, rs0, o);
                rs1 += __shfl_xor_sync(0xffffffffu, rs1, o);
            }
            const float iv0 = 1.0f / rs0, iv1 = 1.0f / rs1;
#pragma unroll
            for (int nf = 0; nf < 7; nf++) {
                S[nf][0] *= iv0; S[nf][1] *= iv0;
                S[nf][2] *= iv1; S[nf][3] *= iv1;
            }
        }

        float O[4][4];
#pragma unroll
        for (int n = 0; n < 4; n++)
#pragma unroll
            for (int q = 0; q < 4; q++) O[n][q] = 0.0f;

#pragma unroll
        for (int kt = 0; kt < 4; kt++) {
            uint32_t ph[4], pl[4];
            {
                float pa0 = S[2*kt][0], pa1 = S[2*kt][1], pa2 = S[2*kt][2], pa3 = S[2*kt][3];
                float pb0 = 0.f, pb1 = 0.f, pb2 = 0.f, pb3 = 0.f;
                if (kt < 3) {
                    pb0 = S[2*kt+1][0]; pb1 = S[2*kt+1][1];
                    pb2 = S[2*kt+1][2]; pb3 = S[2*kt+1][3];
                }
                const float ha0 = rbf(pa0), ha1 = rbf(pa1), ha2 = rbf(pa2), ha3 = rbf(pa3);
                const float hb0 = rbf(pb0), hb1 = rbf(pb1), hb2 = rbf(pb2), hb3 = rbf(pb3);
                ph[0] = pk2(ha0, ha1);  ph[1] = pk2(ha2, ha3);
                ph[2] = pk2(hb0, hb1);  ph[3] = pk2(hb2, hb3);
                pl[0] = pk2(pa0 - ha0, pa1 - ha1);
                pl[1] = pk2(pa2 - ha2, pa3 - ha3);
                pl[2] = pk2(pb0 - hb0, pb1 - hb1);
                pl[3] = pk2(pb2 - hb2, pb3 - hb3);
            }
#pragma unroll
            for (int vg = 0; vg < 2; vg++) {
                uint32_t vh[4], vl[4];
                const uint32_t kr = (uint32_t)(kt * 16 + ((lane >> 3) & 1) * 8 + (lane & 7));
                const uint32_t cb = (uint32_t)(vg * 32 + (lane >> 4) * 16);
                const uint32_t ad = hb + AVH + kr * 64u + swz64(cb, kr);
                LDSM_X4T(vh, ad);
                LDSM_X4T(vl, ad + (AVL - AVH));
#pragma unroll
                for (int nn = 0; nn < 2; nn++) {
                    float* oo = O[vg * 2 + nn];
                    MMA_BF(oo, ph, vh + nn * 2);
                    MMA_BF(oo, ph, vl + nn * 2);
                    MMA_BF(oo, pl, vh + nn * 2);
                }
            }
        }

        {
#pragma unroll
            for (int nf = 0; nf < 4; nf++) {
                const int c = nf * 8 + qc;
                if (r0 < NTOK)
                    *(float2*)(obase + (size_t)r0 * DIMF + c) = make_float2(O[nf][0], O[nf][1]);
                if (r0 + 8 < NTOK)
                    *(float2*)(obase + (size_t)(r0 + 8) * DIMF + c) = make_float2(O[nf][2], O[nf][3]);
            }
        }
    }
}

// =====================================================================
// launch
// =====================================================================
extern "C" void kernel_launch(void* const* d_in, const int* in_sizes, int n_in,
                              void* d_out, int out_size)
{
    const float* x           = (const float*)d_in[0];
    const float* qkv_w       = (const float*)d_in[1];
    const float* qkv_b       = (const float*)d_in[2];
    const float* proj_w      = (const float*)d_in[3];
    const float* proj_b      = (const float*)d_in[4];
    const float* logit_scale = (const float*)d_in[5];
    const float* cpb_w1      = (const float*)d_in[6];
    const float* cpb_b1      = (const float*)d_in[7];
    const float* cpb_w2      = (const float*)d_in[8];
    float* out = (float*)d_out;

    float *qkvbuf, *attnbuf, *biasbuf, *scalebuf;
    unsigned char *wqbuf, *wpbuf;
    cudaGetSymbolAddress((void**)&qkvbuf,   g_qkv);
    cudaGetSymbolAddress((void**)&attnbuf,  g_attn);
    cudaGetSymbolAddress((void**)&biasbuf,  g_bias);
    cudaGetSymbolAddress((void**)&scalebuf, g_scale);
    cudaGetSymbolAddress((void**)&wqbuf,    g_wq);
    cudaGetSymbolAddress((void**)&wpbuf,    g_wp);

    cudaFuncSetAttribute(gemm_mma<2>, cudaFuncAttributeMaxDynamicSharedMemorySize, GEMM_SMEM);
    cudaFuncSetAttribute(gemm_mma<1>, cudaFuncAttributeMaxDynamicSharedMemorySize, GEMM_SMEM);
    cudaFuncSetAttribute(attn_tc,     cudaFuncAttributeMaxDynamicSharedMemorySize, ATTN_SMEM);

    cpb_kernel<<<1, 256>>>(logit_scale, cpb_w1, cpb_b1, cpb_w2, biasbuf, scalebuf);
    wsplit_kernel<<<128, 256>>>(qkv_w, proj_w, wqbuf, wpbuf);

    gemm_mma<2><<<MROWS / 64, 256, GEMM_SMEM>>>(x, wqbuf, qkv_b, qkvbuf, 6);

    attn_tc<<<dim3(B_WIN, 2), 256, ATTN_SMEM>>>(qkvbuf, biasbuf, scalebuf, attnbuf);

    gemm_mma<1><<<MROWS / 64, 256, GEMM_SMEM>>>(attnbuf, wpbuf, proj_b, out, 2);
}

// round 11
// speedup vs baseline: 2.3794x; 1.0001x over previous
#include <cuda_runtime.h>
#include <cuda_bf16.h>
#include <cuda_fp16.h>
#include <cstdint>

// ---------------- problem constants ----------------
#define B_WIN  2048
#define NTOK   49
#define DIMF   256
#define HEADS  8
#define HD     32
#define MROWS  (B_WIN * NTOK)        // 100352
#define QKVCOL 768

#define LOSC   2048.0f               // lo-term pre-scale (keeps fp16 normal)
#define LOINV  4.8828125e-4f         // 1/2048

// ---------------- scratch ----------------
__device__ float g_qkv [MROWS * QKVCOL];
__device__ float g_attn[MROWS * DIMF];      // used as __half buffer (half of it)
__device__ float g_bias[HEADS * 64 * 56];   // padded [8][64][56]; pads stay 0
__device__ float g_scale[HEADS];
__device__ unsigned char g_wq[48 * 16384];  // fp16 hi/lo chunks
__device__ unsigned char g_wp[16 * 16384];

// ---------------- helpers ----------------
static __device__ __forceinline__ uint32_t s2u(const void* p) {
    uint32_t a;
    asm("{ .reg .u64 t; cvta.to.shared.u64 t, %1; cvt.u32.u64 %0, t; }" : "=r"(a) : "l"(p));
    return a;
}
static __device__ __forceinline__ uint32_t swz(uint32_t byte_in_row, uint32_t row) {
    return (byte_in_row & ~0x7Fu) | ((byte_in_row & 0x7Fu) ^ ((row & 7u) << 4));
}
static __device__ __forceinline__ uint32_t swz64(uint32_t c, uint32_t row) {
    return (c & 0xFu) | (((((c >> 4) ^ ((row >> 1) & 3u))) & 3u) << 4);
}

#define LDSM_X4(r, a)                                                        \
    asm volatile("ldmatrix.sync.aligned.m8n8.x4.shared.b16 {%0,%1,%2,%3}, [%4];" \
        : "=r"((r)[0]), "=r"((r)[1]), "=r"((r)[2]), "=r"((r)[3]) : "r"(a))
#define LDSM_X4T(r, a)                                                       \
    asm volatile("ldmatrix.sync.aligned.m8n8.x4.trans.shared.b16 {%0,%1,%2,%3}, [%4];" \
        : "=r"((r)[0]), "=r"((r)[1]), "=r"((r)[2]), "=r"((r)[3]) : "r"(a))

#define MMA_BF(c, a, b)                                                      \
    asm volatile("mma.sync.aligned.m16n8k16.row.col.f32.bf16.bf16.f32 "      \
        "{%0,%1,%2,%3}, {%4,%5,%6,%7}, {%8,%9}, {%0,%1,%2,%3};"              \
        : "+f"((c)[0]), "+f"((c)[1]), "+f"((c)[2]), "+f"((c)[3])             \
        : "r"((a)[0]), "r"((a)[1]), "r"((a)[2]), "r"((a)[3]),                \
          "r"((b)[0]), "r"((b)[1]))
#define MMA_FH(c, a, b)                                                      \
    asm volatile("mma.sync.aligned.m16n8k16.row.col.f32.f16.f16.f32 "        \
        "{%0,%1,%2,%3}, {%4,%5,%6,%7}, {%8,%9}, {%0,%1,%2,%3};"              \
        : "+f"((c)[0]), "+f"((c)[1]), "+f"((c)[2]), "+f"((c)[3])             \
        : "r"((a)[0]), "r"((a)[1]), "r"((a)[2]), "r"((a)[3]),                \
          "r"((b)[0]), "r"((b)[1]))
#define MMA_HH(c2, a, b)                                                     \
    asm volatile("mma.sync.aligned.m16n8k16.row.col.f16.f16.f16.f16 "        \
        "{%0,%1}, {%2,%3,%4,%5}, {%6,%7}, {%0,%1};"                          \
        : "+r"((c2)[0]), "+r"((c2)[1])                                       \
        : "r"((a)[0]), "r"((a)[1]), "r"((a)[2]), "r"((a)[3]),                \
          "r"((b)[0]), "r"((b)[1]))

#define CP16(d, s) \
    asm volatile("cp.async.cg.shared.global [%0], [%1], 16;" :: "r"(d), "l"(s) : "memory")
#define CP_COMMIT() asm volatile("cp.async.commit_group;" ::: "memory")
#define CP_WAIT(n)  asm volatile("cp.async.wait_group %0;" :: "n"(n) : "memory")

static __device__ __forceinline__ uint32_t pk2(float x, float y) {   // bf16x2
    uint32_t r;
    asm("cvt.rn.bf16x2.f32 %0, %1, %2;" : "=r"(r) : "f"(y), "f"(x));
    return r;
}
static __device__ __forceinline__ uint32_t pk2h(float x, float y) {  // f16x2
    uint32_t r;
    asm("cvt.rn.f16x2.f32 %0, %1, %2;" : "=r"(r) : "f"(y), "f"(x));
    return r;
}
static __device__ __forceinline__ float rbf(float x) {
    return __bfloat162float(__float2bfloat16_rn(x));
}

// =====================================================================
// Kernel 1: CPB-MLP bias table + logit scale
// =====================================================================
__device__ __forceinline__ float cpb_coord(int i) {
    float x = (float)(i - 6) * (8.0f / 6.0f);
    return copysignf(log1pf(fabsf(x)) * 0.4808983469629878f, x);
}

__global__ void cpb_kernel(const float* __restrict__ logit_scale,
                           const float* __restrict__ w1,
                           const float* __restrict__ b1,
                           const float* __restrict__ w2,
                           float* __restrict__ bias_out,
                           float* __restrict__ scale_out)
{
    __shared__ float table[169][HEADS];
    const int tid = threadIdx.x;

    if (tid < HEADS) {
        float ls = logit_scale[tid];
        ls = fminf(ls, logf(100.0f));
        ls = fmaxf(ls, -100.0f);
        scale_out[tid] = expf(ls);
    }
    for (int e = tid; e < 169; e += blockDim.x) {
        const int i = e / 13, j = e % 13;
        const float c0 = cpb_coord(i);
        const float c1 = cpb_coord(j);
        float acc[HEADS];
#pragma unroll
        for (int hh = 0; hh < HEADS; hh++) acc[hh] = 0.0f;
        for (int kk = 0; kk < 512; kk++) {
            float hpre = c0 * w1[kk] + c1 * w1[512 + kk] + b1[kk];
            float g = 0.5f * hpre * (1.0f + erff(hpre * 0.7071067811865475f));
#pragma unroll
            for (int hh = 0; hh < HEADS; hh++) acc[hh] += g * w2[kk * 8 + hh];
        }
#pragma unroll
        for (int hh = 0; hh < HEADS; hh++) table[e][hh] = acc[hh];
    }
    __syncthreads();

    for (int idx = tid; idx < HEADS * NTOK * NTOK; idx += blockDim.x) {
        const int hh  = idx / (NTOK * NTOK);
        const int rem = idx % (NTOK * NTOK);
        const int r   = rem / NTOK;
        const int c   = rem % NTOK;
        const int dh  = (r / 7) - (c / 7) + 6;
        const int dw  = (r % 7) - (c % 7) + 6;
        const float v = table[dh * 13 + dw][hh];
        bias_out[hh * 3584 + r * 56 + c] = 16.0f / (1.0f + __expf(-v));
    }
}

// =====================================================================
// Kernel 1b: split weights fp32 -> hi/lo fp16 chunks (lo pre-scaled x2048)
// =====================================================================
__global__ void wsplit_kernel(const float* __restrict__ wq, const float* __restrict__ wp,
                              unsigned char* __restrict__ oq, unsigned char* __restrict__ op)
{
    const int stride = gridDim.x * blockDim.x;
    const int t0 = blockIdx.x * blockDim.x + threadIdx.x;
    for (int idx = t0; idx < 256 * QKVCOL; idx += stride) {
        const int k = idx / QKVCOL, n = idx % QKVCOL;
        float f = wq[idx];
        __half h = __float2half_rn(f);
        __half l = __float2half_rn((f - __half2float(h)) * LOSC);
        const uint32_t off = (uint32_t)((n >> 7) * 8 + (k >> 5)) * 16384u
                           + (uint32_t)(k & 31) * 256u + swz((uint32_t)(n & 127) * 2u, (uint32_t)k);
        *(__half*)(oq + off)        = h;
        *(__half*)(oq + off + 8192) = l;
    }
    for (int idx = t0; idx < 256 * 256; idx += stride) {
        const int k = idx >> 8, n = idx & 255;
        float f = wp[idx];
        __half h = __float2half_rn(f);
        __half l = __float2half_rn((f - __half2float(h)) * LOSC);
        const uint32_t off = (uint32_t)((n >> 7) * 8 + (k >> 5)) * 16384u
                           + (uint32_t)(k & 31) * 256u + swz((uint32_t)(n & 127) * 2u, (uint32_t)k);
        *(__half*)(op + off)        = h;
        *(__half*)(op + off + 8192) = l;
    }
}

// =====================================================================
// Kernel 2/4: fp16 GEMM, single-sync 4-stage pipeline.
//   Chunks gc < split_until: 2-product (A*Whi f32-acc + A*Wlo' f16-acc).
//   Chunks gc >= split_until: 1-product (A*Whi only), copy only hi 8KB.
//   AHALF: A input already fp16 (raw copy into swizzled smem).
// =====================================================================
#define SMW_OFF 32768
#define GEMM_SMEM (32768 + 4 * 16384)

template<bool AHALF>
__global__ __launch_bounds__(256, 2)
void gemm_mma(const void* __restrict__ Ain, const unsigned char* __restrict__ Wp,
              const float* __restrict__ bias, float* __restrict__ C,
              int NT, int split_until)
{
    extern __shared__ char smem[];
    const uint32_t sb = s2u(smem);
    const int tid  = threadIdx.x;
    const int lane = tid & 31;
    const int w    = tid >> 5;
    const int row0 = blockIdx.x * 64;
    const int Ncols = NT * 128;

    // A into swizzled smem (64 rows x 512B)
    if (AHALF) {
        const __half* A16 = (const __half*)Ain;
        for (int i = tid; i < 2048; i += 256) {
            const int r  = i >> 5;
            const int c8 = (i & 31) << 3;
            uint4 v = *(const uint4*)(A16 + (size_t)(row0 + r) * 256 + c8);
            const uint32_t off = (uint32_t)r * 512u + swz((uint32_t)c8 * 2u, (uint32_t)r);
            *(uint4*)(smem + off) = v;
        }
    } else {
        const float* A = (const float*)Ain;
        for (int i = tid; i < 4096; i += 256) {
            const int r  = i >> 6;
            const int c4 = (i & 63) << 2;
            float4 a = *(const float4*)(A + (size_t)(row0 + r) * 256 + c4);
            const uint32_t off = (uint32_t)r * 512u + swz((uint32_t)c4 * 2u, (uint32_t)r);
            uint2 hu; hu.x = pk2h(a.x, a.y); hu.y = pk2h(a.z, a.w);
            *(uint2*)(smem + off) = hu;
        }
    }

    const int wm = w & 1;        // m0 = wm*32
    const int wn = w >> 1;       // n0 = wn*32

    const int NCH = NT * 8;

    // prefetch chunks 0,1,2 into stages 0,1,2
#pragma unroll
    for (int pf = 0; pf < 3; pf++) {
        const unsigned char* src = Wp + (size_t)pf * 16384;
        const uint32_t dst = sb + SMW_OFF + (uint32_t)pf * 16384u;
        const int ncp = (pf < split_until) ? 4 : 2;
        for (int j = 0; j < ncp; j++)
            CP16(dst + (uint32_t)(tid * 16 + j * 4096), src + tid * 16 + j * 4096);
        CP_COMMIT();
    }
    __syncthreads();   // A-tile visible to all warps

    float    acc [2][4][4];
    uint32_t acch[2][4][2];
    int nt = 0;
#pragma unroll
    for (int mf = 0; mf < 2; mf++)
#pragma unroll
        for (int nf = 0; nf < 4; nf++) {
#pragma unroll
            for (int q = 0; q < 4; q++) acc[mf][nf][q] = 0.0f;
            acch[mf][nf][0] = 0u; acch[mf][nf][1] = 0u;
        }

    for (int gc = 0; gc < NCH; gc++) {
        CP_WAIT(2);          // chunk gc landed (per-thread)
        __syncthreads();     // all warps done with chunk gc-1; data of gc visible

        if (gc + 3 < NCH) {
            const unsigned char* src = Wp + (size_t)(gc + 3) * 16384;
            const uint32_t dst = sb + SMW_OFF + (uint32_t)(((gc + 3) & 3) * 16384);
            const int ncp = (gc + 3 < split_until) ? 4 : 2;
            for (int j = 0; j < ncp; j++)
                CP16(dst + (uint32_t)(tid * 16 + j * 4096), src + tid * 16 + j * 4096);
        }
        CP_COMMIT();

        const uint32_t st = sb + SMW_OFF + (uint32_t)((gc & 3) * 16384);
        const int kc = gc & 7;
        const bool two = (gc < split_until);

#pragma unroll
        for (int ks = 0; ks < 2; ks++) {
            uint32_t ah[2][4];
            const int arow = wm * 32 + ((lane >> 3) & 1) * 8 + (lane & 7);
            const int kg   = kc * 32 + ks * 16 + ((lane >> 4) << 3);
#pragma unroll
            for (int mf = 0; mf < 2; mf++) {
                const uint32_t r = (uint32_t)(arow + mf * 16);
                LDSM_X4(ah[mf], sb + r * 512u + swz((uint32_t)kg * 2u, r));
            }
            uint32_t bh[2][4], bl[2][4];
            const uint32_t krow = (uint32_t)(ks * 16 + ((lane >> 3) & 1) * 8 + (lane & 7));
#pragma unroll
            for (int nf2 = 0; nf2 < 2; nf2++) {
                const uint32_t ncol = (uint32_t)(wn * 32 + nf2 * 16 + (lane >> 4) * 8);
                const uint32_t addr = st + krow * 256u + swz(ncol * 2u, krow);
                LDSM_X4T(bh[nf2], addr);
                if (two) LDSM_X4T(bl[nf2], addr + 8192u);
            }
#pragma unroll
            for (int mf = 0; mf < 2; mf++)
#pragma unroll
                for (int nf = 0; nf < 4; nf++) {
                    uint32_t* bph = &bh[nf >> 1][(nf & 1) * 2];
                    MMA_FH(acc[mf][nf], ah[mf], bph);     // A*hi  (f32 accum)
                    if (two) {
                        uint32_t* bpl = &bl[nf >> 1][(nf & 1) * 2];
                        MMA_HH(acch[mf][nf], ah[mf], bpl);    // A*lo' (f16 accum)
                    }
                }
        }

        if (kc == 7) {
            const int g = lane >> 2, t = lane & 3;
#pragma unroll
            for (int nf = 0; nf < 4; nf++) {
                const int col = nt * 128 + wn * 32 + nf * 8 + t * 2;
                const float2 bv = *(const float2*)(bias + col);
#pragma unroll
                for (int mf = 0; mf < 2; mf++) {
                    const int row = row0 + wm * 32 + mf * 16 + g;
                    float2 c01 = __half22float2(*(const __half2*)&acch[mf][nf][0]);
                    float2 c23 = __half22float2(*(const __half2*)&acch[mf][nf][1]);
                    float2 v0 = make_float2(acc[mf][nf][0] + c01.x * LOINV + bv.x,
                                            acc[mf][nf][1] + c01.y * LOINV + bv.y);
                    float2 v1 = make_float2(acc[mf][nf][2] + c23.x * LOINV + bv.x,
                                            acc[mf][nf][3] + c23.y * LOINV + bv.y);
                    *(float2*)(C + (size_t)row * Ncols + col)       = v0;
                    *(float2*)(C + (size_t)(row + 8) * Ncols + col) = v1;
                }
            }
            nt++;
#pragma unroll
            for (int mf = 0; mf < 2; mf++)
#pragma unroll
                for (int nf = 0; nf < 4; nf++) {
#pragma unroll
                    for (int q = 0; q < 4; q++) acc[mf][nf][q] = 0.0f;
                    acch[mf][nf][0] = 0u; acch[mf][nf][1] = 0u;
                }
        }
    }
}

// =====================================================================
// Kernel 3: tensor-core window attention — 4 heads/CTA, grid (2048, 2),
//   256 threads (2 warps/head), 2 CTAs/SM. Output stored as fp16
//   (bit-identical to proj's previous A-conversion).
// =====================================================================
#define AHEAD 21504
#define AQH 0
#define AQL 3584
#define AKH 7168
#define AKL 10752
#define AVH 14336
#define AVL 17920
#define ATTN_SMEM (4 * AHEAD + 512)

__global__ __launch_bounds__(256, 2)
void attn_tc(const float* __restrict__ qkv,
             const float* __restrict__ bias,
             const float* __restrict__ scale,
             __half* __restrict__ attn_out)
{
    extern __shared__ char smem[];
    const uint32_t sb = s2u(smem);
    const int b    = blockIdx.x;
    const int hg   = blockIdx.y;
    const int tid  = threadIdx.x;
    const int lane = tid & 31;
    const int wrp  = tid >> 5;

    {
        int i = tid;
        if (i < 224) {
            const int slot = i / 56, rem = i % 56;
            const int half = rem / 28, rr = 49 + (rem % 28) / 4, c16 = (rem & 3) * 16;
            *(uint4*)(smem + slot * AHEAD + (half ? AVL : AVH) + rr * 64 + c16) =
                make_uint4(0, 0, 0, 0);
        } else if (i < 256) {
            *(uint4*)(smem + 4 * AHEAD + (i - 224) * 16) = make_uint4(0, 0, 0, 0);
        }
    }

    // loader: 4-thread teams, each thread owns 8 dims; uniform round count.
    {
        const float* wb = qkv + (size_t)b * NTOK * QKVCOL;
        const int team = tid >> 2, l4 = tid & 3;
#pragma unroll
        for (int it0 = 0; it0 < 256; it0 += 64) {
            const int it  = it0 + team;
            const bool act = (it < 196);
            const int tok  = act ? (it >> 2) : 0;
            const int slot = it & 3;
            const int hh   = hg * 4 + (act ? slot : 0);
            const float* rowp = wb + (size_t)tok * QKVCOL + hh * HD + l4 * 8;

            float4 q0, q1, k0, k1, v0, v1;
            if (act) {
                q0 = *(const float4*)(rowp);
                q1 = *(const float4*)(rowp + 4);
                k0 = *(const float4*)(rowp + 256);
                k1 = *(const float4*)(rowp + 260);
                v0 = *(const float4*)(rowp + 512);
                v1 = *(const float4*)(rowp + 516);
            } else {
                q0 = q1 = k0 = k1 = v0 = v1 = make_float4(0.f, 0.f, 0.f, 0.f);
            }

            float qss = q0.x*q0.x + q0.y*q0.y + q0.z*q0.z + q0.w*q0.w
                      + q1.x*q1.x + q1.y*q1.y + q1.z*q1.z + q1.w*q1.w;
            float kss = k0.x*k0.x + k0.y*k0.y + k0.z*k0.z + k0.w*k0.w
                      + k1.x*k1.x + k1.y*k1.y + k1.z*k1.z + k1.w*k1.w;
#pragma unroll
            for (int o = 1; o < 4; o <<= 1) {
                qss += __shfl_xor_sync(0xffffffffu, qss, o);
                kss += __shfl_xor_sync(0xffffffffu, kss, o);
            }
            if (act) {
                const float qr = rsqrtf(qss) * __ldg(scale + hh);
                const float kr = rsqrtf(kss);
                q0.x *= qr; q0.y *= qr; q0.z *= qr; q0.w *= qr;
                q1.x *= qr; q1.y *= qr; q1.z *= qr; q1.w *= qr;
                k0.x *= kr; k0.y *= kr; k0.z *= kr; k0.w *= kr;
                k1.x *= kr; k1.y *= kr; k1.z *= kr; k1.w *= kr;

                const uint32_t base = (uint32_t)slot * AHEAD + (uint32_t)tok * 64u
                                    + (uint32_t)((l4 ^ ((tok >> 1) & 3)) << 4);
                {
                    float h0 = rbf(q0.x), h1 = rbf(q0.y), h2 = rbf(q0.z), h3 = rbf(q0.w);
                    float h4 = rbf(q1.x), h5 = rbf(q1.y), h6 = rbf(q1.z), h7 = rbf(q1.w);
                    uint4 hu = make_uint4(pk2(h0,h1), pk2(h2,h3), pk2(h4,h5), pk2(h6,h7));
                    uint4 lu = make_uint4(pk2(q0.x-h0,q0.y-h1), pk2(q0.z-h2,q0.w-h3),
                                          pk2(q1.x-h4,q1.y-h5), pk2(q1.z-h6,q1.w-h7));
                    *(uint4*)(smem + AQH + base) = hu;
                    *(uint4*)(smem + AQL + base) = lu;
                }
                {
                    float h0 = rbf(k0.x), h1 = rbf(k0.y), h2 = rbf(k0.z), h3 = rbf(k0.w);
                    float h4 = rbf(k1.x), h5 = rbf(k1.y), h6 = rbf(k1.z), h7 = rbf(k1.w);
                    uint4 hu = make_uint4(pk2(h0,h1), pk2(h2,h3), pk2(h4,h5), pk2(h6,h7));
                    uint4 lu = make_uint4(pk2(k0.x-h0,k0.y-h1), pk2(k0.z-h2,k0.w-h3),
                                          pk2(k1.x-h4,k1.y-h5), pk2(k1.z-h6,k1.w-h7));
                    *(uint4*)(smem + AKH + base) = hu;
                    *(uint4*)(smem + AKL + base) = lu;
                }
                {
                    float h0 = rbf(v0.x), h1 = rbf(v0.y), h2 = rbf(v0.z), h3 = rbf(v0.w);
                    float h4 = rbf(v1.x), h5 = rbf(v1.y), h6 = rbf(v1.z), h7 = rbf(v1.w);
                    uint4 hu = make_uint4(pk2(h0,h1), pk2(h2,h3), pk2(h4,h5), pk2(h6,h7));
                    uint4 lu = make_uint4(pk2(v0.x-h0,v0.y-h1), pk2(v0.z-h2,v0.w-h3),
                                          pk2(v1.x-h4,v1.y-h5), pk2(v1.z-h6,v1.w-h7));
                    *(uint4*)(smem + AVH + base) = hu;
                    *(uint4*)(smem + AVL + base) = lu;
                }
            }
        }
    }
    __syncthreads();

    const int slot = wrp >> 1;
    const int h    = hg * 4 + slot;
    const int m0base = (wrp & 1) * 32;
    const uint32_t hb = sb + (uint32_t)slot * AHEAD;
    const float* bslab = bias + h * 3584;
    __half* obase = attn_out + (size_t)b * NTOK * DIMF + h * HD;
    const int qrow = lane >> 2;
    const int qc   = (lane & 3) * 2;

#pragma unroll
    for (int mc = 0; mc < 2; mc++) {
        const int m0 = m0base + mc * 16;
        const int r0 = m0 + qrow;

        // init S with bias (pads read 0); loads hide under QK MMAs
        float S[7][4];
#pragma unroll
        for (int nf = 0; nf < 7; nf++) {
            const int c0 = nf * 8 + qc;
            const float2 b0 = *(const float2*)(bslab + r0 * 56 + c0);
            const float2 b1 = *(const float2*)(bslab + (r0 + 8) * 56 + c0);
            S[nf][0] = b0.x; S[nf][1] = b0.y;
            S[nf][2] = b1.x; S[nf][3] = b1.y;
        }

#pragma unroll
        for (int ks = 0; ks < 2; ks++) {
            uint32_t ah[4], al[4];
            {
                const uint32_t r = (uint32_t)(m0 + ((lane >> 3) & 1) * 8 + (lane & 7));
                const uint32_t cb = (uint32_t)(ks * 32 + (lane >> 4) * 16);
                const uint32_t ad = hb + AQH + r * 64u + swz64(cb, r);
                LDSM_X4(ah, ad);
                LDSM_X4(al, ad + (AQL - AQH));
            }
#pragma unroll
            for (int ng = 0; ng < 4; ng++) {
                uint32_t bh[4], bl[4];
                const uint32_t r = (uint32_t)(ng * 16 + (lane & 7) + ((lane >> 4) << 3));
                const uint32_t cb = (uint32_t)(ks * 32 + ((lane >> 3) & 1) * 16);
                const uint32_t ad = hb + AKH + r * 64u + swz64(cb, r);
                LDSM_X4(bh, ad);
                LDSM_X4(bl, ad + (AKL - AKH));
                MMA_BF(S[2 * ng], ah, bh);
                MMA_BF(S[2 * ng], ah, bl);
                MMA_BF(S[2 * ng], al, bh);
                if (ng < 3) {
                    MMA_BF(S[2 * ng + 1], ah, bh + 2);
                    MMA_BF(S[2 * ng + 1], ah, bl + 2);
                    MMA_BF(S[2 * ng + 1], al, bh + 2);
                }
            }
        }

        // mask + softmax
        {
            float mx0 = -1e30f, mx1 = -1e30f;
#pragma unroll
            for (int nf = 0; nf < 7; nf++) {
                const int c0 = nf * 8 + qc;
                S[nf][0] = (c0     < 49) ? S[nf][0] : -1e30f;
                S[nf][1] = (c0 + 1 < 49) ? S[nf][1] : -1e30f;
                S[nf][2] = (c0     < 49) ? S[nf][2] : -1e30f;
                S[nf][3] = (c0 + 1 < 49) ? S[nf][3] : -1e30f;
                mx0 = fmaxf(mx0, fmaxf(S[nf][0], S[nf][1]));
                mx1 = fmaxf(mx1, fmaxf(S[nf][2], S[nf][3]));
            }
#pragma unroll
            for (int o = 1; o < 4; o <<= 1) {
                mx0 = fmaxf(mx0, __shfl_xor_sync(0xffffffffu, mx0, o));
                mx1 = fmaxf(mx1, __shfl_xor_sync(0xffffffffu, mx1, o));
            }
            float rs0 = 0.0f, rs1 = 0.0f;
#pragma unroll
            for (int nf = 0; nf < 7; nf++) {
                float p0 = __expf(S[nf][0] - mx0);
                float p1 = __expf(S[nf][1] - mx0);
                float p2 = __expf(S[nf][2] - mx1);
                float p3 = __expf(S[nf][3] - mx1);
                S[nf][0] = p0; S[nf][1] = p1; S[nf][2] = p2; S[nf][3] = p3;
                rs0 += p0 + p1;  rs1 += p2 + p3;
            }
#pragma unroll
            for (int o = 1; o < 4; o <<= 1) {
                rs0 += __shfl_xor_sync(0xffffffffu, rs0, o);
                rs1 += __shfl_xor_sync(0xffffffffu, rs1, o);
            }
            const float iv0 = 1.0f / rs0, iv1 = 1.0f / rs1;
#pragma unroll
            for (int nf = 0; nf < 7; nf++) {
                S[nf][0] *= iv0; S[nf][1] *= iv0;
                S[nf][2] *= iv1; S[nf][3] *= iv1;
            }
        }

        float O[4][4];
#pragma unroll
        for (int n = 0; n < 4; n++)
#pragma unroll
            for (int q = 0; q < 4; q++) O[n][q] = 0.0f;

#pragma unroll
        for (int kt = 0; kt < 4; kt++) {
            uint32_t ph[4], pl[4];
            {
                float pa0 = S[2*kt][0], pa1 = S[2*kt][1], pa2 = S[2*kt][2], pa3 = S[2*kt][3];
                float pb0 = 0.f, pb1 = 0.f, pb2 = 0.f, pb3 = 0.f;
                if (kt < 3) {
                    pb0 = S[2*kt+1][0]; pb1 = S[2*kt+1][1];
                    pb2 = S[2*kt+1][2]; pb3 = S[2*kt+1][3];
                }
                const float ha0 = rbf(pa0), ha1 = rbf(pa1), ha2 = rbf(pa2), ha3 = rbf(pa3);
                const float hb0 = rbf(pb0), hb1 = rbf(pb1), hb2 = rbf(pb2), hb3 = rbf(pb3);
                ph[0] = pk2(ha0, ha1);  ph[1] = pk2(ha2, ha3);
                ph[2] = pk2(hb0, hb1);  ph[3] = pk2(hb2, hb3);
                pl[0] = pk2(pa0 - ha0, pa1 - ha1);
                pl[1] = pk2(pa2 - ha2, pa3 - ha3);
                pl[2] = pk2(pb0 - hb0, pb1 - hb1);
                pl[3] = pk2(pb2 - hb2, pb3 - hb3);
            }
#pragma unroll
            for (int vg = 0; vg < 2; vg++) {
                uint32_t vh[4], vl[4];
                const uint32_t kr = (uint32_t)(kt * 16 + ((lane >> 3) & 1) * 8 + (lane & 7));
                const uint32_t cb = (uint32_t)(vg * 32 + (lane >> 4) * 16);
                const uint32_t ad = hb + AVH + kr * 64u + swz64(cb, kr);
                LDSM_X4T(vh, ad);
                LDSM_X4T(vl, ad + (AVL - AVH));
#pragma unroll
                for (int nn = 0; nn < 2; nn++) {
                    float* oo = O[vg * 2 + nn];
                    MMA_BF(oo, ph, vh + nn * 2);
                    MMA_BF(oo, ph, vl + nn * 2);
                    MMA_BF(oo, pl, vh + nn * 2);
                }
            }
        }

        // store rows < 49 as fp16 (same rounding proj would apply)
        {
#pragma unroll
            for (int nf = 0; nf < 4; nf++) {
                const int c = nf * 8 + qc;
                if (r0 < NTOK)
                    *(uint32_t*)(obase + (size_t)r0 * DIMF + c) = pk2h(O[nf][0], O[nf][1]);
                if (r0 + 8 < NTOK)
                    *(uint32_t*)(obase + (size_t)(r0 + 8) * DIMF + c) = pk2h(O[nf][2], O[nf][3]);
            }
        }
    }
}

// =====================================================================
// launch
// =====================================================================
extern "C" void kernel_launch(void* const* d_in, const int* in_sizes, int n_in,
                              void* d_out, int out_size)
{
    const float* x           = (const float*)d_in[0];
    const float* qkv_w       = (const float*)d_in[1];
    const float* qkv_b       = (const float*)d_in[2];
    const float* proj_w      = (const float*)d_in[3];
    const float* proj_b      = (const float*)d_in[4];
    const float* logit_scale = (const float*)d_in[5];
    const float* cpb_w1      = (const float*)d_in[6];
    const float* cpb_b1      = (const float*)d_in[7];
    const float* cpb_w2      = (const float*)d_in[8];
    float* out = (float*)d_out;

    float *qkvbuf, *attnbuf, *biasbuf, *scalebuf;
    unsigned char *wqbuf, *wpbuf;
    cudaGetSymbolAddress((void**)&qkvbuf,   g_qkv);
    cudaGetSymbolAddress((void**)&attnbuf,  g_attn);
    cudaGetSymbolAddress((void**)&biasbuf,  g_bias);
    cudaGetSymbolAddress((void**)&scalebuf, g_scale);
    cudaGetSymbolAddress((void**)&wqbuf,    g_wq);
    cudaGetSymbolAddress((void**)&wpbuf,    g_wp);

    cudaFuncSetAttribute(gemm_mma<false>, cudaFuncAttributeMaxDynamicSharedMemorySize, GEMM_SMEM);
    cudaFuncSetAttribute(gemm_mma<true>,  cudaFuncAttributeMaxDynamicSharedMemorySize, GEMM_SMEM);
    cudaFuncSetAttribute(attn_tc,         cudaFuncAttributeMaxDynamicSharedMemorySize, ATTN_SMEM);

    cpb_kernel<<<1, 256>>>(logit_scale, cpb_w1, cpb_b1, cpb_w2, biasbuf, scalebuf);
    wsplit_kernel<<<128, 256>>>(qkv_w, proj_w, wqbuf, wpbuf);

    // QKV: q,k tiles (chunks 0..31) 2-product; v tiles (32..47) 1-product
    gemm_mma<false><<<MROWS / 64, 256, GEMM_SMEM>>>(x, wqbuf, qkv_b, qkvbuf, 6, 32);

    attn_tc<<<dim3(B_WIN, 2), 256, ATTN_SMEM>>>(qkvbuf, biasbuf, scalebuf,
                                                (__half*)attnbuf);

    // proj: all 1-product; A already fp16
    gemm_mma<true><<<MROWS / 64, 256, GEMM_SMEM>>>(attnbuf, wpbuf, proj_b, out, 2, 0);
}